// round 5
// baseline (speedup 1.0000x reference)
#include <cuda_runtime.h>
#include <math.h>

// Problem constants
#define BDIM 2
#define SDIM 2048
#define DDIM 1024
#define NHEAD 16
#define HDIM 64
#define MDIM 4096
#define ROWS (BDIM*SDIM)          // 4096 token rows
#define QKVC (NHEAD*3*HDIM)       // 3072 packed qkv columns

// ---------------- scratch (device globals; no allocation allowed) ----------
__device__ float g_ln  [ROWS*DDIM];            // 16 MB, reused for ln1 & ln2
__device__ float g_wp  [DDIM*QKVC];            // 12 MB packed W_qkv
__device__ float g_qkv [ROWS*QKVC];            // 48 MB
__device__ float g_atto[BDIM*NHEAD*SDIM*HDIM]; // 16 MB attention out (b,n,s,h)
__device__ float g_wsum[DDIM];
__device__ float g_x1  [ROWS*DDIM];            // 16 MB residual after attention
__device__ float g_h   [ROWS*MDIM];            // 64 MB MLP hidden

// ---------------- layernorm (ddof=1, eps=1e-4) ------------------------------
__global__ __launch_bounds__(256) void ln_kernel(
    const float* __restrict__ x, const float* __restrict__ w,
    const float* __restrict__ bb, float* __restrict__ y)
{
    int row = blockIdx.x;
    int t = threadIdx.x;
    const float4* xr = (const float4*)(x + (size_t)row * DDIM);
    float4 v = xr[t];

    __shared__ float red[8];
    __shared__ float s_mu, s_inv;

    float s = v.x + v.y + v.z + v.w;
    #pragma unroll
    for (int o = 16; o > 0; o >>= 1) s += __shfl_xor_sync(0xffffffffu, s, o);
    if ((t & 31) == 0) red[t >> 5] = s;
    __syncthreads();
    if (t == 0) {
        float tot = 0.f;
        #pragma unroll
        for (int i = 0; i < 8; ++i) tot += red[i];
        s_mu = tot * (1.0f / DDIM);
    }
    __syncthreads();
    float mu = s_mu;
    float dx = v.x - mu, dy = v.y - mu, dz = v.z - mu, dw = v.w - mu;
    float ss = dx*dx + dy*dy + dz*dz + dw*dw;
    #pragma unroll
    for (int o = 16; o > 0; o >>= 1) ss += __shfl_xor_sync(0xffffffffu, ss, o);
    __syncthreads();
    if ((t & 31) == 0) red[t >> 5] = ss;
    __syncthreads();
    if (t == 0) {
        float tot = 0.f;
        #pragma unroll
        for (int i = 0; i < 8; ++i) tot += red[i];
        s_inv = rsqrtf(tot * (1.0f / (DDIM - 1)) + 1e-4f);
    }
    __syncthreads();
    float inv = s_inv;
    float4 wv = ((const float4*)w)[t];
    float4 bv = ((const float4*)bb)[t];
    float4 o;
    o.x = dx * inv * wv.x + bv.x;
    o.y = dy * inv * wv.y + bv.y;
    o.z = dz * inv * wv.z + bv.z;
    o.w = dw * inv * wv.w + bv.w;
    ((float4*)(y + (size_t)row * DDIM))[t] = o;
}

// ---------------- pack W_qkv[N,D,192] -> Wp[D, N*192] -----------------------
__global__ __launch_bounds__(256) void pack_wqkv(
    const float* __restrict__ W, float* __restrict__ Wp)
{
    int idx = blockIdx.x * 256 + threadIdx.x;           // < DDIM*QKVC
    int k = idx / QKVC;
    int c = idx - k * QKVC;
    int n = c / 192;
    int j = c - n * 192;
    Wp[idx] = W[((size_t)n * DDIM + k) * 192 + j];
}

// ---------------- w_sum[d] = sum_{n,h} W_out[n,h,d] -------------------------
__global__ __launch_bounds__(256) void wsum_kernel(
    const float* __restrict__ Wout, float* __restrict__ ws)
{
    int d = blockIdx.x * 256 + threadIdx.x;
    float s = 0.f;
    for (int i = 0; i < NHEAD * HDIM; ++i) s += Wout[(size_t)i * DDIM + d];
    ws[d] = s;
}

// ---------------- SGEMM 128x128x8, 256 threads, 8x8 microtile ---------------
__device__ __forceinline__ float gelu_exact(float v) {
    return 0.5f * v * (1.0f + erff(v * 0.70710678118654752440f));
}

// EPI: 0 = plain store, 1 = +bias then gelu, 2 = +bias +res (residual add)
template<int EPI>
__global__ __launch_bounds__(256) void sgemm_k(
    const float* __restrict__ A, const float* __restrict__ B,
    float* __restrict__ C, int M, int N, int K,
    const float* __restrict__ bias, const float* __restrict__ res)
{
    __shared__ __align__(16) float As[8 * 128];
    __shared__ __align__(16) float Bs[8 * 128];

    int bm = blockIdx.y * 128, bn = blockIdx.x * 128;
    int tid = threadIdx.x;
    int arow = tid >> 1, acol = (tid & 1) << 2;   // A tile 128x8 via float4
    int brow = tid >> 5, bcol = (tid & 31) << 2;  // B tile 8x128 via float4
    int ty = tid >> 4, tx = tid & 15;

    const float* Ap = A + (size_t)(bm + arow) * K + acol;
    const float* Bp = B + (size_t)brow * N + bn + bcol;

    float acc[8][8];
    #pragma unroll
    for (int i = 0; i < 8; ++i)
        #pragma unroll
        for (int j = 0; j < 8; ++j) acc[i][j] = 0.f;

    for (int k0 = 0; k0 < K; k0 += 8) {
        float4 av = *(const float4*)(Ap + k0);
        float4 bv = *(const float4*)(Bp + (size_t)k0 * N);
        As[(acol + 0) * 128 + arow] = av.x;
        As[(acol + 1) * 128 + arow] = av.y;
        As[(acol + 2) * 128 + arow] = av.z;
        As[(acol + 3) * 128 + arow] = av.w;
        *(float4*)(Bs + brow * 128 + bcol) = bv;
        __syncthreads();
        #pragma unroll
        for (int kk = 0; kk < 8; ++kk) {
            float4 a0 = *(const float4*)(As + kk * 128 + ty * 8);
            float4 a1 = *(const float4*)(As + kk * 128 + ty * 8 + 4);
            float4 b0 = *(const float4*)(Bs + kk * 128 + tx * 8);
            float4 b1 = *(const float4*)(Bs + kk * 128 + tx * 8 + 4);
            float a[8] = {a0.x, a0.y, a0.z, a0.w, a1.x, a1.y, a1.z, a1.w};
            float bb[8] = {b0.x, b0.y, b0.z, b0.w, b1.x, b1.y, b1.z, b1.w};
            #pragma unroll
            for (int i = 0; i < 8; ++i)
                #pragma unroll
                for (int j = 0; j < 8; ++j)
                    acc[i][j] += a[i] * bb[j];
        }
        __syncthreads();
    }

    #pragma unroll
    for (int i = 0; i < 8; ++i) {
        int row = bm + ty * 8 + i;
        #pragma unroll
        for (int j = 0; j < 8; j += 4) {
            int col = bn + tx * 8 + j;
            float4 c = make_float4(acc[i][j], acc[i][j+1], acc[i][j+2], acc[i][j+3]);
            if (EPI == 1) {
                c.x = gelu_exact(c.x + bias[col + 0]);
                c.y = gelu_exact(c.y + bias[col + 1]);
                c.z = gelu_exact(c.z + bias[col + 2]);
                c.w = gelu_exact(c.w + bias[col + 3]);
            } else if (EPI == 2) {
                const float* rp = res + (size_t)row * N + col;
                c.x += bias[col + 0] + rp[0];
                c.y += bias[col + 1] + rp[1];
                c.z += bias[col + 2] + rp[2];
                c.w += bias[col + 3] + rp[3];
            }
            *(float4*)(C + (size_t)row * N + col) = c;
        }
    }
}

// ---------------- flash attention: 64 q x 64 k tiles, fp32 ------------------
// qkv packed rows: qkv[(b*S+s)*3072 + n*192 + {0:q,64:k,128:v} + h]
__global__ __launch_bounds__(128) void flash_kernel(
    const float* __restrict__ qkv, float* __restrict__ atto)
{
    extern __shared__ float sm[];
    float* Qt = sm;                 // Qt[h*64 + i]   (Q^T, pre-scaled)
    float* KP = sm + 64 * 64;       // K: KP[h*64+j]; later P: KP[i*65+j]
    float* Vs = KP + 64 * 65;       // Vs[j*64 + h]

    int qt = blockIdx.x, n = blockIdx.y, b = blockIdx.z;
    int tid = threadIdx.x;
    int ty = tid >> 4, tx = tid & 15;   // rows ty*8..+7, cols tx*4..+3
    const float* base = qkv + (size_t)b * SDIM * QKVC + n * 192;

    // load Q tile transposed + scaled
    #pragma unroll
    for (int it = 0; it < 8; ++it) {
        int idx = tid + it * 128;
        int r = idx >> 4;
        int h4 = (idx & 15) << 2;
        float4 v = *(const float4*)(base + (size_t)(qt * 64 + r) * QKVC + h4);
        Qt[(h4 + 0) * 64 + r] = v.x * 0.125f;
        Qt[(h4 + 1) * 64 + r] = v.y * 0.125f;
        Qt[(h4 + 2) * 64 + r] = v.z * 0.125f;
        Qt[(h4 + 3) * 64 + r] = v.w * 0.125f;
    }

    float m[8], l[8], acc[8][4];
    #pragma unroll
    for (int i = 0; i < 8; ++i) {
        m[i] = -INFINITY; l[i] = 0.f;
        acc[i][0] = acc[i][1] = acc[i][2] = acc[i][3] = 0.f;
    }

    for (int kt = 0; kt <= qt; ++kt) {
        __syncthreads();   // protect KP/Vs from previous iteration readers
        #pragma unroll
        for (int it = 0; it < 8; ++it) {
            int idx = tid + it * 128;
            int r = idx >> 4;
            int h4 = (idx & 15) << 2;
            const float* rb = base + (size_t)(kt * 64 + r) * QKVC + h4;
            float4 kv = *(const float4*)(rb + 64);
            KP[(h4 + 0) * 64 + r] = kv.x;
            KP[(h4 + 1) * 64 + r] = kv.y;
            KP[(h4 + 2) * 64 + r] = kv.z;
            KP[(h4 + 3) * 64 + r] = kv.w;
            float4 vv = *(const float4*)(rb + 128);
            *(float4*)(Vs + r * 64 + h4) = vv;
        }
        __syncthreads();

        // S = (Q*scale) @ K^T   (contraction over h)
        float s[8][4];
        #pragma unroll
        for (int i = 0; i < 8; ++i)
            #pragma unroll
            for (int j = 0; j < 4; ++j) s[i][j] = 0.f;
        #pragma unroll 8
        for (int h = 0; h < 64; ++h) {
            float4 a0 = *(const float4*)(Qt + h * 64 + ty * 8);
            float4 a1 = *(const float4*)(Qt + h * 64 + ty * 8 + 4);
            float4 b0 = *(const float4*)(KP + h * 64 + tx * 4);
            float a[8] = {a0.x, a0.y, a0.z, a0.w, a1.x, a1.y, a1.z, a1.w};
            float bb[4] = {b0.x, b0.y, b0.z, b0.w};
            #pragma unroll
            for (int i = 0; i < 8; ++i)
                #pragma unroll
                for (int j = 0; j < 4; ++j)
                    s[i][j] += a[i] * bb[j];
        }

        // causal mask (only the diagonal tile needs it)
        if (kt == qt) {
            #pragma unroll
            for (int i = 0; i < 8; ++i)
                #pragma unroll
                for (int j = 0; j < 4; ++j)
                    if (tx * 4 + j > ty * 8 + i) s[i][j] = -INFINITY;
        }

        // online softmax (row groups = 16 contiguous lanes -> width-16 shfl)
        #pragma unroll
        for (int i = 0; i < 8; ++i) {
            float rm = fmaxf(fmaxf(s[i][0], s[i][1]), fmaxf(s[i][2], s[i][3]));
            #pragma unroll
            for (int o = 1; o < 16; o <<= 1)
                rm = fmaxf(rm, __shfl_xor_sync(0xffffffffu, rm, o, 16));
            float mnew = fmaxf(m[i], rm);
            float alpha = __expf(m[i] - mnew);
            m[i] = mnew;
            float rs = 0.f;
            #pragma unroll
            for (int j = 0; j < 4; ++j) {
                float p = __expf(s[i][j] - mnew);
                s[i][j] = p;
                rs += p;
            }
            #pragma unroll
            for (int o = 1; o < 16; o <<= 1)
                rs += __shfl_xor_sync(0xffffffffu, rs, o, 16);
            l[i] = l[i] * alpha + rs;
            acc[i][0] *= alpha; acc[i][1] *= alpha;
            acc[i][2] *= alpha; acc[i][3] *= alpha;
        }

        __syncthreads();   // everyone done reading K before P overwrites it
        #pragma unroll
        for (int i = 0; i < 8; ++i)
            #pragma unroll
            for (int j = 0; j < 4; ++j)
                KP[(ty * 8 + i) * 65 + tx * 4 + j] = s[i][j];
        __syncthreads();

        // acc += P @ V
        #pragma unroll 8
        for (int j = 0; j < 64; ++j) {
            float4 bv = *(const float4*)(Vs + j * 64 + tx * 4);
            #pragma unroll
            for (int i = 0; i < 8; ++i) {
                float a = KP[(ty * 8 + i) * 65 + j];
                acc[i][0] += a * bv.x;
                acc[i][1] += a * bv.y;
                acc[i][2] += a * bv.z;
                acc[i][3] += a * bv.w;
            }
        }
    }

    float* ob = atto + ((size_t)(b * NHEAD + n) * SDIM + qt * 64) * HDIM;
    #pragma unroll
    for (int i = 0; i < 8; ++i) {
        float inv = 1.0f / l[i];
        float4 o = make_float4(acc[i][0] * inv, acc[i][1] * inv,
                               acc[i][2] * inv, acc[i][3] * inv);
        *(float4*)(ob + (size_t)(ty * 8 + i) * HDIM + tx * 4) = o;
    }
}

// ------- residual + torch-reinterpretation "projection": --------------------
// x1[b,s,d] = x[b,s,d] + atto_flat[b, d*S + s] * w_sum[d]
__global__ void resid_attn(const float* __restrict__ x,
                           const float* __restrict__ atto,
                           const float* __restrict__ wsum,
                           float* __restrict__ x1)
{
    __shared__ float tile[32][33];
    int b = blockIdx.z;
    int d0 = blockIdx.x * 32, s0 = blockIdx.y * 32;
    int tx = threadIdx.x, ty = threadIdx.y;   // 32 x 8
    const float* ab = atto + (size_t)b * (DDIM * SDIM);
    #pragma unroll
    for (int r = 0; r < 32; r += 8) {
        int d = d0 + ty + r, s = s0 + tx;
        tile[ty + r][tx] = ab[(size_t)d * SDIM + s];
    }
    __syncthreads();
    #pragma unroll
    for (int r = 0; r < 32; r += 8) {
        int s = s0 + ty + r, d = d0 + tx;
        size_t idx = ((size_t)b * SDIM + s) * DDIM + d;
        x1[idx] = x[idx] + tile[tx][ty + r] * wsum[d];
    }
}

// ---------------------------------------------------------------------------
extern "C" void kernel_launch(void* const* d_in, const int* in_sizes, int n_in,
                              void* d_out, int out_size)
{
    const float* x    = (const float*)d_in[0];
    const float* Wqkv = (const float*)d_in[1];
    const float* Wout = (const float*)d_in[2];
    const float* ln1w = (const float*)d_in[3];
    const float* ln1b = (const float*)d_in[4];
    const float* ln2w = (const float*)d_in[5];
    const float* ln2b = (const float*)d_in[6];
    const float* W1   = (const float*)d_in[7];
    const float* b1   = (const float*)d_in[8];
    const float* W2   = (const float*)d_in[9];
    const float* b2   = (const float*)d_in[10];
    float* out = (float*)d_out;

    float *p_ln, *p_wp, *p_qkv, *p_atto, *p_wsum, *p_x1, *p_h;
    cudaGetSymbolAddress((void**)&p_ln,   g_ln);
    cudaGetSymbolAddress((void**)&p_wp,   g_wp);
    cudaGetSymbolAddress((void**)&p_qkv,  g_qkv);
    cudaGetSymbolAddress((void**)&p_atto, g_atto);
    cudaGetSymbolAddress((void**)&p_wsum, g_wsum);
    cudaGetSymbolAddress((void**)&p_x1,   g_x1);
    cudaGetSymbolAddress((void**)&p_h,    g_h);

    // ln1
    ln_kernel<<<ROWS, 256>>>(x, ln1w, ln1b, p_ln);
    // weight prep (cheap, independent)
    pack_wqkv<<<(DDIM * QKVC) / 256, 256>>>(Wqkv, p_wp);
    wsum_kernel<<<DDIM / 256, 256>>>(Wout, p_wsum);
    // QKV projection: [4096,1024] x [1024,3072]
    sgemm_k<0><<<dim3(QKVC / 128, ROWS / 128), 256>>>(
        p_ln, p_wp, p_qkv, ROWS, QKVC, DDIM, nullptr, nullptr);
    // attention
    int smem = (64 * 64 + 64 * 65 + 64 * 64) * (int)sizeof(float);  // 49408 B
    cudaFuncSetAttribute(flash_kernel,
                         cudaFuncAttributeMaxDynamicSharedMemorySize, smem);
    flash_kernel<<<dim3(SDIM / 64, NHEAD, BDIM), 128, smem>>>(p_qkv, p_atto);
    // residual + reinterpretation-projection
    resid_attn<<<dim3(DDIM / 32, SDIM / 32, BDIM), dim3(32, 8)>>>(
        x, p_atto, p_wsum, p_x1);
    // ln2
    ln_kernel<<<ROWS, 256>>>(p_x1, ln2w, ln2b, p_ln);
    // MLP: gelu(ln2 @ W1 + b1) @ W2 + b2 + x1
    sgemm_k<1><<<dim3(MDIM / 128, ROWS / 128), 256>>>(
        p_ln, W1, p_h, ROWS, MDIM, DDIM, b1, nullptr);
    sgemm_k<2><<<dim3(DDIM / 128, ROWS / 128), 256>>>(
        p_h, W2, out, ROWS, DDIM, MDIM, b2, p_x1);
}

// round 9
// speedup vs baseline: 2.2044x; 2.2044x over previous
#include <cuda_runtime.h>
#include <math.h>
#include <stdint.h>

// Problem constants
#define BDIM 2
#define SDIM 2048
#define DDIM 1024
#define NHEAD 16
#define HDIM 64
#define MDIM 4096
#define ROWS (BDIM*SDIM)          // 4096 token rows
#define QKVC (NHEAD*3*HDIM)       // 3072 packed qkv columns

// ---------------- scratch (device globals; no allocation allowed) ----------
__device__ float g_ln  [ROWS*DDIM];            // 16 MB, reused for ln1 & ln2
__device__ float g_wqt [QKVC*DDIM];            // 12 MB W_qkv^T  [3072,1024]
__device__ float g_w1t [MDIM*DDIM];            // 16 MB W1^T     [4096,1024]
__device__ float g_w2t [DDIM*MDIM];            // 16 MB W2^T     [1024,4096]
__device__ float g_qkv [ROWS*QKVC];            // 48 MB
__device__ float g_atto[BDIM*NHEAD*SDIM*HDIM]; // 16 MB attention out (b,n,s,h)
__device__ float g_wsum[DDIM];
__device__ float g_x1  [ROWS*DDIM];            // 16 MB residual after attention
__device__ float g_h   [ROWS*MDIM];            // 64 MB MLP hidden

// ============================ helpers =======================================
__device__ __forceinline__ float to_tf32(float x) {
    uint32_t u;
    asm("cvt.rna.tf32.f32 %0, %1;" : "=r"(u) : "f"(x));
    return __uint_as_float(u);
}
__device__ __forceinline__ uint32_t smem_u32(const void* p) {
    uint32_t a;
    asm("{ .reg .u64 t; cvta.to.shared.u64 t, %1; cvt.u32.u64 %0, t; }"
        : "=r"(a) : "l"(p));
    return a;
}
__device__ __forceinline__ void cp16(uint32_t dst, const void* src) {
    asm volatile("cp.async.cg.shared.global [%0], [%1], 16;" :: "r"(dst), "l"(src));
}
__device__ __forceinline__ float gelu_exact(float v) {
    return 0.5f * v * (1.0f + erff(v * 0.70710678118654752440f));
}

#define MMA_TF32(c, a, b) \
    asm volatile("mma.sync.aligned.m16n8k8.row.col.f32.tf32.tf32.f32 " \
        "{%0,%1,%2,%3}, {%4,%5,%6,%7}, {%8,%9}, {%0,%1,%2,%3};" \
        : "+f"((c)[0]), "+f"((c)[1]), "+f"((c)[2]), "+f"((c)[3]) \
        : "r"((a)[0]), "r"((a)[1]), "r"((a)[2]), "r"((a)[3]), \
          "r"((b)[0]), "r"((b)[1]))

// ========== tf32 HMMA GEMM: C[M,N] = A[M,K] * Bt[N,K]^T =====================
// A row-major [M,K], Bt row-major [N,K]. CTA tile 128x128, 256 thr (8 warps,
// 2x4 -> warp tile 64x32). K staged at 32, 3-deep cp.async pipeline.
// smem pitch 36 floats -> fragment LDS bank = (4q+k)%32: conflict-free.
#define PITCH 36
#define STAGE_F (128*PITCH)                    // floats per stage per operand
#define GEMM_SMEM (2*3*STAGE_F*4)              // 110592 bytes

// EPI: 0 = plain, 1 = +bias, gelu, tf32-round, 2 = +bias +res
template<int EPI>
__global__ __launch_bounds__(256)
void mma_gemm(const float* __restrict__ A, const float* __restrict__ Bt,
              float* __restrict__ C, int M, int N, int K,
              const float* __restrict__ bias, const float* __restrict__ res)
{
    extern __shared__ float sm[];
    float* As = sm;                 // [3][STAGE_F]
    float* Bs = sm + 3 * STAGE_F;

    const int tid = threadIdx.x;
    const int wid = tid >> 5, lane = tid & 31;
    const int bm = blockIdx.y * 128, bn = blockIdx.x * 128;
    const int mbase = (wid >> 2) * 64;      // warpM in {0,1}
    const int nbase = (wid & 3) * 32;       // warpN in {0..3}
    const int q = lane >> 2, r4 = lane & 3;

    const uint32_t sA = smem_u32(As);
    const uint32_t sB = smem_u32(Bs);
    const int nst = K >> 5;

    auto load_stage = [&](int s) {
        int slot = s - (s / 3) * 3;
        int k0 = s << 5;
        const float* Ag = A + (size_t)bm * K + k0;
        const float* Bg = Bt + (size_t)bn * K + k0;
        uint32_t ab = sA + slot * (STAGE_F * 4);
        uint32_t bb = sB + slot * (STAGE_F * 4);
        #pragma unroll
        for (int i = 0; i < 4; ++i) {
            int linear = i * 256 + tid;          // 0..1023
            int row = linear >> 3, c4 = linear & 7;
            uint32_t off = (uint32_t)(row * PITCH + c4 * 4) * 4;
            cp16(ab + off, Ag + (size_t)row * K + c4 * 4);
            cp16(bb + off, Bg + (size_t)row * K + c4 * 4);
        }
        asm volatile("cp.async.commit_group;" ::: "memory");
    };

    float c[4][4][4];
    #pragma unroll
    for (int mt = 0; mt < 4; ++mt)
        #pragma unroll
        for (int nt = 0; nt < 4; ++nt)
            #pragma unroll
            for (int j = 0; j < 4; ++j) c[mt][nt][j] = 0.f;

    load_stage(0); load_stage(1); load_stage(2);   // nst >= 3 always

    for (int s = 0; s < nst; ++s) {
        int slot = s - (s / 3) * 3;
        asm volatile("cp.async.wait_group 2;" ::: "memory");
        __syncthreads();

        const float* a_s = As + slot * STAGE_F;
        const float* b_s = Bs + slot * STAGE_F;
        #pragma unroll
        for (int kk = 0; kk < 4; ++kk) {
            int kb = kk * 8;
            uint32_t a[4][4];
            #pragma unroll
            for (int mt = 0; mt < 4; ++mt) {
                const float* ap = a_s + (mbase + mt * 16 + q) * PITCH + kb + r4;
                a[mt][0] = __float_as_uint(ap[0]);
                a[mt][1] = __float_as_uint(ap[8 * PITCH]);
                a[mt][2] = __float_as_uint(ap[4]);
                a[mt][3] = __float_as_uint(ap[8 * PITCH + 4]);
            }
            uint32_t b[4][2];
            #pragma unroll
            for (int nt = 0; nt < 4; ++nt) {
                const float* bp = b_s + (nbase + nt * 8 + q) * PITCH + kb + r4;
                b[nt][0] = __float_as_uint(bp[0]);
                b[nt][1] = __float_as_uint(bp[4]);
            }
            #pragma unroll
            for (int mt = 0; mt < 4; ++mt)
                #pragma unroll
                for (int nt = 0; nt < 4; ++nt)
                    MMA_TF32(c[mt][nt], a[mt], b[nt]);
        }

        __syncthreads();   // stage consumed before overwrite
        if (s + 3 < nst) load_stage(s + 3);
        else asm volatile("cp.async.commit_group;" ::: "memory");
    }

    // Epilogue. c0,c1: (row, 2*r4 +0/1); c2,c3: (row+8, same cols)
    #pragma unroll
    for (int mt = 0; mt < 4; ++mt) {
        #pragma unroll
        for (int nt = 0; nt < 4; ++nt) {
            int row0 = bm + mbase + mt * 16 + q;
            int col  = bn + nbase + nt * 8 + r4 * 2;
            #pragma unroll
            for (int h = 0; h < 2; ++h) {
                int row = row0 + h * 8;
                float vx = c[mt][nt][2 * h], vy = c[mt][nt][2 * h + 1];
                if (EPI == 1) {
                    vx = to_tf32(gelu_exact(vx + bias[col]));
                    vy = to_tf32(gelu_exact(vy + bias[col + 1]));
                } else if (EPI == 2) {
                    const float* rp = res + (size_t)row * N + col;
                    vx += bias[col] + rp[0];
                    vy += bias[col + 1] + rp[1];
                }
                *(float2*)(C + (size_t)row * N + col) = make_float2(vx, vy);
            }
        }
    }
}

// ---------------- layernorm (ddof=1, eps=1e-4) + tf32 rounding --------------
__global__ __launch_bounds__(256) void ln_kernel(
    const float* __restrict__ x, const float* __restrict__ w,
    const float* __restrict__ bb, float* __restrict__ y)
{
    int row = blockIdx.x;
    int t = threadIdx.x;
    const float4* xr = (const float4*)(x + (size_t)row * DDIM);
    float4 v = xr[t];

    __shared__ float red[8];
    __shared__ float s_mu, s_inv;

    float s = v.x + v.y + v.z + v.w;
    #pragma unroll
    for (int o = 16; o > 0; o >>= 1) s += __shfl_xor_sync(0xffffffffu, s, o);
    if ((t & 31) == 0) red[t >> 5] = s;
    __syncthreads();
    if (t == 0) {
        float tot = 0.f;
        #pragma unroll
        for (int i = 0; i < 8; ++i) tot += red[i];
        s_mu = tot * (1.0f / DDIM);
    }
    __syncthreads();
    float mu = s_mu;
    float dx = v.x - mu, dy = v.y - mu, dz = v.z - mu, dw = v.w - mu;
    float ss = dx*dx + dy*dy + dz*dz + dw*dw;
    #pragma unroll
    for (int o = 16; o > 0; o >>= 1) ss += __shfl_xor_sync(0xffffffffu, ss, o);
    __syncthreads();
    if ((t & 31) == 0) red[t >> 5] = ss;
    __syncthreads();
    if (t == 0) {
        float tot = 0.f;
        #pragma unroll
        for (int i = 0; i < 8; ++i) tot += red[i];
        s_inv = rsqrtf(tot * (1.0f / (DDIM - 1)) + 1e-4f);
    }
    __syncthreads();
    float inv = s_inv;
    float4 wv = ((const float4*)w)[t];
    float4 bv = ((const float4*)bb)[t];
    float4 o;
    o.x = to_tf32(dx * inv * wv.x + bv.x);
    o.y = to_tf32(dy * inv * wv.y + bv.y);
    o.z = to_tf32(dz * inv * wv.z + bv.z);
    o.w = to_tf32(dw * inv * wv.w + bv.w);
    ((float4*)(y + (size_t)row * DDIM))[t] = o;
}

// ------------- transpose [K,N] -> [N,K] with tf32 rounding ------------------
__global__ __launch_bounds__(256) void transpose_tf32(
    const float* __restrict__ in, float* __restrict__ out, int K, int N)
{
    __shared__ float t[32][33];
    int k0 = blockIdx.y * 32, n0 = blockIdx.x * 32;
    int tx = threadIdx.x, ty = threadIdx.y;   // 32 x 8
    #pragma unroll
    for (int r = 0; r < 32; r += 8)
        t[ty + r][tx] = in[(size_t)(k0 + ty + r) * N + n0 + tx];
    __syncthreads();
    #pragma unroll
    for (int r = 0; r < 32; r += 8)
        out[(size_t)(n0 + ty + r) * K + k0 + tx] = to_tf32(t[tx][ty + r]);
}

// ------- pack+transpose W_qkv[N,D,192] -> [(n*192+j), d] + tf32 round -------
__global__ __launch_bounds__(256) void pack_wqkv_t(
    const float* __restrict__ W, float* __restrict__ out)
{
    __shared__ float t[32][33];
    int j0 = blockIdx.x * 32, d0 = blockIdx.y * 32, n = blockIdx.z;
    int tx = threadIdx.x, ty = threadIdx.y;   // 32 x 8
    #pragma unroll
    for (int r = 0; r < 32; r += 8)
        t[ty + r][tx] = W[((size_t)n * DDIM + d0 + ty + r) * 192 + j0 + tx];
    __syncthreads();
    #pragma unroll
    for (int r = 0; r < 32; r += 8)
        out[((size_t)n * 192 + j0 + ty + r) * DDIM + d0 + tx] = to_tf32(t[tx][ty + r]);
}

// ---------------- w_sum[d] = sum_{n,h} W_out[n,h,d] -------------------------
__global__ __launch_bounds__(256) void wsum_kernel(
    const float* __restrict__ Wout, float* __restrict__ ws)
{
    int d = blockIdx.x * 256 + threadIdx.x;
    float s = 0.f;
    for (int i = 0; i < NHEAD * HDIM; ++i) s += Wout[(size_t)i * DDIM + d];
    ws[d] = s;
}

// ---------------- flash attention: 64 q x 64 k tiles, fp32 ------------------
__global__ __launch_bounds__(128) void flash_kernel(
    const float* __restrict__ qkv, float* __restrict__ atto)
{
    extern __shared__ float smf[];
    float* Qt = smf;                // Qt[h*64 + i]   (Q^T, pre-scaled)
    float* KP = smf + 64 * 64;      // K: KP[h*64+j]; later P: KP[i*65+j]
    float* Vs = KP + 64 * 65;       // Vs[j*64 + h]

    int qt = blockIdx.x, n = blockIdx.y, b = blockIdx.z;
    int tid = threadIdx.x;
    int ty = tid >> 4, tx = tid & 15;
    const float* base = qkv + (size_t)b * SDIM * QKVC + n * 192;

    #pragma unroll
    for (int it = 0; it < 8; ++it) {
        int idx = tid + it * 128;
        int r = idx >> 4;
        int h4 = (idx & 15) << 2;
        float4 v = *(const float4*)(base + (size_t)(qt * 64 + r) * QKVC + h4);
        Qt[(h4 + 0) * 64 + r] = v.x * 0.125f;
        Qt[(h4 + 1) * 64 + r] = v.y * 0.125f;
        Qt[(h4 + 2) * 64 + r] = v.z * 0.125f;
        Qt[(h4 + 3) * 64 + r] = v.w * 0.125f;
    }

    float m[8], l[8], acc[8][4];
    #pragma unroll
    for (int i = 0; i < 8; ++i) {
        m[i] = -INFINITY; l[i] = 0.f;
        acc[i][0] = acc[i][1] = acc[i][2] = acc[i][3] = 0.f;
    }

    for (int kt = 0; kt <= qt; ++kt) {
        __syncthreads();
        #pragma unroll
        for (int it = 0; it < 8; ++it) {
            int idx = tid + it * 128;
            int r = idx >> 4;
            int h4 = (idx & 15) << 2;
            const float* rb = base + (size_t)(kt * 64 + r) * QKVC + h4;
            float4 kv = *(const float4*)(rb + 64);
            KP[(h4 + 0) * 64 + r] = kv.x;
            KP[(h4 + 1) * 64 + r] = kv.y;
            KP[(h4 + 2) * 64 + r] = kv.z;
            KP[(h4 + 3) * 64 + r] = kv.w;
            float4 vv = *(const float4*)(rb + 128);
            *(float4*)(Vs + r * 64 + h4) = vv;
        }
        __syncthreads();

        float s[8][4];
        #pragma unroll
        for (int i = 0; i < 8; ++i)
            #pragma unroll
            for (int j = 0; j < 4; ++j) s[i][j] = 0.f;
        #pragma unroll 8
        for (int h = 0; h < 64; ++h) {
            float4 a0 = *(const float4*)(Qt + h * 64 + ty * 8);
            float4 a1 = *(const float4*)(Qt + h * 64 + ty * 8 + 4);
            float4 b0 = *(const float4*)(KP + h * 64 + tx * 4);
            float a[8] = {a0.x, a0.y, a0.z, a0.w, a1.x, a1.y, a1.z, a1.w};
            float bb[4] = {b0.x, b0.y, b0.z, b0.w};
            #pragma unroll
            for (int i = 0; i < 8; ++i)
                #pragma unroll
                for (int j = 0; j < 4; ++j)
                    s[i][j] += a[i] * bb[j];
        }

        if (kt == qt) {
            #pragma unroll
            for (int i = 0; i < 8; ++i)
                #pragma unroll
                for (int j = 0; j < 4; ++j)
                    if (tx * 4 + j > ty * 8 + i) s[i][j] = -INFINITY;
        }

        #pragma unroll
        for (int i = 0; i < 8; ++i) {
            float rm = fmaxf(fmaxf(s[i][0], s[i][1]), fmaxf(s[i][2], s[i][3]));
            #pragma unroll
            for (int o = 1; o < 16; o <<= 1)
                rm = fmaxf(rm, __shfl_xor_sync(0xffffffffu, rm, o, 16));
            float mnew = fmaxf(m[i], rm);
            float alpha = __expf(m[i] - mnew);
            m[i] = mnew;
            float rs = 0.f;
            #pragma unroll
            for (int j = 0; j < 4; ++j) {
                float p = __expf(s[i][j] - mnew);
                s[i][j] = p;
                rs += p;
            }
            #pragma unroll
            for (int o = 1; o < 16; o <<= 1)
                rs += __shfl_xor_sync(0xffffffffu, rs, o, 16);
            l[i] = l[i] * alpha + rs;
            acc[i][0] *= alpha; acc[i][1] *= alpha;
            acc[i][2] *= alpha; acc[i][3] *= alpha;
        }

        __syncthreads();
        #pragma unroll
        for (int i = 0; i < 8; ++i)
            #pragma unroll
            for (int j = 0; j < 4; ++j)
                KP[(ty * 8 + i) * 65 + tx * 4 + j] = s[i][j];
        __syncthreads();

        #pragma unroll 8
        for (int j = 0; j < 64; ++j) {
            float4 bv = *(const float4*)(Vs + j * 64 + tx * 4);
            #pragma unroll
            for (int i = 0; i < 8; ++i) {
                float a = KP[(ty * 8 + i) * 65 + j];
                acc[i][0] += a * bv.x;
                acc[i][1] += a * bv.y;
                acc[i][2] += a * bv.z;
                acc[i][3] += a * bv.w;
            }
        }
    }

    float* ob = atto + ((size_t)(b * NHEAD + n) * SDIM + qt * 64) * HDIM;
    #pragma unroll
    for (int i = 0; i < 8; ++i) {
        float inv = 1.0f / l[i];
        float4 o = make_float4(acc[i][0] * inv, acc[i][1] * inv,
                               acc[i][2] * inv, acc[i][3] * inv);
        *(float4*)(ob + (size_t)(ty * 8 + i) * HDIM + tx * 4) = o;
    }
}

// ------- residual + torch-reinterpretation "projection" ---------------------
__global__ void resid_attn(const float* __restrict__ x,
                           const float* __restrict__ atto,
                           const float* __restrict__ wsum,
                           float* __restrict__ x1)
{
    __shared__ float tile[32][33];
    int b = blockIdx.z;
    int d0 = blockIdx.x * 32, s0 = blockIdx.y * 32;
    int tx = threadIdx.x, ty = threadIdx.y;   // 32 x 8
    const float* ab = atto + (size_t)b * (DDIM * SDIM);
    #pragma unroll
    for (int r = 0; r < 32; r += 8) {
        int d = d0 + ty + r, s = s0 + tx;
        tile[ty + r][tx] = ab[(size_t)d * SDIM + s];
    }
    __syncthreads();
    #pragma unroll
    for (int r = 0; r < 32; r += 8) {
        int s = s0 + ty + r, d = d0 + tx;
        size_t idx = ((size_t)b * SDIM + s) * DDIM + d;
        x1[idx] = x[idx] + tile[tx][ty + r] * wsum[d];
    }
}

// ---------------------------------------------------------------------------
extern "C" void kernel_launch(void* const* d_in, const int* in_sizes, int n_in,
                              void* d_out, int out_size)
{
    const float* x    = (const float*)d_in[0];
    const float* Wqkv = (const float*)d_in[1];
    const float* Wout = (const float*)d_in[2];
    const float* ln1w = (const float*)d_in[3];
    const float* ln1b = (const float*)d_in[4];
    const float* ln2w = (const float*)d_in[5];
    const float* ln2b = (const float*)d_in[6];
    const float* W1   = (const float*)d_in[7];
    const float* b1   = (const float*)d_in[8];
    const float* W2   = (const float*)d_in[9];
    const float* b2   = (const float*)d_in[10];
    float* out = (float*)d_out;

    float *p_ln, *p_wqt, *p_w1t, *p_w2t, *p_qkv, *p_atto, *p_wsum, *p_x1, *p_h;
    cudaGetSymbolAddress((void**)&p_ln,   g_ln);
    cudaGetSymbolAddress((void**)&p_wqt,  g_wqt);
    cudaGetSymbolAddress((void**)&p_w1t,  g_w1t);
    cudaGetSymbolAddress((void**)&p_w2t,  g_w2t);
    cudaGetSymbolAddress((void**)&p_qkv,  g_qkv);
    cudaGetSymbolAddress((void**)&p_atto, g_atto);
    cudaGetSymbolAddress((void**)&p_wsum, g_wsum);
    cudaGetSymbolAddress((void**)&p_x1,   g_x1);
    cudaGetSymbolAddress((void**)&p_h,    g_h);

    cudaFuncSetAttribute(mma_gemm<0>, cudaFuncAttributeMaxDynamicSharedMemorySize, GEMM_SMEM);
    cudaFuncSetAttribute(mma_gemm<1>, cudaFuncAttributeMaxDynamicSharedMemorySize, GEMM_SMEM);
    cudaFuncSetAttribute(mma_gemm<2>, cudaFuncAttributeMaxDynamicSharedMemorySize, GEMM_SMEM);

    // ln1 + weight prep
    ln_kernel<<<ROWS, 256>>>(x, ln1w, ln1b, p_ln);
    pack_wqkv_t<<<dim3(6, 32, 16), dim3(32, 8)>>>(Wqkv, p_wqt);
    transpose_tf32<<<dim3(MDIM / 32, DDIM / 32), dim3(32, 8)>>>(W1, p_w1t, DDIM, MDIM);
    transpose_tf32<<<dim3(DDIM / 32, MDIM / 32), dim3(32, 8)>>>(W2, p_w2t, MDIM, DDIM);
    wsum_kernel<<<DDIM / 256, 256>>>(Wout, p_wsum);

    // QKV projection: [4096,1024] x [1024,3072]  (tf32 HMMA)
    mma_gemm<0><<<dim3(QKVC / 128, ROWS / 128), 256, GEMM_SMEM>>>(
        p_ln, p_wqt, p_qkv, ROWS, QKVC, DDIM, nullptr, nullptr);

    // attention (fp32 SIMT)
    int smem = (64 * 64 + 64 * 65 + 64 * 64) * (int)sizeof(float);
    cudaFuncSetAttribute(flash_kernel,
                         cudaFuncAttributeMaxDynamicSharedMemorySize, smem);
    flash_kernel<<<dim3(SDIM / 64, NHEAD, BDIM), 128, smem>>>(p_qkv, p_atto);

    // residual + reinterpretation-projection
    resid_attn<<<dim3(DDIM / 32, SDIM / 32, BDIM), dim3(32, 8)>>>(
        x, p_atto, p_wsum, p_x1);

    // ln2
    ln_kernel<<<ROWS, 256>>>(p_x1, ln2w, ln2b, p_ln);

    // MLP: gelu(ln2 @ W1 + b1) @ W2 + b2 + x1   (tf32 HMMA)
    mma_gemm<1><<<dim3(MDIM / 128, ROWS / 128), 256, GEMM_SMEM>>>(
        p_ln, p_w1t, p_h, ROWS, MDIM, DDIM, b1, nullptr);
    mma_gemm<2><<<dim3(DDIM / 128, ROWS / 128), 256, GEMM_SMEM>>>(
        p_h, p_w2t, out, ROWS, DDIM, MDIM, b2, p_x1);
}

// round 10
// speedup vs baseline: 2.2198x; 1.0070x over previous
#include <cuda_runtime.h>
#include <math.h>
#include <stdint.h>

// Problem constants
#define BDIM 2
#define SDIM 2048
#define DDIM 1024
#define NHEAD 16
#define HDIM 64
#define MDIM 4096
#define ROWS (BDIM*SDIM)          // 4096 token rows
#define QKVC (NHEAD*3*HDIM)       // 3072 packed qkv columns

// ---------------- scratch (device globals; no allocation allowed) ----------
__device__ float g_ln  [ROWS*DDIM];            // 16 MB, reused for ln1 & ln2
__device__ float g_wqt [QKVC*DDIM];            // 12 MB W_qkv^T  [3072,1024]
__device__ float g_w1t [MDIM*DDIM];            // 16 MB W1^T     [4096,1024]
__device__ float g_w2t [DDIM*MDIM];            // 16 MB W2^T     [1024,4096]
__device__ float g_qkv [ROWS*QKVC];            // 48 MB
__device__ float g_atto[BDIM*NHEAD*SDIM*HDIM]; // 16 MB attention out (b,n,s,h)
__device__ float g_wsum[DDIM];
__device__ float g_x1  [ROWS*DDIM];            // 16 MB residual after attention
__device__ float g_h   [ROWS*MDIM];            // 64 MB MLP hidden

// ============================ helpers =======================================
__device__ __forceinline__ float to_tf32(float x) {
    uint32_t u;
    asm("cvt.rna.tf32.f32 %0, %1;" : "=r"(u) : "f"(x));
    return __uint_as_float(u);
}
__device__ __forceinline__ uint32_t smem_u32(const void* p) {
    uint32_t a;
    asm("{ .reg .u64 t; cvta.to.shared.u64 t, %1; cvt.u32.u64 %0, t; }"
        : "=r"(a) : "l"(p));
    return a;
}
__device__ __forceinline__ void cp16(uint32_t dst, const void* src) {
    asm volatile("cp.async.cg.shared.global [%0], [%1], 16;" :: "r"(dst), "l"(src));
}
__device__ __forceinline__ float gelu_exact(float v) {
    return 0.5f * v * (1.0f + erff(v * 0.70710678118654752440f));
}

#define MMA_TF32(c, a, b) \
    asm volatile("mma.sync.aligned.m16n8k8.row.col.f32.tf32.tf32.f32 " \
        "{%0,%1,%2,%3}, {%4,%5,%6,%7}, {%8,%9}, {%0,%1,%2,%3};" \
        : "+f"((c)[0]), "+f"((c)[1]), "+f"((c)[2]), "+f"((c)[3]) \
        : "r"((a)[0]), "r"((a)[1]), "r"((a)[2]), "r"((a)[3]), \
          "r"((b)[0]), "r"((b)[1]))

// ========== tf32 HMMA GEMM: C[M,N] = A[M,K] * Bt[N,K]^T =====================
// A row-major [M,K], Bt row-major [N,K]. CTA tile 128x128, 256 thr (8 warps,
// 2x4 -> warp tile 64x32). K staged at 32, 3-deep cp.async pipeline.
// smem pitch 36 floats -> fragment LDS bank = (4q+k)%32: conflict-free.
#define PITCH 36
#define STAGE_F (128*PITCH)                    // floats per stage per operand
#define GEMM_SMEM (2*3*STAGE_F*4)              // 110592 bytes

// EPI: 0 = plain, 1 = +bias, gelu, tf32-round, 2 = +bias +res
template<int EPI>
__global__ __launch_bounds__(256)
void mma_gemm(const float* __restrict__ A, const float* __restrict__ Bt,
              float* __restrict__ C, int M, int N, int K,
              const float* __restrict__ bias, const float* __restrict__ res)
{
    extern __shared__ float sm[];
    float* As = sm;                 // [3][STAGE_F]
    float* Bs = sm + 3 * STAGE_F;

    const int tid = threadIdx.x;
    const int wid = tid >> 5, lane = tid & 31;
    const int bm = blockIdx.y * 128, bn = blockIdx.x * 128;
    const int mbase = (wid >> 2) * 64;      // warpM in {0,1}
    const int nbase = (wid & 3) * 32;       // warpN in {0..3}
    const int q = lane >> 2, r4 = lane & 3;

    const uint32_t sA = smem_u32(As);
    const uint32_t sB = smem_u32(Bs);
    const int nst = K >> 5;

    auto load_stage = [&](int s) {
        int slot = s - (s / 3) * 3;
        int k0 = s << 5;
        const float* Ag = A + (size_t)bm * K + k0;
        const float* Bg = Bt + (size_t)bn * K + k0;
        uint32_t ab = sA + slot * (STAGE_F * 4);
        uint32_t bb = sB + slot * (STAGE_F * 4);
        #pragma unroll
        for (int i = 0; i < 4; ++i) {
            int linear = i * 256 + tid;          // 0..1023
            int row = linear >> 3, c4 = linear & 7;
            uint32_t off = (uint32_t)(row * PITCH + c4 * 4) * 4;
            cp16(ab + off, Ag + (size_t)row * K + c4 * 4);
            cp16(bb + off, Bg + (size_t)row * K + c4 * 4);
        }
        asm volatile("cp.async.commit_group;" ::: "memory");
    };

    float c[4][4][4];
    #pragma unroll
    for (int mt = 0; mt < 4; ++mt)
        #pragma unroll
        for (int nt = 0; nt < 4; ++nt)
            #pragma unroll
            for (int j = 0; j < 4; ++j) c[mt][nt][j] = 0.f;

    load_stage(0); load_stage(1); load_stage(2);   // nst >= 3 always

    for (int s = 0; s < nst; ++s) {
        int slot = s - (s / 3) * 3;
        asm volatile("cp.async.wait_group 2;" ::: "memory");
        __syncthreads();

        const float* a_s = As + slot * STAGE_F;
        const float* b_s = Bs + slot * STAGE_F;
        #pragma unroll
        for (int kk = 0; kk < 4; ++kk) {
            int kb = kk * 8;
            uint32_t a[4][4];
            #pragma unroll
            for (int mt = 0; mt < 4; ++mt) {
                const float* ap = a_s + (mbase + mt * 16 + q) * PITCH + kb + r4;
                a[mt][0] = __float_as_uint(ap[0]);
                a[mt][1] = __float_as_uint(ap[8 * PITCH]);
                a[mt][2] = __float_as_uint(ap[4]);
                a[mt][3] = __float_as_uint(ap[8 * PITCH + 4]);
            }
            uint32_t b[4][2];
            #pragma unroll
            for (int nt = 0; nt < 4; ++nt) {
                const float* bp = b_s + (nbase + nt * 8 + q) * PITCH + kb + r4;
                b[nt][0] = __float_as_uint(bp[0]);
                b[nt][1] = __float_as_uint(bp[4]);
            }
            #pragma unroll
            for (int mt = 0; mt < 4; ++mt)
                #pragma unroll
                for (int nt = 0; nt < 4; ++nt)
                    MMA_TF32(c[mt][nt], a[mt], b[nt]);
        }

        __syncthreads();   // stage consumed before overwrite
        if (s + 3 < nst) load_stage(s + 3);
        else asm volatile("cp.async.commit_group;" ::: "memory");
    }

    // Epilogue. c0,c1: (row, 2*r4 +0/1); c2,c3: (row+8, same cols)
    #pragma unroll
    for (int mt = 0; mt < 4; ++mt) {
        #pragma unroll
        for (int nt = 0; nt < 4; ++nt) {
            int row0 = bm + mbase + mt * 16 + q;
            int col  = bn + nbase + nt * 8 + r4 * 2;
            #pragma unroll
            for (int h = 0; h < 2; ++h) {
                int row = row0 + h * 8;
                float vx = c[mt][nt][2 * h], vy = c[mt][nt][2 * h + 1];
                if (EPI == 1) {
                    vx = to_tf32(gelu_exact(vx + bias[col]));
                    vy = to_tf32(gelu_exact(vy + bias[col + 1]));
                } else if (EPI == 2) {
                    const float* rp = res + (size_t)row * N + col;
                    vx += bias[col] + rp[0];
                    vy += bias[col + 1] + rp[1];
                }
                *(float2*)(C + (size_t)row * N + col) = make_float2(vx, vy);
            }
        }
    }
}

// ---------------- layernorm (ddof=1, eps=1e-4) + tf32 rounding --------------
__global__ __launch_bounds__(256) void ln_kernel(
    const float* __restrict__ x, const float* __restrict__ w,
    const float* __restrict__ bb, float* __restrict__ y)
{
    int row = blockIdx.x;
    int t = threadIdx.x;
    const float4* xr = (const float4*)(x + (size_t)row * DDIM);
    float4 v = xr[t];

    __shared__ float red[8];
    __shared__ float s_mu, s_inv;

    float s = v.x + v.y + v.z + v.w;
    #pragma unroll
    for (int o = 16; o > 0; o >>= 1) s += __shfl_xor_sync(0xffffffffu, s, o);
    if ((t & 31) == 0) red[t >> 5] = s;
    __syncthreads();
    if (t == 0) {
        float tot = 0.f;
        #pragma unroll
        for (int i = 0; i < 8; ++i) tot += red[i];
        s_mu = tot * (1.0f / DDIM);
    }
    __syncthreads();
    float mu = s_mu;
    float dx = v.x - mu, dy = v.y - mu, dz = v.z - mu, dw = v.w - mu;
    float ss = dx*dx + dy*dy + dz*dz + dw*dw;
    #pragma unroll
    for (int o = 16; o > 0; o >>= 1) ss += __shfl_xor_sync(0xffffffffu, ss, o);
    __syncthreads();
    if ((t & 31) == 0) red[t >> 5] = ss;
    __syncthreads();
    if (t == 0) {
        float tot = 0.f;
        #pragma unroll
        for (int i = 0; i < 8; ++i) tot += red[i];
        s_inv = rsqrtf(tot * (1.0f / (DDIM - 1)) + 1e-4f);
    }
    __syncthreads();
    float inv = s_inv;
    float4 wv = ((const float4*)w)[t];
    float4 bv = ((const float4*)bb)[t];
    float4 o;
    o.x = to_tf32(dx * inv * wv.x + bv.x);
    o.y = to_tf32(dy * inv * wv.y + bv.y);
    o.z = to_tf32(dz * inv * wv.z + bv.z);
    o.w = to_tf32(dw * inv * wv.w + bv.w);
    ((float4*)(y + (size_t)row * DDIM))[t] = o;
}

// ------------- transpose [K,N] -> [N,K] with tf32 rounding ------------------
__global__ __launch_bounds__(256) void transpose_tf32(
    const float* __restrict__ in, float* __restrict__ out, int K, int N)
{
    __shared__ float t[32][33];
    int k0 = blockIdx.y * 32, n0 = blockIdx.x * 32;
    int tx = threadIdx.x, ty = threadIdx.y;   // 32 x 8
    #pragma unroll
    for (int r = 0; r < 32; r += 8)
        t[ty + r][tx] = in[(size_t)(k0 + ty + r) * N + n0 + tx];
    __syncthreads();
    #pragma unroll
    for (int r = 0; r < 32; r += 8)
        out[(size_t)(n0 + ty + r) * K + k0 + tx] = to_tf32(t[tx][ty + r]);
}

// ------- pack+transpose W_qkv[N,D,192] -> [(n*192+j), d] + tf32 round -------
__global__ __launch_bounds__(256) void pack_wqkv_t(
    const float* __restrict__ W, float* __restrict__ out)
{
    __shared__ float t[32][33];
    int j0 = blockIdx.x * 32, d0 = blockIdx.y * 32, n = blockIdx.z;
    int tx = threadIdx.x, ty = threadIdx.y;   // 32 x 8
    #pragma unroll
    for (int r = 0; r < 32; r += 8)
        t[ty + r][tx] = W[((size_t)n * DDIM + d0 + ty + r) * 192 + j0 + tx];
    __syncthreads();
    #pragma unroll
    for (int r = 0; r < 32; r += 8)
        out[((size_t)n * 192 + j0 + ty + r) * DDIM + d0 + tx] = to_tf32(t[tx][ty + r]);
}

// ---------------- w_sum[d] = sum_{n,h} W_out[n,h,d] -------------------------
__global__ __launch_bounds__(256) void wsum_kernel(
    const float* __restrict__ Wout, float* __restrict__ ws)
{
    int d = blockIdx.x * 256 + threadIdx.x;
    float s = 0.f;
    for (int i = 0; i < NHEAD * HDIM; ++i) s += Wout[(size_t)i * DDIM + d];
    ws[d] = s;
}

// ---------------- flash attention: 64 q x 64 k tiles, fp32 ------------------
__global__ __launch_bounds__(128) void flash_kernel(
    const float* __restrict__ qkv, float* __restrict__ atto)
{
    extern __shared__ float smf[];
    float* Qt = smf;                // Qt[h*64 + i]   (Q^T, pre-scaled)
    float* KP = smf + 64 * 64;      // K: KP[h*64+j]; later P: KP[i*65+j]
    float* Vs = KP + 64 * 65;       // Vs[j*64 + h]

    int qt = blockIdx.x, n = blockIdx.y, b = blockIdx.z;
    int tid = threadIdx.x;
    int ty = tid >> 4, tx = tid & 15;
    const float* base = qkv + (size_t)b * SDIM * QKVC + n * 192;

    #pragma unroll
    for (int it = 0; it < 8; ++it) {
        int idx = tid + it * 128;
        int r = idx >> 4;
        int h4 = (idx & 15) << 2;
        float4 v = *(const float4*)(base + (size_t)(qt * 64 + r) * QKVC + h4);
        Qt[(h4 + 0) * 64 + r] = v.x * 0.125f;
        Qt[(h4 + 1) * 64 + r] = v.y * 0.125f;
        Qt[(h4 + 2) * 64 + r] = v.z * 0.125f;
        Qt[(h4 + 3) * 64 + r] = v.w * 0.125f;
    }

    float m[8], l[8], acc[8][4];
    #pragma unroll
    for (int i = 0; i < 8; ++i) {
        m[i] = -INFINITY; l[i] = 0.f;
        acc[i][0] = acc[i][1] = acc[i][2] = acc[i][3] = 0.f;
    }

    for (int kt = 0; kt <= qt; ++kt) {
        __syncthreads();
        #pragma unroll
        for (int it = 0; it < 8; ++it) {
            int idx = tid + it * 128;
            int r = idx >> 4;
            int h4 = (idx & 15) << 2;
            const float* rb = base + (size_t)(kt * 64 + r) * QKVC + h4;
            float4 kv = *(const float4*)(rb + 64);
            KP[(h4 + 0) * 64 + r] = kv.x;
            KP[(h4 + 1) * 64 + r] = kv.y;
            KP[(h4 + 2) * 64 + r] = kv.z;
            KP[(h4 + 3) * 64 + r] = kv.w;
            float4 vv = *(const float4*)(rb + 128);
            *(float4*)(Vs + r * 64 + h4) = vv;
        }
        __syncthreads();

        float s[8][4];
        #pragma unroll
        for (int i = 0; i < 8; ++i)
            #pragma unroll
            for (int j = 0; j < 4; ++j) s[i][j] = 0.f;
        #pragma unroll 8
        for (int h = 0; h < 64; ++h) {
            float4 a0 = *(const float4*)(Qt + h * 64 + ty * 8);
            float4 a1 = *(const float4*)(Qt + h * 64 + ty * 8 + 4);
            float4 b0 = *(const float4*)(KP + h * 64 + tx * 4);
            float a[8] = {a0.x, a0.y, a0.z, a0.w, a1.x, a1.y, a1.z, a1.w};
            float bb[4] = {b0.x, b0.y, b0.z, b0.w};
            #pragma unroll
            for (int i = 0; i < 8; ++i)
                #pragma unroll
                for (int j = 0; j < 4; ++j)
                    s[i][j] += a[i] * bb[j];
        }

        if (kt == qt) {
            #pragma unroll
            for (int i = 0; i < 8; ++i)
                #pragma unroll
                for (int j = 0; j < 4; ++j)
                    if (tx * 4 + j > ty * 8 + i) s[i][j] = -INFINITY;
        }

        #pragma unroll
        for (int i = 0; i < 8; ++i) {
            float rm = fmaxf(fmaxf(s[i][0], s[i][1]), fmaxf(s[i][2], s[i][3]));
            #pragma unroll
            for (int o = 1; o < 16; o <<= 1)
                rm = fmaxf(rm, __shfl_xor_sync(0xffffffffu, rm, o, 16));
            float mnew = fmaxf(m[i], rm);
            float alpha = __expf(m[i] - mnew);
            m[i] = mnew;
            float rs = 0.f;
            #pragma unroll
            for (int j = 0; j < 4; ++j) {
                float p = __expf(s[i][j] - mnew);
                s[i][j] = p;
                rs += p;
            }
            #pragma unroll
            for (int o = 1; o < 16; o <<= 1)
                rs += __shfl_xor_sync(0xffffffffu, rs, o, 16);
            l[i] = l[i] * alpha + rs;
            acc[i][0] *= alpha; acc[i][1] *= alpha;
            acc[i][2] *= alpha; acc[i][3] *= alpha;
        }

        __syncthreads();
        #pragma unroll
        for (int i = 0; i < 8; ++i)
            #pragma unroll
            for (int j = 0; j < 4; ++j)
                KP[(ty * 8 + i) * 65 + tx * 4 + j] = s[i][j];
        __syncthreads();

        #pragma unroll 8
        for (int j = 0; j < 64; ++j) {
            float4 bv = *(const float4*)(Vs + j * 64 + tx * 4);
            #pragma unroll
            for (int i = 0; i < 8; ++i) {
                float a = KP[(ty * 8 + i) * 65 + j];
                acc[i][0] += a * bv.x;
                acc[i][1] += a * bv.y;
                acc[i][2] += a * bv.z;
                acc[i][3] += a * bv.w;
            }
        }
    }

    float* ob = atto + ((size_t)(b * NHEAD + n) * SDIM + qt * 64) * HDIM;
    #pragma unroll
    for (int i = 0; i < 8; ++i) {
        float inv = 1.0f / l[i];
        float4 o = make_float4(acc[i][0] * inv, acc[i][1] * inv,
                               acc[i][2] * inv, acc[i][3] * inv);
        *(float4*)(ob + (size_t)(ty * 8 + i) * HDIM + tx * 4) = o;
    }
}

// ------- residual + torch-reinterpretation "projection" ---------------------
__global__ void resid_attn(const float* __restrict__ x,
                           const float* __restrict__ atto,
                           const float* __restrict__ wsum,
                           float* __restrict__ x1)
{
    __shared__ float tile[32][33];
    int b = blockIdx.z;
    int d0 = blockIdx.x * 32, s0 = blockIdx.y * 32;
    int tx = threadIdx.x, ty = threadIdx.y;   // 32 x 8
    const float* ab = atto + (size_t)b * (DDIM * SDIM);
    #pragma unroll
    for (int r = 0; r < 32; r += 8) {
        int d = d0 + ty + r, s = s0 + tx;
        tile[ty + r][tx] = ab[(size_t)d * SDIM + s];
    }
    __syncthreads();
    #pragma unroll
    for (int r = 0; r < 32; r += 8) {
        int s = s0 + ty + r, d = d0 + tx;
        size_t idx = ((size_t)b * SDIM + s) * DDIM + d;
        x1[idx] = x[idx] + tile[tx][ty + r] * wsum[d];
    }
}

// ---------------------------------------------------------------------------
extern "C" void kernel_launch(void* const* d_in, const int* in_sizes, int n_in,
                              void* d_out, int out_size)
{
    const float* x    = (const float*)d_in[0];
    const float* Wqkv = (const float*)d_in[1];
    const float* Wout = (const float*)d_in[2];
    const float* ln1w = (const float*)d_in[3];
    const float* ln1b = (const float*)d_in[4];
    const float* ln2w = (const float*)d_in[5];
    const float* ln2b = (const float*)d_in[6];
    const float* W1   = (const float*)d_in[7];
    const float* b1   = (const float*)d_in[8];
    const float* W2   = (const float*)d_in[9];
    const float* b2   = (const float*)d_in[10];
    float* out = (float*)d_out;

    float *p_ln, *p_wqt, *p_w1t, *p_w2t, *p_qkv, *p_atto, *p_wsum, *p_x1, *p_h;
    cudaGetSymbolAddress((void**)&p_ln,   g_ln);
    cudaGetSymbolAddress((void**)&p_wqt,  g_wqt);
    cudaGetSymbolAddress((void**)&p_w1t,  g_w1t);
    cudaGetSymbolAddress((void**)&p_w2t,  g_w2t);
    cudaGetSymbolAddress((void**)&p_qkv,  g_qkv);
    cudaGetSymbolAddress((void**)&p_atto, g_atto);
    cudaGetSymbolAddress((void**)&p_wsum, g_wsum);
    cudaGetSymbolAddress((void**)&p_x1,   g_x1);
    cudaGetSymbolAddress((void**)&p_h,    g_h);

    cudaFuncSetAttribute(mma_gemm<0>, cudaFuncAttributeMaxDynamicSharedMemorySize, GEMM_SMEM);
    cudaFuncSetAttribute(mma_gemm<1>, cudaFuncAttributeMaxDynamicSharedMemorySize, GEMM_SMEM);
    cudaFuncSetAttribute(mma_gemm<2>, cudaFuncAttributeMaxDynamicSharedMemorySize, GEMM_SMEM);

    // ln1 + weight prep
    ln_kernel<<<ROWS, 256>>>(x, ln1w, ln1b, p_ln);
    pack_wqkv_t<<<dim3(6, 32, 16), dim3(32, 8)>>>(Wqkv, p_wqt);
    transpose_tf32<<<dim3(MDIM / 32, DDIM / 32), dim3(32, 8)>>>(W1, p_w1t, DDIM, MDIM);
    transpose_tf32<<<dim3(DDIM / 32, MDIM / 32), dim3(32, 8)>>>(W2, p_w2t, MDIM, DDIM);
    wsum_kernel<<<DDIM / 256, 256>>>(Wout, p_wsum);

    // QKV projection: [4096,1024] x [1024,3072]  (tf32 HMMA)
    mma_gemm<0><<<dim3(QKVC / 128, ROWS / 128), 256, GEMM_SMEM>>>(
        p_ln, p_wqt, p_qkv, ROWS, QKVC, DDIM, nullptr, nullptr);

    // attention (fp32 SIMT)
    int smem = (64 * 64 + 64 * 65 + 64 * 64) * (int)sizeof(float);
    cudaFuncSetAttribute(flash_kernel,
                         cudaFuncAttributeMaxDynamicSharedMemorySize, smem);
    flash_kernel<<<dim3(SDIM / 64, NHEAD, BDIM), 128, smem>>>(p_qkv, p_atto);

    // residual + reinterpretation-projection
    resid_attn<<<dim3(DDIM / 32, SDIM / 32, BDIM), dim3(32, 8)>>>(
        x, p_atto, p_wsum, p_x1);

    // ln2
    ln_kernel<<<ROWS, 256>>>(p_x1, ln2w, ln2b, p_ln);

    // MLP: gelu(ln2 @ W1 + b1) @ W2 + b2 + x1   (tf32 HMMA)
    mma_gemm<1><<<dim3(MDIM / 128, ROWS / 128), 256, GEMM_SMEM>>>(
        p_ln, p_w1t, p_h, ROWS, MDIM, DDIM, b1, nullptr);
    mma_gemm<2><<<dim3(DDIM / 128, ROWS / 128), 256, GEMM_SMEM>>>(
        p_h, p_w2t, out, ROWS, DDIM, MDIM, b2, p_x1);
}

// round 11
// speedup vs baseline: 3.0728x; 1.3843x over previous
#include <cuda_runtime.h>
#include <math.h>
#include <stdint.h>

// Problem constants
#define BDIM 2
#define SDIM 2048
#define DDIM 1024
#define NHEAD 16
#define HDIM 64
#define MDIM 4096
#define ROWS (BDIM*SDIM)          // 4096 token rows
#define QKVC (NHEAD*3*HDIM)       // 3072 packed qkv columns

// ---------------- scratch (device globals; no allocation allowed) ----------
__device__ float g_ln  [ROWS*DDIM];            // 16 MB, reused for ln1 & ln2
__device__ float g_wqt [QKVC*DDIM];            // 12 MB W_qkv^T  [3072,1024]
__device__ float g_w1t [MDIM*DDIM];            // 16 MB W1^T     [4096,1024]
__device__ float g_w2t [DDIM*MDIM];            // 16 MB W2^T     [1024,4096]
__device__ float g_qkv [ROWS*QKVC];            // 48 MB
__device__ float g_atto[BDIM*NHEAD*SDIM*HDIM]; // 16 MB attention out (b,n,s,h)
__device__ float g_wsum[DDIM];
__device__ float g_x1  [ROWS*DDIM];            // 16 MB residual after attention
__device__ float g_h   [ROWS*MDIM];            // 64 MB MLP hidden

// ============================ helpers =======================================
__device__ __forceinline__ float to_tf32(float x) {
    uint32_t u;
    asm("cvt.rna.tf32.f32 %0, %1;" : "=r"(u) : "f"(x));
    return __uint_as_float(u);
}
__device__ __forceinline__ uint32_t smem_u32(const void* p) {
    uint32_t a;
    asm("{ .reg .u64 t; cvta.to.shared.u64 t, %1; cvt.u32.u64 %0, t; }"
        : "=r"(a) : "l"(p));
    return a;
}
__device__ __forceinline__ void cp16(uint32_t dst, const void* src) {
    asm volatile("cp.async.cg.shared.global [%0], [%1], 16;" :: "r"(dst), "l"(src));
}
__device__ __forceinline__ float gelu_exact(float v) {
    return 0.5f * v * (1.0f + erff(v * 0.70710678118654752440f));
}

#define MMA_TF32(c, a, b) \
    asm volatile("mma.sync.aligned.m16n8k8.row.col.f32.tf32.tf32.f32 " \
        "{%0,%1,%2,%3}, {%4,%5,%6,%7}, {%8,%9}, {%0,%1,%2,%3};" \
        : "+f"((c)[0]), "+f"((c)[1]), "+f"((c)[2]), "+f"((c)[3]) \
        : "r"((a)[0]), "r"((a)[1]), "r"((a)[2]), "r"((a)[3]), \
          "r"((b)[0]), "r"((b)[1]))

// ========== tf32 HMMA GEMM: C[M,N] = A[M,K] * Bt[N,K]^T =====================
#define PITCH 36
#define STAGE_F (128*PITCH)
#define GEMM_SMEM (2*3*STAGE_F*4)              // 110592 bytes

// EPI: 0 = plain, 1 = +bias, gelu, tf32-round, 2 = +bias +res, 3 = tf32-round
template<int EPI>
__global__ __launch_bounds__(256)
void mma_gemm(const float* __restrict__ A, const float* __restrict__ Bt,
              float* __restrict__ C, int M, int N, int K,
              const float* __restrict__ bias, const float* __restrict__ res)
{
    extern __shared__ float sm[];
    float* As = sm;                 // [3][STAGE_F]
    float* Bs = sm + 3 * STAGE_F;

    const int tid = threadIdx.x;
    const int wid = tid >> 5, lane = tid & 31;
    const int bm = blockIdx.y * 128, bn = blockIdx.x * 128;
    const int mbase = (wid >> 2) * 64;
    const int nbase = (wid & 3) * 32;
    const int q = lane >> 2, r4 = lane & 3;

    const uint32_t sA = smem_u32(As);
    const uint32_t sB = smem_u32(Bs);
    const int nst = K >> 5;

    auto load_stage = [&](int s) {
        int slot = s - (s / 3) * 3;
        int k0 = s << 5;
        const float* Ag = A + (size_t)bm * K + k0;
        const float* Bg = Bt + (size_t)bn * K + k0;
        uint32_t ab = sA + slot * (STAGE_F * 4);
        uint32_t bb = sB + slot * (STAGE_F * 4);
        #pragma unroll
        for (int i = 0; i < 4; ++i) {
            int linear = i * 256 + tid;
            int row = linear >> 3, c4 = linear & 7;
            uint32_t off = (uint32_t)(row * PITCH + c4 * 4) * 4;
            cp16(ab + off, Ag + (size_t)row * K + c4 * 4);
            cp16(bb + off, Bg + (size_t)row * K + c4 * 4);
        }
        asm volatile("cp.async.commit_group;" ::: "memory");
    };

    float c[4][4][4];
    #pragma unroll
    for (int mt = 0; mt < 4; ++mt)
        #pragma unroll
        for (int nt = 0; nt < 4; ++nt)
            #pragma unroll
            for (int j = 0; j < 4; ++j) c[mt][nt][j] = 0.f;

    load_stage(0); load_stage(1); load_stage(2);

    for (int s = 0; s < nst; ++s) {
        int slot = s - (s / 3) * 3;
        asm volatile("cp.async.wait_group 2;" ::: "memory");
        __syncthreads();

        const float* a_s = As + slot * STAGE_F;
        const float* b_s = Bs + slot * STAGE_F;
        #pragma unroll
        for (int kk = 0; kk < 4; ++kk) {
            int kb = kk * 8;
            uint32_t a[4][4];
            #pragma unroll
            for (int mt = 0; mt < 4; ++mt) {
                const float* ap = a_s + (mbase + mt * 16 + q) * PITCH + kb + r4;
                a[mt][0] = __float_as_uint(ap[0]);
                a[mt][1] = __float_as_uint(ap[8 * PITCH]);
                a[mt][2] = __float_as_uint(ap[4]);
                a[mt][3] = __float_as_uint(ap[8 * PITCH + 4]);
            }
            uint32_t b[4][2];
            #pragma unroll
            for (int nt = 0; nt < 4; ++nt) {
                const float* bp = b_s + (nbase + nt * 8 + q) * PITCH + kb + r4;
                b[nt][0] = __float_as_uint(bp[0]);
                b[nt][1] = __float_as_uint(bp[4]);
            }
            #pragma unroll
            for (int mt = 0; mt < 4; ++mt)
                #pragma unroll
                for (int nt = 0; nt < 4; ++nt)
                    MMA_TF32(c[mt][nt], a[mt], b[nt]);
        }

        __syncthreads();
        if (s + 3 < nst) load_stage(s + 3);
        else asm volatile("cp.async.commit_group;" ::: "memory");
    }

    #pragma unroll
    for (int mt = 0; mt < 4; ++mt) {
        #pragma unroll
        for (int nt = 0; nt < 4; ++nt) {
            int row0 = bm + mbase + mt * 16 + q;
            int col  = bn + nbase + nt * 8 + r4 * 2;
            #pragma unroll
            for (int h = 0; h < 2; ++h) {
                int row = row0 + h * 8;
                float vx = c[mt][nt][2 * h], vy = c[mt][nt][2 * h + 1];
                if (EPI == 1) {
                    vx = to_tf32(gelu_exact(vx + bias[col]));
                    vy = to_tf32(gelu_exact(vy + bias[col + 1]));
                } else if (EPI == 2) {
                    const float* rp = res + (size_t)row * N + col;
                    vx += bias[col] + rp[0];
                    vy += bias[col + 1] + rp[1];
                } else if (EPI == 3) {
                    vx = to_tf32(vx);
                    vy = to_tf32(vy);
                }
                *(float2*)(C + (size_t)row * N + col) = make_float2(vx, vy);
            }
        }
    }
}

// ---------------- layernorm (ddof=1, eps=1e-4) + tf32 rounding --------------
__global__ __launch_bounds__(256) void ln_kernel(
    const float* __restrict__ x, const float* __restrict__ w,
    const float* __restrict__ bb, float* __restrict__ y)
{
    int row = blockIdx.x;
    int t = threadIdx.x;
    const float4* xr = (const float4*)(x + (size_t)row * DDIM);
    float4 v = xr[t];

    __shared__ float red[8];
    __shared__ float s_mu, s_inv;

    float s = v.x + v.y + v.z + v.w;
    #pragma unroll
    for (int o = 16; o > 0; o >>= 1) s += __shfl_xor_sync(0xffffffffu, s, o);
    if ((t & 31) == 0) red[t >> 5] = s;
    __syncthreads();
    if (t == 0) {
        float tot = 0.f;
        #pragma unroll
        for (int i = 0; i < 8; ++i) tot += red[i];
        s_mu = tot * (1.0f / DDIM);
    }
    __syncthreads();
    float mu = s_mu;
    float dx = v.x - mu, dy = v.y - mu, dz = v.z - mu, dw = v.w - mu;
    float ss = dx*dx + dy*dy + dz*dz + dw*dw;
    #pragma unroll
    for (int o = 16; o > 0; o >>= 1) ss += __shfl_xor_sync(0xffffffffu, ss, o);
    __syncthreads();
    if ((t & 31) == 0) red[t >> 5] = ss;
    __syncthreads();
    if (t == 0) {
        float tot = 0.f;
        #pragma unroll
        for (int i = 0; i < 8; ++i) tot += red[i];
        s_inv = rsqrtf(tot * (1.0f / (DDIM - 1)) + 1e-4f);
    }
    __syncthreads();
    float inv = s_inv;
    float4 wv = ((const float4*)w)[t];
    float4 bv = ((const float4*)bb)[t];
    float4 o;
    o.x = to_tf32(dx * inv * wv.x + bv.x);
    o.y = to_tf32(dy * inv * wv.y + bv.y);
    o.z = to_tf32(dz * inv * wv.z + bv.z);
    o.w = to_tf32(dw * inv * wv.w + bv.w);
    ((float4*)(y + (size_t)row * DDIM))[t] = o;
}

// ------------- transpose [K,N] -> [N,K] with tf32 rounding ------------------
__global__ __launch_bounds__(256) void transpose_tf32(
    const float* __restrict__ in, float* __restrict__ out, int K, int N)
{
    __shared__ float t[32][33];
    int k0 = blockIdx.y * 32, n0 = blockIdx.x * 32;
    int tx = threadIdx.x, ty = threadIdx.y;
    #pragma unroll
    for (int r = 0; r < 32; r += 8)
        t[ty + r][tx] = in[(size_t)(k0 + ty + r) * N + n0 + tx];
    __syncthreads();
    #pragma unroll
    for (int r = 0; r < 32; r += 8)
        out[(size_t)(n0 + ty + r) * K + k0 + tx] = to_tf32(t[tx][ty + r]);
}

// ------- pack+transpose W_qkv[N,D,192] -> [(n*192+j), d] + tf32 round -------
__global__ __launch_bounds__(256) void pack_wqkv_t(
    const float* __restrict__ W, float* __restrict__ out)
{
    __shared__ float t[32][33];
    int j0 = blockIdx.x * 32, d0 = blockIdx.y * 32, n = blockIdx.z;
    int tx = threadIdx.x, ty = threadIdx.y;
    #pragma unroll
    for (int r = 0; r < 32; r += 8)
        t[ty + r][tx] = W[((size_t)n * DDIM + d0 + ty + r) * 192 + j0 + tx];
    __syncthreads();
    #pragma unroll
    for (int r = 0; r < 32; r += 8)
        out[((size_t)n * 192 + j0 + ty + r) * DDIM + d0 + tx] = to_tf32(t[tx][ty + r]);
}

// ---------------- w_sum[d] = sum_{n,h} W_out[n,h,d] -------------------------
__global__ __launch_bounds__(256) void wsum_kernel(
    const float* __restrict__ Wout, float* __restrict__ ws)
{
    int d = blockIdx.x * 256 + threadIdx.x;
    float s = 0.f;
    for (int i = 0; i < NHEAD * HDIM; ++i) s += Wout[(size_t)i * DDIM + d];
    ws[d] = s;
}

// ============ flash attention with tf32 HMMA: 64q x 64k tiles ===============
// 128 threads / 4 warps; warp w owns q rows [w*16, w*16+16).
// smem pitch 68 (68 % 32 == 4) -> fragment LDS bank = (4q+r4)%32, conflict-free
#define FP 68
#define FLASH_SMEM (4*64*FP*4)   // Qs, Ks, Vt, Ps = 69632 bytes

__global__ __launch_bounds__(128) void flash_mma(
    const float* __restrict__ qkv, float* __restrict__ atto)
{
    extern __shared__ float smf[];
    float* Qs = smf;                 // [64][FP] Q, scaled, row-major (q x h)
    float* Ks = smf + 64 * FP;       // [64][FP] K row-major (j x h)
    float* Vt = smf + 2 * 64 * FP;   // [64][FP] V transposed (h x j)
    float* Ps = smf + 3 * 64 * FP;   // [64][FP] P, warp-private row bands

    const int qt = blockIdx.x, n = blockIdx.y, b = blockIdx.z;
    const int tid = threadIdx.x, wid = tid >> 5, lane = tid & 31;
    const int q = lane >> 2, r4 = lane & 3;
    const int mrow = wid * 16;
    const float* base = qkv + (size_t)b * SDIM * QKVC + n * 192;

    // load Q tile (already tf32-rounded in gmem; *0.125 is exact)
    #pragma unroll
    for (int i = 0; i < 8; ++i) {
        int linear = i * 128 + tid;
        int row = linear >> 4, c4 = (linear & 15) << 2;
        float4 v = *(const float4*)(base + (size_t)(qt * 64 + row) * QKVC + c4);
        float* dst = Qs + row * FP + c4;
        dst[0] = v.x * 0.125f; dst[1] = v.y * 0.125f;
        dst[2] = v.z * 0.125f; dst[3] = v.w * 0.125f;
    }

    float m0 = -INFINITY, m1 = -INFINITY, l0 = 0.f, l1 = 0.f;
    float o[8][4];
    #pragma unroll
    for (int nt = 0; nt < 8; ++nt)
        o[nt][0] = o[nt][1] = o[nt][2] = o[nt][3] = 0.f;

    for (int kt = 0; kt <= qt; ++kt) {
        __syncthreads();
        // load K row-major, V transposed
        #pragma unroll
        for (int i = 0; i < 8; ++i) {
            int linear = i * 128 + tid;
            int row = linear >> 4, c4 = (linear & 15) << 2;
            const float* rb = base + (size_t)(kt * 64 + row) * QKVC;
            float4 kv = *(const float4*)(rb + 64 + c4);
            float* kd = Ks + row * FP + c4;
            kd[0] = kv.x; kd[1] = kv.y; kd[2] = kv.z; kd[3] = kv.w;
            float4 vv = *(const float4*)(rb + 128 + c4);
            Vt[(c4 + 0) * FP + row] = vv.x;
            Vt[(c4 + 1) * FP + row] = vv.y;
            Vt[(c4 + 2) * FP + row] = vv.z;
            Vt[(c4 + 3) * FP + row] = vv.w;
        }
        __syncthreads();

        // S = Q @ K^T  (16x64 per warp, k=64)
        float c[8][4];
        #pragma unroll
        for (int nt = 0; nt < 8; ++nt)
            c[nt][0] = c[nt][1] = c[nt][2] = c[nt][3] = 0.f;
        #pragma unroll
        for (int kk = 0; kk < 8; ++kk) {
            int kb = kk * 8;
            const float* ap = Qs + (mrow + q) * FP + kb + r4;
            uint32_t a[4] = {__float_as_uint(ap[0]), __float_as_uint(ap[8 * FP]),
                             __float_as_uint(ap[4]), __float_as_uint(ap[8 * FP + 4])};
            #pragma unroll
            for (int nt = 0; nt < 8; ++nt) {
                const float* bp = Ks + (nt * 8 + q) * FP + kb + r4;
                uint32_t bf[2] = {__float_as_uint(bp[0]), __float_as_uint(bp[4])};
                MMA_TF32(c[nt], a, bf);
            }
        }

        // causal mask on diagonal tile (relative indices: qt==kt)
        if (kt == qt) {
            int i0 = mrow + q;
            #pragma unroll
            for (int nt = 0; nt < 8; ++nt) {
                int j0 = nt * 8 + 2 * r4;
                if (j0     > i0)     c[nt][0] = -INFINITY;
                if (j0 + 1 > i0)     c[nt][1] = -INFINITY;
                if (j0     > i0 + 8) c[nt][2] = -INFINITY;
                if (j0 + 1 > i0 + 8) c[nt][3] = -INFINITY;
            }
        }

        // online softmax; rows live in 4 lanes (xor 1,2)
        float rm0 = -INFINITY, rm1 = -INFINITY;
        #pragma unroll
        for (int nt = 0; nt < 8; ++nt) {
            rm0 = fmaxf(rm0, fmaxf(c[nt][0], c[nt][1]));
            rm1 = fmaxf(rm1, fmaxf(c[nt][2], c[nt][3]));
        }
        rm0 = fmaxf(rm0, __shfl_xor_sync(0xffffffffu, rm0, 1));
        rm0 = fmaxf(rm0, __shfl_xor_sync(0xffffffffu, rm0, 2));
        rm1 = fmaxf(rm1, __shfl_xor_sync(0xffffffffu, rm1, 1));
        rm1 = fmaxf(rm1, __shfl_xor_sync(0xffffffffu, rm1, 2));
        float mn0 = fmaxf(m0, rm0), mn1 = fmaxf(m1, rm1);
        float al0 = __expf(m0 - mn0), al1 = __expf(m1 - mn1);
        m0 = mn0; m1 = mn1;
        float rs0 = 0.f, rs1 = 0.f;
        #pragma unroll
        for (int nt = 0; nt < 8; ++nt) {
            c[nt][0] = __expf(c[nt][0] - mn0); rs0 += c[nt][0];
            c[nt][1] = __expf(c[nt][1] - mn0); rs0 += c[nt][1];
            c[nt][2] = __expf(c[nt][2] - mn1); rs1 += c[nt][2];
            c[nt][3] = __expf(c[nt][3] - mn1); rs1 += c[nt][3];
        }
        rs0 += __shfl_xor_sync(0xffffffffu, rs0, 1);
        rs0 += __shfl_xor_sync(0xffffffffu, rs0, 2);
        rs1 += __shfl_xor_sync(0xffffffffu, rs1, 1);
        rs1 += __shfl_xor_sync(0xffffffffu, rs1, 2);
        l0 = l0 * al0 + rs0;
        l1 = l1 * al1 + rs1;
        #pragma unroll
        for (int nt = 0; nt < 8; ++nt) {
            o[nt][0] *= al0; o[nt][1] *= al0;
            o[nt][2] *= al1; o[nt][3] *= al1;
        }

        // P -> warp-private smem band (tf32-rounded), then A-fragment reload
        __syncwarp();
        float* pr = Ps + (mrow + q) * FP;
        #pragma unroll
        for (int nt = 0; nt < 8; ++nt) {
            *(float2*)(pr + nt * 8 + 2 * r4) =
                make_float2(to_tf32(c[nt][0]), to_tf32(c[nt][1]));
            *(float2*)(pr + 8 * FP + nt * 8 + 2 * r4) =
                make_float2(to_tf32(c[nt][2]), to_tf32(c[nt][3]));
        }
        __syncwarp();

        // O += P @ V   (A = P [16 x 64], B = Vt rows = h)
        #pragma unroll
        for (int kk = 0; kk < 8; ++kk) {
            int kb = kk * 8;
            const float* ap = Ps + (mrow + q) * FP + kb + r4;
            uint32_t a[4] = {__float_as_uint(ap[0]), __float_as_uint(ap[8 * FP]),
                             __float_as_uint(ap[4]), __float_as_uint(ap[8 * FP + 4])};
            #pragma unroll
            for (int nt = 0; nt < 8; ++nt) {
                const float* bp = Vt + (nt * 8 + q) * FP + kb + r4;
                uint32_t bf[2] = {__float_as_uint(bp[0]), __float_as_uint(bp[4])};
                MMA_TF32(o[nt], a, bf);
            }
        }
    }

    // normalize + store (b,n,s,h)
    float inv0 = 1.0f / l0, inv1 = 1.0f / l1;
    float* ob = atto + ((size_t)(b * NHEAD + n) * SDIM + qt * 64) * HDIM;
    int row0 = mrow + q;
    #pragma unroll
    for (int nt = 0; nt < 8; ++nt) {
        int col = nt * 8 + 2 * r4;
        *(float2*)(ob + (size_t)row0 * HDIM + col) =
            make_float2(o[nt][0] * inv0, o[nt][1] * inv0);
        *(float2*)(ob + (size_t)(row0 + 8) * HDIM + col) =
            make_float2(o[nt][2] * inv1, o[nt][3] * inv1);
    }
}

// ------- residual + torch-reinterpretation "projection" ---------------------
__global__ void resid_attn(const float* __restrict__ x,
                           const float* __restrict__ atto,
                           const float* __restrict__ wsum,
                           float* __restrict__ x1)
{
    __shared__ float tile[32][33];
    int b = blockIdx.z;
    int d0 = blockIdx.x * 32, s0 = blockIdx.y * 32;
    int tx = threadIdx.x, ty = threadIdx.y;
    const float* ab = atto + (size_t)b * (DDIM * SDIM);
    #pragma unroll
    for (int r = 0; r < 32; r += 8) {
        int d = d0 + ty + r, s = s0 + tx;
        tile[ty + r][tx] = ab[(size_t)d * SDIM + s];
    }
    __syncthreads();
    #pragma unroll
    for (int r = 0; r < 32; r += 8) {
        int s = s0 + ty + r, d = d0 + tx;
        size_t idx = ((size_t)b * SDIM + s) * DDIM + d;
        x1[idx] = x[idx] + tile[tx][ty + r] * wsum[d];
    }
}

// ---------------------------------------------------------------------------
extern "C" void kernel_launch(void* const* d_in, const int* in_sizes, int n_in,
                              void* d_out, int out_size)
{
    const float* x    = (const float*)d_in[0];
    const float* Wqkv = (const float*)d_in[1];
    const float* Wout = (const float*)d_in[2];
    const float* ln1w = (const float*)d_in[3];
    const float* ln1b = (const float*)d_in[4];
    const float* ln2w = (const float*)d_in[5];
    const float* ln2b = (const float*)d_in[6];
    const float* W1   = (const float*)d_in[7];
    const float* b1   = (const float*)d_in[8];
    const float* W2   = (const float*)d_in[9];
    const float* b2   = (const float*)d_in[10];
    float* out = (float*)d_out;

    float *p_ln, *p_wqt, *p_w1t, *p_w2t, *p_qkv, *p_atto, *p_wsum, *p_x1, *p_h;
    cudaGetSymbolAddress((void**)&p_ln,   g_ln);
    cudaGetSymbolAddress((void**)&p_wqt,  g_wqt);
    cudaGetSymbolAddress((void**)&p_w1t,  g_w1t);
    cudaGetSymbolAddress((void**)&p_w2t,  g_w2t);
    cudaGetSymbolAddress((void**)&p_qkv,  g_qkv);
    cudaGetSymbolAddress((void**)&p_atto, g_atto);
    cudaGetSymbolAddress((void**)&p_wsum, g_wsum);
    cudaGetSymbolAddress((void**)&p_x1,   g_x1);
    cudaGetSymbolAddress((void**)&p_h,    g_h);

    cudaFuncSetAttribute(mma_gemm<1>, cudaFuncAttributeMaxDynamicSharedMemorySize, GEMM_SMEM);
    cudaFuncSetAttribute(mma_gemm<2>, cudaFuncAttributeMaxDynamicSharedMemorySize, GEMM_SMEM);
    cudaFuncSetAttribute(mma_gemm<3>, cudaFuncAttributeMaxDynamicSharedMemorySize, GEMM_SMEM);
    cudaFuncSetAttribute(flash_mma, cudaFuncAttributeMaxDynamicSharedMemorySize, FLASH_SMEM);

    // ln1 + weight prep
    ln_kernel<<<ROWS, 256>>>(x, ln1w, ln1b, p_ln);
    pack_wqkv_t<<<dim3(6, 32, 16), dim3(32, 8)>>>(Wqkv, p_wqt);
    transpose_tf32<<<dim3(MDIM / 32, DDIM / 32), dim3(32, 8)>>>(W1, p_w1t, DDIM, MDIM);
    transpose_tf32<<<dim3(DDIM / 32, MDIM / 32), dim3(32, 8)>>>(W2, p_w2t, MDIM, DDIM);
    wsum_kernel<<<DDIM / 256, 256>>>(Wout, p_wsum);

    // QKV projection (tf32 HMMA, output tf32-rounded for flash MMA inputs)
    mma_gemm<3><<<dim3(QKVC / 128, ROWS / 128), 256, GEMM_SMEM>>>(
        p_ln, p_wqt, p_qkv, ROWS, QKVC, DDIM, nullptr, nullptr);

    // attention (tf32 HMMA flash)
    flash_mma<<<dim3(SDIM / 64, NHEAD, BDIM), 128, FLASH_SMEM>>>(p_qkv, p_atto);

    // residual + reinterpretation-projection
    resid_attn<<<dim3(DDIM / 32, SDIM / 32, BDIM), dim3(32, 8)>>>(
        x, p_atto, p_wsum, p_x1);

    // ln2
    ln_kernel<<<ROWS, 256>>>(p_x1, ln2w, ln2b, p_ln);

    // MLP (tf32 HMMA)
    mma_gemm<1><<<dim3(MDIM / 128, ROWS / 128), 256, GEMM_SMEM>>>(
        p_ln, p_w1t, p_h, ROWS, MDIM, DDIM, b1, nullptr);
    mma_gemm<2><<<dim3(DDIM / 128, ROWS / 128), 256, GEMM_SMEM>>>(
        p_h, p_w2t, out, ROWS, DDIM, MDIM, b2, p_x1);
}

// round 12
// speedup vs baseline: 4.6803x; 1.5231x over previous
#include <cuda_runtime.h>
#include <cuda_fp16.h>
#include <math.h>
#include <stdint.h>

// Problem constants
#define BDIM 2
#define SDIM 2048
#define DDIM 1024
#define NHEAD 16
#define HDIM 64
#define MDIM 4096
#define ROWS (BDIM*SDIM)          // 4096 token rows
#define QKVC (NHEAD*3*HDIM)       // 3072 packed qkv columns

// ---------------- scratch (device globals; no allocation allowed) ----------
__device__ __half g_ln  [ROWS*DDIM];            // 8 MB, reused for ln1 & ln2
__device__ __half g_wqt [QKVC*DDIM];            // 6 MB W_qkv^T  [3072,1024]
__device__ __half g_w1t [MDIM*DDIM];            // 8 MB W1^T     [4096,1024]
__device__ __half g_w2t [DDIM*MDIM];            // 8 MB W2^T     [1024,4096]
__device__ __half g_qkv [ROWS*QKVC];            // 24 MB
__device__ float  g_atto[BDIM*NHEAD*SDIM*HDIM]; // 16 MB attention out (b,n,s,h)
__device__ float  g_wsum[DDIM];
__device__ float  g_x1  [ROWS*DDIM];            // 16 MB residual after attention
__device__ __half g_h   [ROWS*MDIM];            // 32 MB MLP hidden

// ============================ helpers =======================================
__device__ __forceinline__ uint32_t smem_u32(const void* p) {
    uint32_t a;
    asm("{ .reg .u64 t; cvta.to.shared.u64 t, %1; cvt.u32.u64 %0, t; }"
        : "=r"(a) : "l"(p));
    return a;
}
__device__ __forceinline__ void cp16(uint32_t dst, const void* src) {
    asm volatile("cp.async.cg.shared.global [%0], [%1], 16;" :: "r"(dst), "l"(src));
}
__device__ __forceinline__ float gelu_exact(float v) {
    return 0.5f * v * (1.0f + erff(v * 0.70710678118654752440f));
}
__device__ __forceinline__ uint32_t pack_h2(float x, float y) {
    __half2 h = __floats2half2_rn(x, y);
    return *(uint32_t*)&h;
}

// fp16 MMA, fp32 accumulate: m16n8k16
#define MMA_F16(c, a, b) \
    asm volatile("mma.sync.aligned.m16n8k16.row.col.f32.f16.f16.f32 " \
        "{%0,%1,%2,%3}, {%4,%5,%6,%7}, {%8,%9}, {%0,%1,%2,%3};" \
        : "+f"((c)[0]), "+f"((c)[1]), "+f"((c)[2]), "+f"((c)[3]) \
        : "r"((a)[0]), "r"((a)[1]), "r"((a)[2]), "r"((a)[3]), \
          "r"((b)[0]), "r"((b)[1]))

// ========== fp16 HMMA GEMM: C[M,N] = A[M,K] * Bt[N,K]^T =====================
// A row-major [M,K] half, Bt row-major [N,K] half. CTA 128x128, 256 thr
// (8 warps 2x4 -> warp tile 64x32). K staged at 32, 4-deep cp.async pipeline.
// smem pitch 40 halves (80B): fragment bank = (20q+r4)%32 -> conflict-free.
#define GP 40
#define STAGE_H (128*GP)                      // halves per stage per operand
#define NSTG 4
#define GEMM_SMEM (2*NSTG*STAGE_H*2)          // 81920 bytes

// EPI: 1 = +bias, gelu -> half; 2 = +bias +res -> float; 3 = plain -> half
template<int EPI>
__global__ __launch_bounds__(256, 2)
void mma_gemm(const __half* __restrict__ A, const __half* __restrict__ Bt,
              void* __restrict__ Cv, int M, int N, int K,
              const float* __restrict__ bias, const float* __restrict__ res)
{
    extern __shared__ __half smh[];
    __half* As = smh;                  // [NSTG][STAGE_H]
    __half* Bs = smh + NSTG * STAGE_H;

    const int tid = threadIdx.x;
    const int wid = tid >> 5, lane = tid & 31;
    const int bm = blockIdx.y * 128, bn = blockIdx.x * 128;
    const int mbase = (wid >> 2) * 64;
    const int nbase = (wid & 3) * 32;
    const int q = lane >> 2, r4 = lane & 3;

    const uint32_t sA = smem_u32(As);
    const uint32_t sB = smem_u32(Bs);
    const int nst = K >> 5;

    auto load_stage = [&](int s) {
        int slot = s & (NSTG - 1);
        int k0 = s << 5;
        const __half* Ag = A + (size_t)bm * K + k0;
        const __half* Bg = Bt + (size_t)bn * K + k0;
        uint32_t ab = sA + slot * (STAGE_H * 2);
        uint32_t bb = sB + slot * (STAGE_H * 2);
        #pragma unroll
        for (int i = 0; i < 2; ++i) {
            int linear = i * 256 + tid;          // 0..511
            int row = linear >> 2, c = linear & 3;
            uint32_t off = (uint32_t)(row * GP + c * 8) * 2;
            cp16(ab + off, Ag + (size_t)row * K + c * 8);
            cp16(bb + off, Bg + (size_t)row * K + c * 8);
        }
        asm volatile("cp.async.commit_group;" ::: "memory");
    };

    float c[4][4][4];
    #pragma unroll
    for (int mt = 0; mt < 4; ++mt)
        #pragma unroll
        for (int nt = 0; nt < 4; ++nt)
            #pragma unroll
            for (int j = 0; j < 4; ++j) c[mt][nt][j] = 0.f;

    load_stage(0); load_stage(1); load_stage(2); load_stage(3);

    for (int s = 0; s < nst; ++s) {
        int slot = s & (NSTG - 1);
        asm volatile("cp.async.wait_group 3;" ::: "memory");
        __syncthreads();

        const __half* a_s = As + slot * STAGE_H;
        const __half* b_s = Bs + slot * STAGE_H;
        #pragma unroll
        for (int kk = 0; kk < 2; ++kk) {
            int kb = kk * 16;
            uint32_t a[4][4];
            #pragma unroll
            for (int mt = 0; mt < 4; ++mt) {
                const __half* ap = a_s + (mbase + mt * 16 + q) * GP + kb + 2 * r4;
                a[mt][0] = *(const uint32_t*)(ap);
                a[mt][1] = *(const uint32_t*)(ap + 8 * GP);
                a[mt][2] = *(const uint32_t*)(ap + 8);
                a[mt][3] = *(const uint32_t*)(ap + 8 * GP + 8);
            }
            uint32_t b[4][2];
            #pragma unroll
            for (int nt = 0; nt < 4; ++nt) {
                const __half* bp = b_s + (nbase + nt * 8 + q) * GP + kb + 2 * r4;
                b[nt][0] = *(const uint32_t*)(bp);
                b[nt][1] = *(const uint32_t*)(bp + 8);
            }
            #pragma unroll
            for (int mt = 0; mt < 4; ++mt)
                #pragma unroll
                for (int nt = 0; nt < 4; ++nt)
                    MMA_F16(c[mt][nt], a[mt], b[nt]);
        }

        __syncthreads();
        if (s + NSTG < nst) load_stage(s + NSTG);
        else asm volatile("cp.async.commit_group;" ::: "memory");
    }

    // Epilogue: c0,c1 = (row, 2r4..2r4+1); c2,c3 = (row+8, same cols)
    #pragma unroll
    for (int mt = 0; mt < 4; ++mt) {
        #pragma unroll
        for (int nt = 0; nt < 4; ++nt) {
            int row0 = bm + mbase + mt * 16 + q;
            int col  = bn + nbase + nt * 8 + r4 * 2;
            #pragma unroll
            for (int h = 0; h < 2; ++h) {
                int row = row0 + h * 8;
                float vx = c[mt][nt][2 * h], vy = c[mt][nt][2 * h + 1];
                if (EPI == 1) {
                    vx = gelu_exact(vx + bias[col]);
                    vy = gelu_exact(vy + bias[col + 1]);
                    __half* C = (__half*)Cv;
                    *(uint32_t*)(C + (size_t)row * N + col) = pack_h2(vx, vy);
                } else if (EPI == 2) {
                    const float* rp = res + (size_t)row * N + col;
                    vx += bias[col] + rp[0];
                    vy += bias[col + 1] + rp[1];
                    float* C = (float*)Cv;
                    *(float2*)(C + (size_t)row * N + col) = make_float2(vx, vy);
                } else {
                    __half* C = (__half*)Cv;
                    *(uint32_t*)(C + (size_t)row * N + col) = pack_h2(vx, vy);
                }
            }
        }
    }
}

// ---------------- layernorm (ddof=1, eps=1e-4) -> half ----------------------
__global__ __launch_bounds__(256) void ln_kernel(
    const float* __restrict__ x, const float* __restrict__ w,
    const float* __restrict__ bb, __half* __restrict__ y)
{
    int row = blockIdx.x;
    int t = threadIdx.x;
    const float4* xr = (const float4*)(x + (size_t)row * DDIM);
    float4 v = xr[t];

    __shared__ float red[8];
    __shared__ float s_mu, s_inv;

    float s = v.x + v.y + v.z + v.w;
    #pragma unroll
    for (int o = 16; o > 0; o >>= 1) s += __shfl_xor_sync(0xffffffffu, s, o);
    if ((t & 31) == 0) red[t >> 5] = s;
    __syncthreads();
    if (t == 0) {
        float tot = 0.f;
        #pragma unroll
        for (int i = 0; i < 8; ++i) tot += red[i];
        s_mu = tot * (1.0f / DDIM);
    }
    __syncthreads();
    float mu = s_mu;
    float dx = v.x - mu, dy = v.y - mu, dz = v.z - mu, dw = v.w - mu;
    float ss = dx*dx + dy*dy + dz*dz + dw*dw;
    #pragma unroll
    for (int o = 16; o > 0; o >>= 1) ss += __shfl_xor_sync(0xffffffffu, ss, o);
    __syncthreads();
    if ((t & 31) == 0) red[t >> 5] = ss;
    __syncthreads();
    if (t == 0) {
        float tot = 0.f;
        #pragma unroll
        for (int i = 0; i < 8; ++i) tot += red[i];
        s_inv = rsqrtf(tot * (1.0f / (DDIM - 1)) + 1e-4f);
    }
    __syncthreads();
    float inv = s_inv;
    float4 wv = ((const float4*)w)[t];
    float4 bv = ((const float4*)bb)[t];
    uint2 o;
    o.x = pack_h2(dx * inv * wv.x + bv.x, dy * inv * wv.y + bv.y);
    o.y = pack_h2(dz * inv * wv.z + bv.z, dw * inv * wv.w + bv.w);
    *(uint2*)(y + (size_t)row * DDIM + t * 4) = o;
}

// ------------- transpose [K,N] float -> [N,K] half --------------------------
__global__ __launch_bounds__(256) void transpose_h(
    const float* __restrict__ in, __half* __restrict__ out, int K, int N)
{
    __shared__ float t[32][33];
    int k0 = blockIdx.y * 32, n0 = blockIdx.x * 32;
    int tx = threadIdx.x, ty = threadIdx.y;
    #pragma unroll
    for (int r = 0; r < 32; r += 8)
        t[ty + r][tx] = in[(size_t)(k0 + ty + r) * N + n0 + tx];
    __syncthreads();
    #pragma unroll
    for (int r = 0; r < 32; r += 8)
        out[(size_t)(n0 + ty + r) * K + k0 + tx] = __float2half_rn(t[tx][ty + r]);
}

// ------- pack+transpose W_qkv[N,D,192] -> [(n*192+j), d] half ----------------
__global__ __launch_bounds__(256) void pack_wqkv_t(
    const float* __restrict__ W, __half* __restrict__ out)
{
    __shared__ float t[32][33];
    int j0 = blockIdx.x * 32, d0 = blockIdx.y * 32, n = blockIdx.z;
    int tx = threadIdx.x, ty = threadIdx.y;
    #pragma unroll
    for (int r = 0; r < 32; r += 8)
        t[ty + r][tx] = W[((size_t)n * DDIM + d0 + ty + r) * 192 + j0 + tx];
    __syncthreads();
    #pragma unroll
    for (int r = 0; r < 32; r += 8)
        out[((size_t)n * 192 + j0 + ty + r) * DDIM + d0 + tx] =
            __float2half_rn(t[tx][ty + r]);
}

// ---------------- w_sum[d] = sum_{n,h} W_out[n,h,d] -------------------------
__global__ __launch_bounds__(256) void wsum_kernel(
    const float* __restrict__ Wout, float* __restrict__ ws)
{
    int d = blockIdx.x * 256 + threadIdx.x;
    float s = 0.f;
    for (int i = 0; i < NHEAD * HDIM; ++i) s += Wout[(size_t)i * DDIM + d];
    ws[d] = s;
}

// ============ flash attention, fp16 HMMA: 64q x 64k tiles ===================
// 128 thr / 4 warps; warp w owns q rows [w*16, w*16+16).
// smem pitch 72 halves (144B): fragment bank = (4q+r4+const)%32, conflict-free
#define FPH 72
#define FLASH_SMEM (4*64*FPH*2)   // Qs, Ks, Vt, Ps = 36864 bytes

__global__ __launch_bounds__(128) void flash_mma(
    const __half* __restrict__ qkv, float* __restrict__ atto)
{
    extern __shared__ __half smf[];
    __half* Qs = smf;                  // [64][FPH] Q, scaled (q x h)
    __half* Ks = smf + 64 * FPH;       // [64][FPH] K (j x h)
    __half* Vt = smf + 2 * 64 * FPH;   // [64][FPH] V transposed (h x j)
    __half* Ps = smf + 3 * 64 * FPH;   // [64][FPH] P, warp-private bands

    const int qt = blockIdx.x, n = blockIdx.y, b = blockIdx.z;
    const int tid = threadIdx.x, wid = tid >> 5, lane = tid & 31;
    const int q = lane >> 2, r4 = lane & 3;
    const int mrow = wid * 16;
    const __half* base = qkv + (size_t)b * SDIM * QKVC + n * 192;
    const __half2 qscale = __float2half2_rn(0.125f);   // exact

    // load Q tile, scaled (8 halves per chunk; 512 chunks / 128 thr = 4 each)
    #pragma unroll
    for (int i = 0; i < 4; ++i) {
        int linear = i * 128 + tid;
        int row = linear >> 3, c8 = (linear & 7) * 8;
        uint4 v = *(const uint4*)(base + (size_t)(qt * 64 + row) * QKVC + c8);
        __half2* h = (__half2*)&v;
        h[0] = __hmul2(h[0], qscale); h[1] = __hmul2(h[1], qscale);
        h[2] = __hmul2(h[2], qscale); h[3] = __hmul2(h[3], qscale);
        *(uint4*)(Qs + row * FPH + c8) = v;
    }

    float m0 = -INFINITY, m1 = -INFINITY, l0 = 0.f, l1 = 0.f;
    float o[8][4];
    #pragma unroll
    for (int nt = 0; nt < 8; ++nt)
        o[nt][0] = o[nt][1] = o[nt][2] = o[nt][3] = 0.f;

    for (int kt = 0; kt <= qt; ++kt) {
        __syncthreads();
        #pragma unroll
        for (int i = 0; i < 4; ++i) {
            int linear = i * 128 + tid;
            int row = linear >> 3, c8 = (linear & 7) * 8;
            const __half* rb = base + (size_t)(kt * 64 + row) * QKVC;
            *(uint4*)(Ks + row * FPH + c8) = *(const uint4*)(rb + 64 + c8);
            uint4 vv = *(const uint4*)(rb + 128 + c8);
            const __half* vh = (const __half*)&vv;
            #pragma unroll
            for (int j = 0; j < 8; ++j)
                Vt[(c8 + j) * FPH + row] = vh[j];
        }
        __syncthreads();

        // S = Q @ K^T  (16x64 per warp, k=64 -> 4 k16 steps)
        float c[8][4];
        #pragma unroll
        for (int nt = 0; nt < 8; ++nt)
            c[nt][0] = c[nt][1] = c[nt][2] = c[nt][3] = 0.f;
        #pragma unroll
        for (int kk = 0; kk < 4; ++kk) {
            int kb = kk * 16;
            const __half* ap = Qs + (mrow + q) * FPH + kb + 2 * r4;
            uint32_t a[4] = {*(const uint32_t*)(ap),
                             *(const uint32_t*)(ap + 8 * FPH),
                             *(const uint32_t*)(ap + 8),
                             *(const uint32_t*)(ap + 8 * FPH + 8)};
            #pragma unroll
            for (int nt = 0; nt < 8; ++nt) {
                const __half* bp = Ks + (nt * 8 + q) * FPH + kb + 2 * r4;
                uint32_t bf[2] = {*(const uint32_t*)(bp),
                                  *(const uint32_t*)(bp + 8)};
                MMA_F16(c[nt], a, bf);
            }
        }

        // causal mask on diagonal tile
        if (kt == qt) {
            int i0 = mrow + q;
            #pragma unroll
            for (int nt = 0; nt < 8; ++nt) {
                int j0 = nt * 8 + 2 * r4;
                if (j0     > i0)     c[nt][0] = -INFINITY;
                if (j0 + 1 > i0)     c[nt][1] = -INFINITY;
                if (j0     > i0 + 8) c[nt][2] = -INFINITY;
                if (j0 + 1 > i0 + 8) c[nt][3] = -INFINITY;
            }
        }

        // online softmax; rows live in 4 lanes (xor 1,2)
        float rm0 = -INFINITY, rm1 = -INFINITY;
        #pragma unroll
        for (int nt = 0; nt < 8; ++nt) {
            rm0 = fmaxf(rm0, fmaxf(c[nt][0], c[nt][1]));
            rm1 = fmaxf(rm1, fmaxf(c[nt][2], c[nt][3]));
        }
        rm0 = fmaxf(rm0, __shfl_xor_sync(0xffffffffu, rm0, 1));
        rm0 = fmaxf(rm0, __shfl_xor_sync(0xffffffffu, rm0, 2));
        rm1 = fmaxf(rm1, __shfl_xor_sync(0xffffffffu, rm1, 1));
        rm1 = fmaxf(rm1, __shfl_xor_sync(0xffffffffu, rm1, 2));
        float mn0 = fmaxf(m0, rm0), mn1 = fmaxf(m1, rm1);
        float al0 = __expf(m0 - mn0), al1 = __expf(m1 - mn1);
        m0 = mn0; m1 = mn1;
        float rs0 = 0.f, rs1 = 0.f;
        #pragma unroll
        for (int nt = 0; nt < 8; ++nt) {
            c[nt][0] = __expf(c[nt][0] - mn0); rs0 += c[nt][0];
            c[nt][1] = __expf(c[nt][1] - mn0); rs0 += c[nt][1];
            c[nt][2] = __expf(c[nt][2] - mn1); rs1 += c[nt][2];
            c[nt][3] = __expf(c[nt][3] - mn1); rs1 += c[nt][3];
        }
        rs0 += __shfl_xor_sync(0xffffffffu, rs0, 1);
        rs0 += __shfl_xor_sync(0xffffffffu, rs0, 2);
        rs1 += __shfl_xor_sync(0xffffffffu, rs1, 1);
        rs1 += __shfl_xor_sync(0xffffffffu, rs1, 2);
        l0 = l0 * al0 + rs0;
        l1 = l1 * al1 + rs1;
        #pragma unroll
        for (int nt = 0; nt < 8; ++nt) {
            o[nt][0] *= al0; o[nt][1] *= al0;
            o[nt][2] *= al1; o[nt][3] *= al1;
        }

        // P (half) -> warp-private smem band, then A-fragment reload
        __syncwarp();
        __half* pr = Ps + (mrow + q) * FPH;
        #pragma unroll
        for (int nt = 0; nt < 8; ++nt) {
            *(uint32_t*)(pr + nt * 8 + 2 * r4) = pack_h2(c[nt][0], c[nt][1]);
            *(uint32_t*)(pr + 8 * FPH + nt * 8 + 2 * r4) = pack_h2(c[nt][2], c[nt][3]);
        }
        __syncwarp();

        // O += P @ V   (A = P [16 x 64], B = Vt)
        #pragma unroll
        for (int kk = 0; kk < 4; ++kk) {
            int kb = kk * 16;
            const __half* ap = Ps + (mrow + q) * FPH + kb + 2 * r4;
            uint32_t a[4] = {*(const uint32_t*)(ap),
                             *(const uint32_t*)(ap + 8 * FPH),
                             *(const uint32_t*)(ap + 8),
                             *(const uint32_t*)(ap + 8 * FPH + 8)};
            #pragma unroll
            for (int nt = 0; nt < 8; ++nt) {
                const __half* bp = Vt + (nt * 8 + q) * FPH + kb + 2 * r4;
                uint32_t bf[2] = {*(const uint32_t*)(bp),
                                  *(const uint32_t*)(bp + 8)};
                MMA_F16(o[nt], a, bf);
            }
        }
    }

    // normalize + store (b,n,s,h) fp32
    float inv0 = 1.0f / l0, inv1 = 1.0f / l1;
    float* ob = atto + ((size_t)(b * NHEAD + n) * SDIM + qt * 64) * HDIM;
    int row0 = mrow + q;
    #pragma unroll
    for (int nt = 0; nt < 8; ++nt) {
        int col = nt * 8 + 2 * r4;
        *(float2*)(ob + (size_t)row0 * HDIM + col) =
            make_float2(o[nt][0] * inv0, o[nt][1] * inv0);
        *(float2*)(ob + (size_t)(row0 + 8) * HDIM + col) =
            make_float2(o[nt][2] * inv1, o[nt][3] * inv1);
    }
}

// ------- residual + torch-reinterpretation "projection" ---------------------
__global__ void resid_attn(const float* __restrict__ x,
                           const float* __restrict__ atto,
                           const float* __restrict__ wsum,
                           float* __restrict__ x1)
{
    __shared__ float tile[32][33];
    int b = blockIdx.z;
    int d0 = blockIdx.x * 32, s0 = blockIdx.y * 32;
    int tx = threadIdx.x, ty = threadIdx.y;
    const float* ab = atto + (size_t)b * (DDIM * SDIM);
    #pragma unroll
    for (int r = 0; r < 32; r += 8) {
        int d = d0 + ty + r, s = s0 + tx;
        tile[ty + r][tx] = ab[(size_t)d * SDIM + s];
    }
    __syncthreads();
    #pragma unroll
    for (int r = 0; r < 32; r += 8) {
        int s = s0 + ty + r, d = d0 + tx;
        size_t idx = ((size_t)b * SDIM + s) * DDIM + d;
        x1[idx] = x[idx] + tile[tx][ty + r] * wsum[d];
    }
}

// ---------------------------------------------------------------------------
extern "C" void kernel_launch(void* const* d_in, const int* in_sizes, int n_in,
                              void* d_out, int out_size)
{
    const float* x    = (const float*)d_in[0];
    const float* Wqkv = (const float*)d_in[1];
    const float* Wout = (const float*)d_in[2];
    const float* ln1w = (const float*)d_in[3];
    const float* ln1b = (const float*)d_in[4];
    const float* ln2w = (const float*)d_in[5];
    const float* ln2b = (const float*)d_in[6];
    const float* W1   = (const float*)d_in[7];
    const float* b1   = (const float*)d_in[8];
    const float* W2   = (const float*)d_in[9];
    const float* b2   = (const float*)d_in[10];
    float* out = (float*)d_out;

    __half *p_ln, *p_wqt, *p_w1t, *p_w2t, *p_qkv, *p_h;
    float *p_atto, *p_wsum, *p_x1;
    cudaGetSymbolAddress((void**)&p_ln,   g_ln);
    cudaGetSymbolAddress((void**)&p_wqt,  g_wqt);
    cudaGetSymbolAddress((void**)&p_w1t,  g_w1t);
    cudaGetSymbolAddress((void**)&p_w2t,  g_w2t);
    cudaGetSymbolAddress((void**)&p_qkv,  g_qkv);
    cudaGetSymbolAddress((void**)&p_atto, g_atto);
    cudaGetSymbolAddress((void**)&p_wsum, g_wsum);
    cudaGetSymbolAddress((void**)&p_x1,   g_x1);
    cudaGetSymbolAddress((void**)&p_h,    g_h);

    cudaFuncSetAttribute(mma_gemm<1>, cudaFuncAttributeMaxDynamicSharedMemorySize, GEMM_SMEM);
    cudaFuncSetAttribute(mma_gemm<2>, cudaFuncAttributeMaxDynamicSharedMemorySize, GEMM_SMEM);
    cudaFuncSetAttribute(mma_gemm<3>, cudaFuncAttributeMaxDynamicSharedMemorySize, GEMM_SMEM);
    cudaFuncSetAttribute(flash_mma, cudaFuncAttributeMaxDynamicSharedMemorySize, FLASH_SMEM);

    // ln1 + weight prep (all emit fp16)
    ln_kernel<<<ROWS, 256>>>(x, ln1w, ln1b, p_ln);
    pack_wqkv_t<<<dim3(6, 32, 16), dim3(32, 8)>>>(Wqkv, p_wqt);
    transpose_h<<<dim3(MDIM / 32, DDIM / 32), dim3(32, 8)>>>(W1, p_w1t, DDIM, MDIM);
    transpose_h<<<dim3(DDIM / 32, MDIM / 32), dim3(32, 8)>>>(W2, p_w2t, MDIM, DDIM);
    wsum_kernel<<<DDIM / 256, 256>>>(Wout, p_wsum);

    // QKV projection (fp16 HMMA, half out for flash)
    mma_gemm<3><<<dim3(QKVC / 128, ROWS / 128), 256, GEMM_SMEM>>>(
        p_ln, p_wqt, p_qkv, ROWS, QKVC, DDIM, nullptr, nullptr);

    // attention (fp16 HMMA flash)
    flash_mma<<<dim3(SDIM / 64, NHEAD, BDIM), 128, FLASH_SMEM>>>(p_qkv, p_atto);

    // residual + reinterpretation-projection
    resid_attn<<<dim3(DDIM / 32, SDIM / 32, BDIM), dim3(32, 8)>>>(
        x, p_atto, p_wsum, p_x1);

    // ln2
    ln_kernel<<<ROWS, 256>>>(p_x1, ln2w, ln2b, p_ln);

    // MLP (fp16 HMMA)
    mma_gemm<1><<<dim3(MDIM / 128, ROWS / 128), 256, GEMM_SMEM>>>(
        p_ln, p_w1t, p_h, ROWS, MDIM, DDIM, b1, nullptr);
    mma_gemm<2><<<dim3(DDIM / 128, ROWS / 128), 256, GEMM_SMEM>>>(
        p_h, p_w2t, out, ROWS, DDIM, MDIM, b2, p_x1);
}

// round 13
// speedup vs baseline: 4.9224x; 1.0517x over previous
#include <cuda_runtime.h>
#include <cuda_fp16.h>
#include <math.h>
#include <stdint.h>

// Problem constants
#define BDIM 2
#define SDIM 2048
#define DDIM 1024
#define NHEAD 16
#define HDIM 64
#define MDIM 4096
#define ROWS (BDIM*SDIM)          // 4096 token rows
#define QKVC (NHEAD*3*HDIM)       // 3072 packed qkv columns

// ---------------- scratch (device globals; no allocation allowed) ----------
__device__ __half g_ln  [ROWS*DDIM];            // 8 MB, reused for ln1 & ln2
__device__ __half g_wqt [QKVC*DDIM];            // 6 MB W_qkv^T  [3072,1024]
__device__ __half g_w1t [MDIM*DDIM];            // 8 MB W1^T     [4096,1024]
__device__ __half g_w2t [DDIM*MDIM];            // 8 MB W2^T     [1024,4096]
__device__ __half g_qkv [ROWS*QKVC];            // 24 MB
__device__ float  g_atto[BDIM*NHEAD*SDIM*HDIM]; // 16 MB attention out (b,n,s,h)
__device__ float  g_wsum[DDIM];
__device__ float  g_x1  [ROWS*DDIM];            // 16 MB residual after attention
__device__ __half g_h   [ROWS*MDIM];            // 32 MB MLP hidden

// ============================ helpers =======================================
__device__ __forceinline__ uint32_t smem_u32(const void* p) {
    uint32_t a;
    asm("{ .reg .u64 t; cvta.to.shared.u64 t, %1; cvt.u32.u64 %0, t; }"
        : "=r"(a) : "l"(p));
    return a;
}
__device__ __forceinline__ void cp16(uint32_t dst, const void* src) {
    asm volatile("cp.async.cg.shared.global [%0], [%1], 16;" :: "r"(dst), "l"(src));
}
__device__ __forceinline__ float gelu_exact(float v) {
    return 0.5f * v * (1.0f + erff(v * 0.70710678118654752440f));
}
__device__ __forceinline__ uint32_t pack_h2(float x, float y) {
    __half2 h = __floats2half2_rn(x, y);
    return *(uint32_t*)&h;
}

// fp16 MMA, fp32 accumulate: m16n8k16
#define MMA_F16(c, a, b) \
    asm volatile("mma.sync.aligned.m16n8k16.row.col.f32.f16.f16.f32 " \
        "{%0,%1,%2,%3}, {%4,%5,%6,%7}, {%8,%9}, {%0,%1,%2,%3};" \
        : "+f"((c)[0]), "+f"((c)[1]), "+f"((c)[2]), "+f"((c)[3]) \
        : "r"((a)[0]), "r"((a)[1]), "r"((a)[2]), "r"((a)[3]), \
          "r"((b)[0]), "r"((b)[1]))

// ========== fp16 HMMA GEMM: C[M,N] = A[M,K] * Bt[N,K]^T =====================
// CTA 128x128, 256 thr (8 warps 2x4 -> warp tile 64x32). K staged at 32,
// 4-deep cp.async pipeline. smem pitch 40 halves: conflict-free fragments.
#define GP 40
#define STAGE_H (128*GP)
#define NSTG 4
#define GEMM_SMEM (2*NSTG*STAGE_H*2)          // 81920 bytes

// EPI: 1 = +bias, gelu -> half; 2 = +bias +res -> float; 3 = plain -> half
template<int EPI>
__global__ __launch_bounds__(256, 2)
void mma_gemm(const __half* __restrict__ A, const __half* __restrict__ Bt,
              void* __restrict__ Cv, int M, int N, int K,
              const float* __restrict__ bias, const float* __restrict__ res)
{
    extern __shared__ __half smh[];
    __half* As = smh;                  // [NSTG][STAGE_H]
    __half* Bs = smh + NSTG * STAGE_H;

    const int tid = threadIdx.x;
    const int wid = tid >> 5, lane = tid & 31;
    const int bm = blockIdx.y * 128, bn = blockIdx.x * 128;
    const int mbase = (wid >> 2) * 64;
    const int nbase = (wid & 3) * 32;
    const int q = lane >> 2, r4 = lane & 3;

    const uint32_t sA = smem_u32(As);
    const uint32_t sB = smem_u32(Bs);
    const int nst = K >> 5;

    auto load_stage = [&](int s) {
        int slot = s & (NSTG - 1);
        int k0 = s << 5;
        const __half* Ag = A + (size_t)bm * K + k0;
        const __half* Bg = Bt + (size_t)bn * K + k0;
        uint32_t ab = sA + slot * (STAGE_H * 2);
        uint32_t bb = sB + slot * (STAGE_H * 2);
        #pragma unroll
        for (int i = 0; i < 2; ++i) {
            int linear = i * 256 + tid;
            int row = linear >> 2, c = linear & 3;
            uint32_t off = (uint32_t)(row * GP + c * 8) * 2;
            cp16(ab + off, Ag + (size_t)row * K + c * 8);
            cp16(bb + off, Bg + (size_t)row * K + c * 8);
        }
        asm volatile("cp.async.commit_group;" ::: "memory");
    };

    float c[4][4][4];
    #pragma unroll
    for (int mt = 0; mt < 4; ++mt)
        #pragma unroll
        for (int nt = 0; nt < 4; ++nt)
            #pragma unroll
            for (int j = 0; j < 4; ++j) c[mt][nt][j] = 0.f;

    load_stage(0); load_stage(1); load_stage(2); load_stage(3);

    for (int s = 0; s < nst; ++s) {
        int slot = s & (NSTG - 1);
        asm volatile("cp.async.wait_group 3;" ::: "memory");
        __syncthreads();

        const __half* a_s = As + slot * STAGE_H;
        const __half* b_s = Bs + slot * STAGE_H;
        #pragma unroll
        for (int kk = 0; kk < 2; ++kk) {
            int kb = kk * 16;
            uint32_t a[4][4];
            #pragma unroll
            for (int mt = 0; mt < 4; ++mt) {
                const __half* ap = a_s + (mbase + mt * 16 + q) * GP + kb + 2 * r4;
                a[mt][0] = *(const uint32_t*)(ap);
                a[mt][1] = *(const uint32_t*)(ap + 8 * GP);
                a[mt][2] = *(const uint32_t*)(ap + 8);
                a[mt][3] = *(const uint32_t*)(ap + 8 * GP + 8);
            }
            uint32_t b[4][2];
            #pragma unroll
            for (int nt = 0; nt < 4; ++nt) {
                const __half* bp = b_s + (nbase + nt * 8 + q) * GP + kb + 2 * r4;
                b[nt][0] = *(const uint32_t*)(bp);
                b[nt][1] = *(const uint32_t*)(bp + 8);
            }
            #pragma unroll
            for (int mt = 0; mt < 4; ++mt)
                #pragma unroll
                for (int nt = 0; nt < 4; ++nt)
                    MMA_F16(c[mt][nt], a[mt], b[nt]);
        }

        __syncthreads();
        if (s + NSTG < nst) load_stage(s + NSTG);
        else asm volatile("cp.async.commit_group;" ::: "memory");
    }

    #pragma unroll
    for (int mt = 0; mt < 4; ++mt) {
        #pragma unroll
        for (int nt = 0; nt < 4; ++nt) {
            int row0 = bm + mbase + mt * 16 + q;
            int col  = bn + nbase + nt * 8 + r4 * 2;
            #pragma unroll
            for (int h = 0; h < 2; ++h) {
                int row = row0 + h * 8;
                float vx = c[mt][nt][2 * h], vy = c[mt][nt][2 * h + 1];
                if (EPI == 1) {
                    vx = gelu_exact(vx + bias[col]);
                    vy = gelu_exact(vy + bias[col + 1]);
                    __half* C = (__half*)Cv;
                    *(uint32_t*)(C + (size_t)row * N + col) = pack_h2(vx, vy);
                } else if (EPI == 2) {
                    const float* rp = res + (size_t)row * N + col;
                    vx += bias[col] + rp[0];
                    vy += bias[col + 1] + rp[1];
                    float* C = (float*)Cv;
                    *(float2*)(C + (size_t)row * N + col) = make_float2(vx, vy);
                } else {
                    __half* C = (__half*)Cv;
                    *(uint32_t*)(C + (size_t)row * N + col) = pack_h2(vx, vy);
                }
            }
        }
    }
}

// ---------------- layernorm (ddof=1, eps=1e-4) -> half ----------------------
__global__ __launch_bounds__(256) void ln_kernel(
    const float* __restrict__ x, const float* __restrict__ w,
    const float* __restrict__ bb, __half* __restrict__ y)
{
    int row = blockIdx.x;
    int t = threadIdx.x;
    const float4* xr = (const float4*)(x + (size_t)row * DDIM);
    float4 v = xr[t];

    __shared__ float red[8];
    __shared__ float s_mu, s_inv;

    float s = v.x + v.y + v.z + v.w;
    #pragma unroll
    for (int o = 16; o > 0; o >>= 1) s += __shfl_xor_sync(0xffffffffu, s, o);
    if ((t & 31) == 0) red[t >> 5] = s;
    __syncthreads();
    if (t == 0) {
        float tot = 0.f;
        #pragma unroll
        for (int i = 0; i < 8; ++i) tot += red[i];
        s_mu = tot * (1.0f / DDIM);
    }
    __syncthreads();
    float mu = s_mu;
    float dx = v.x - mu, dy = v.y - mu, dz = v.z - mu, dw = v.w - mu;
    float ss = dx*dx + dy*dy + dz*dz + dw*dw;
    #pragma unroll
    for (int o = 16; o > 0; o >>= 1) ss += __shfl_xor_sync(0xffffffffu, ss, o);
    __syncthreads();
    if ((t & 31) == 0) red[t >> 5] = ss;
    __syncthreads();
    if (t == 0) {
        float tot = 0.f;
        #pragma unroll
        for (int i = 0; i < 8; ++i) tot += red[i];
        s_inv = rsqrtf(tot * (1.0f / (DDIM - 1)) + 1e-4f);
    }
    __syncthreads();
    float inv = s_inv;
    float4 wv = ((const float4*)w)[t];
    float4 bv = ((const float4*)bb)[t];
    uint2 o;
    o.x = pack_h2(dx * inv * wv.x + bv.x, dy * inv * wv.y + bv.y);
    o.y = pack_h2(dz * inv * wv.z + bv.z, dw * inv * wv.w + bv.w);
    *(uint2*)(y + (size_t)row * DDIM + t * 4) = o;
}

// ------------- transpose [K,N] float -> [N,K] half --------------------------
__global__ __launch_bounds__(256) void transpose_h(
    const float* __restrict__ in, __half* __restrict__ out, int K, int N)
{
    __shared__ float t[32][33];
    int k0 = blockIdx.y * 32, n0 = blockIdx.x * 32;
    int tx = threadIdx.x, ty = threadIdx.y;
    #pragma unroll
    for (int r = 0; r < 32; r += 8)
        t[ty + r][tx] = in[(size_t)(k0 + ty + r) * N + n0 + tx];
    __syncthreads();
    #pragma unroll
    for (int r = 0; r < 32; r += 8)
        out[(size_t)(n0 + ty + r) * K + k0 + tx] = __float2half_rn(t[tx][ty + r]);
}

// ------- pack+transpose W_qkv[N,D,192] -> [(n*192+j), d] half ----------------
__global__ __launch_bounds__(256) void pack_wqkv_t(
    const float* __restrict__ W, __half* __restrict__ out)
{
    __shared__ float t[32][33];
    int j0 = blockIdx.x * 32, d0 = blockIdx.y * 32, n = blockIdx.z;
    int tx = threadIdx.x, ty = threadIdx.y;
    #pragma unroll
    for (int r = 0; r < 32; r += 8)
        t[ty + r][tx] = W[((size_t)n * DDIM + d0 + ty + r) * 192 + j0 + tx];
    __syncthreads();
    #pragma unroll
    for (int r = 0; r < 32; r += 8)
        out[((size_t)n * 192 + j0 + ty + r) * DDIM + d0 + tx] =
            __float2half_rn(t[tx][ty + r]);
}

// ---------------- w_sum[d] = sum_{n,h} W_out[n,h,d] -------------------------
__global__ __launch_bounds__(256) void wsum_kernel(
    const float* __restrict__ Wout, float* __restrict__ ws)
{
    int d = blockIdx.x * 256 + threadIdx.x;
    float s = 0.f;
    for (int i = 0; i < NHEAD * HDIM; ++i) s += Wout[(size_t)i * DDIM + d];
    ws[d] = s;
}

// ============ flash attention, fp16 HMMA: 64q x 64k tiles ===================
// 128 thr / 4 warps; warp w owns q rows [w*16, w*16+16).
// P stays in registers (C-fragment == A-fragment mapping).
// K/V double-buffered in smem with register prefetch: 1 syncthreads per tile.
#define FPH 72
#define FLASH_SMEM (5*64*FPH*2)   // Qs + 2*Ks + 2*Vt = 46080 bytes

__global__ __launch_bounds__(128) void flash_mma(
    const __half* __restrict__ qkv, float* __restrict__ atto)
{
    extern __shared__ __half smf[];
    __half* Qs = smf;                    // [64][FPH] Q, scaled
    __half* Kb = smf + 64 * FPH;         // [2][64][FPH] K row-major (j x h)
    __half* Vb = smf + 3 * 64 * FPH;     // [2][64][FPH] V transposed (h x j)

    const int qt = (int)gridDim.x - 1 - (int)blockIdx.x;   // longest first
    const int n = blockIdx.y, b = blockIdx.z;
    const int tid = threadIdx.x, wid = tid >> 5, lane = tid & 31;
    const int q = lane >> 2, r4 = lane & 3;
    const int mrow = wid * 16;
    const __half* base = qkv + (size_t)b * SDIM * QKVC + n * 192;
    const __half2 qscale = __float2half2_rn(0.125f);   // exact

    // load Q tile, scaled
    #pragma unroll
    for (int i = 0; i < 4; ++i) {
        int linear = i * 128 + tid;
        int row = linear >> 3, c8 = (linear & 7) * 8;
        uint4 v = *(const uint4*)(base + (size_t)(qt * 64 + row) * QKVC + c8);
        __half2* h = (__half2*)&v;
        h[0] = __hmul2(h[0], qscale); h[1] = __hmul2(h[1], qscale);
        h[2] = __hmul2(h[2], qscale); h[3] = __hmul2(h[3], qscale);
        *(uint4*)(Qs + row * FPH + c8) = v;
    }

    uint4 kr[4], vr[4];
    auto ldg_tile = [&](int kt) {
        #pragma unroll
        for (int i = 0; i < 4; ++i) {
            int linear = i * 128 + tid;
            int row = linear >> 3, c8 = (linear & 7) * 8;
            const __half* rb = base + (size_t)(kt * 64 + row) * QKVC;
            kr[i] = *(const uint4*)(rb + 64 + c8);
            vr[i] = *(const uint4*)(rb + 128 + c8);
        }
    };
    auto sts_tile = [&](int buf) {
        __half* Ksb = Kb + buf * 64 * FPH;
        __half* Vtb = Vb + buf * 64 * FPH;
        #pragma unroll
        for (int i = 0; i < 4; ++i) {
            int linear = i * 128 + tid;
            int row = linear >> 3, c8 = (linear & 7) * 8;
            *(uint4*)(Ksb + row * FPH + c8) = kr[i];
            const __half* vh = (const __half*)&vr[i];
            #pragma unroll
            for (int j = 0; j < 8; ++j)
                Vtb[(c8 + j) * FPH + row] = vh[j];
        }
    };

    float m0 = -INFINITY, m1 = -INFINITY, l0 = 0.f, l1 = 0.f;
    float o[8][4];
    #pragma unroll
    for (int nt = 0; nt < 8; ++nt)
        o[nt][0] = o[nt][1] = o[nt][2] = o[nt][3] = 0.f;

    ldg_tile(0);
    sts_tile(0);
    __syncthreads();

    for (int kt = 0; kt <= qt; ++kt) {
        int cur = kt & 1;
        if (kt < qt) ldg_tile(kt + 1);            // prefetch into registers

        const __half* Ks = Kb + cur * 64 * FPH;
        const __half* Vt = Vb + cur * 64 * FPH;

        // S = Q @ K^T  (16x64 per warp, 4 k16 steps)
        float c[8][4];
        #pragma unroll
        for (int nt = 0; nt < 8; ++nt)
            c[nt][0] = c[nt][1] = c[nt][2] = c[nt][3] = 0.f;
        #pragma unroll
        for (int kk = 0; kk < 4; ++kk) {
            int kb = kk * 16;
            const __half* ap = Qs + (mrow + q) * FPH + kb + 2 * r4;
            uint32_t a[4] = {*(const uint32_t*)(ap),
                             *(const uint32_t*)(ap + 8 * FPH),
                             *(const uint32_t*)(ap + 8),
                             *(const uint32_t*)(ap + 8 * FPH + 8)};
            #pragma unroll
            for (int nt = 0; nt < 8; ++nt) {
                const __half* bp = Ks + (nt * 8 + q) * FPH + kb + 2 * r4;
                uint32_t bf[2] = {*(const uint32_t*)(bp),
                                  *(const uint32_t*)(bp + 8)};
                MMA_F16(c[nt], a, bf);
            }
        }

        // causal mask on diagonal tile
        if (kt == qt) {
            int i0 = mrow + q;
            #pragma unroll
            for (int nt = 0; nt < 8; ++nt) {
                int j0 = nt * 8 + 2 * r4;
                if (j0     > i0)     c[nt][0] = -INFINITY;
                if (j0 + 1 > i0)     c[nt][1] = -INFINITY;
                if (j0     > i0 + 8) c[nt][2] = -INFINITY;
                if (j0 + 1 > i0 + 8) c[nt][3] = -INFINITY;
            }
        }

        // online softmax; rows live in 4 lanes (xor 1,2)
        float rm0 = -INFINITY, rm1 = -INFINITY;
        #pragma unroll
        for (int nt = 0; nt < 8; ++nt) {
            rm0 = fmaxf(rm0, fmaxf(c[nt][0], c[nt][1]));
            rm1 = fmaxf(rm1, fmaxf(c[nt][2], c[nt][3]));
        }
        rm0 = fmaxf(rm0, __shfl_xor_sync(0xffffffffu, rm0, 1));
        rm0 = fmaxf(rm0, __shfl_xor_sync(0xffffffffu, rm0, 2));
        rm1 = fmaxf(rm1, __shfl_xor_sync(0xffffffffu, rm1, 1));
        rm1 = fmaxf(rm1, __shfl_xor_sync(0xffffffffu, rm1, 2));
        float mn0 = fmaxf(m0, rm0), mn1 = fmaxf(m1, rm1);
        float al0 = __expf(m0 - mn0), al1 = __expf(m1 - mn1);
        m0 = mn0; m1 = mn1;
        float rs0 = 0.f, rs1 = 0.f;
        #pragma unroll
        for (int nt = 0; nt < 8; ++nt) {
            c[nt][0] = __expf(c[nt][0] - mn0); rs0 += c[nt][0];
            c[nt][1] = __expf(c[nt][1] - mn0); rs0 += c[nt][1];
            c[nt][2] = __expf(c[nt][2] - mn1); rs1 += c[nt][2];
            c[nt][3] = __expf(c[nt][3] - mn1); rs1 += c[nt][3];
        }
        rs0 += __shfl_xor_sync(0xffffffffu, rs0, 1);
        rs0 += __shfl_xor_sync(0xffffffffu, rs0, 2);
        rs1 += __shfl_xor_sync(0xffffffffu, rs1, 1);
        rs1 += __shfl_xor_sync(0xffffffffu, rs1, 2);
        l0 = l0 * al0 + rs0;
        l1 = l1 * al1 + rs1;
        #pragma unroll
        for (int nt = 0; nt < 8; ++nt) {
            o[nt][0] *= al0; o[nt][1] *= al0;
            o[nt][2] *= al1; o[nt][3] *= al1;
        }

        // O += P @ V — P converted register-direct to A-fragments:
        // a0 = P(q, kb+2r4..+1)   = c[2kk][0..1]
        // a1 = P(q+8, kb+2r4..+1) = c[2kk][2..3]
        // a2 = P(q, kb+8+2r4..+1) = c[2kk+1][0..1]
        // a3 = P(q+8, ...)        = c[2kk+1][2..3]
        #pragma unroll
        for (int kk = 0; kk < 4; ++kk) {
            int kb = kk * 16;
            uint32_t a[4] = {pack_h2(c[2*kk][0],   c[2*kk][1]),
                             pack_h2(c[2*kk][2],   c[2*kk][3]),
                             pack_h2(c[2*kk+1][0], c[2*kk+1][1]),
                             pack_h2(c[2*kk+1][2], c[2*kk+1][3])};
            #pragma unroll
            for (int nt = 0; nt < 8; ++nt) {
                const __half* bp = Vt + (nt * 8 + q) * FPH + kb + 2 * r4;
                uint32_t bf[2] = {*(const uint32_t*)(bp),
                                  *(const uint32_t*)(bp + 8)};
                MMA_F16(o[nt], a, bf);
            }
        }

        if (kt < qt) {
            sts_tile(cur ^ 1);
            __syncthreads();
        }
    }

    // normalize + store (b,n,s,h) fp32
    float inv0 = 1.0f / l0, inv1 = 1.0f / l1;
    float* ob = atto + ((size_t)(b * NHEAD + n) * SDIM + qt * 64) * HDIM;
    int row0 = mrow + q;
    #pragma unroll
    for (int nt = 0; nt < 8; ++nt) {
        int col = nt * 8 + 2 * r4;
        *(float2*)(ob + (size_t)row0 * HDIM + col) =
            make_float2(o[nt][0] * inv0, o[nt][1] * inv0);
        *(float2*)(ob + (size_t)(row0 + 8) * HDIM + col) =
            make_float2(o[nt][2] * inv1, o[nt][3] * inv1);
    }
}

// ------- residual + torch-reinterpretation "projection" ---------------------
__global__ void resid_attn(const float* __restrict__ x,
                           const float* __restrict__ atto,
                           const float* __restrict__ wsum,
                           float* __restrict__ x1)
{
    __shared__ float tile[32][33];
    int b = blockIdx.z;
    int d0 = blockIdx.x * 32, s0 = blockIdx.y * 32;
    int tx = threadIdx.x, ty = threadIdx.y;
    const float* ab = atto + (size_t)b * (DDIM * SDIM);
    #pragma unroll
    for (int r = 0; r < 32; r += 8) {
        int d = d0 + ty + r, s = s0 + tx;
        tile[ty + r][tx] = ab[(size_t)d * SDIM + s];
    }
    __syncthreads();
    #pragma unroll
    for (int r = 0; r < 32; r += 8) {
        int s = s0 + ty + r, d = d0 + tx;
        size_t idx = ((size_t)b * SDIM + s) * DDIM + d;
        x1[idx] = x[idx] + tile[tx][ty + r] * wsum[d];
    }
}

// ---------------------------------------------------------------------------
extern "C" void kernel_launch(void* const* d_in, const int* in_sizes, int n_in,
                              void* d_out, int out_size)
{
    const float* x    = (const float*)d_in[0];
    const float* Wqkv = (const float*)d_in[1];
    const float* Wout = (const float*)d_in[2];
    const float* ln1w = (const float*)d_in[3];
    const float* ln1b = (const float*)d_in[4];
    const float* ln2w = (const float*)d_in[5];
    const float* ln2b = (const float*)d_in[6];
    const float* W1   = (const float*)d_in[7];
    const float* b1   = (const float*)d_in[8];
    const float* W2   = (const float*)d_in[9];
    const float* b2   = (const float*)d_in[10];
    float* out = (float*)d_out;

    __half *p_ln, *p_wqt, *p_w1t, *p_w2t, *p_qkv, *p_h;
    float *p_atto, *p_wsum, *p_x1;
    cudaGetSymbolAddress((void**)&p_ln,   g_ln);
    cudaGetSymbolAddress((void**)&p_wqt,  g_wqt);
    cudaGetSymbolAddress((void**)&p_w1t,  g_w1t);
    cudaGetSymbolAddress((void**)&p_w2t,  g_w2t);
    cudaGetSymbolAddress((void**)&p_qkv,  g_qkv);
    cudaGetSymbolAddress((void**)&p_atto, g_atto);
    cudaGetSymbolAddress((void**)&p_wsum, g_wsum);
    cudaGetSymbolAddress((void**)&p_x1,   g_x1);
    cudaGetSymbolAddress((void**)&p_h,    g_h);

    cudaFuncSetAttribute(mma_gemm<1>, cudaFuncAttributeMaxDynamicSharedMemorySize, GEMM_SMEM);
    cudaFuncSetAttribute(mma_gemm<2>, cudaFuncAttributeMaxDynamicSharedMemorySize, GEMM_SMEM);
    cudaFuncSetAttribute(mma_gemm<3>, cudaFuncAttributeMaxDynamicSharedMemorySize, GEMM_SMEM);
    cudaFuncSetAttribute(flash_mma, cudaFuncAttributeMaxDynamicSharedMemorySize, FLASH_SMEM);

    // ln1 + weight prep (all emit fp16)
    ln_kernel<<<ROWS, 256>>>(x, ln1w, ln1b, p_ln);
    pack_wqkv_t<<<dim3(6, 32, 16), dim3(32, 8)>>>(Wqkv, p_wqt);
    transpose_h<<<dim3(MDIM / 32, DDIM / 32), dim3(32, 8)>>>(W1, p_w1t, DDIM, MDIM);
    transpose_h<<<dim3(DDIM / 32, MDIM / 32), dim3(32, 8)>>>(W2, p_w2t, MDIM, DDIM);
    wsum_kernel<<<DDIM / 256, 256>>>(Wout, p_wsum);

    // QKV projection (fp16 HMMA, half out for flash)
    mma_gemm<3><<<dim3(QKVC / 128, ROWS / 128), 256, GEMM_SMEM>>>(
        p_ln, p_wqt, p_qkv, ROWS, QKVC, DDIM, nullptr, nullptr);

    // attention (fp16 HMMA flash, double-buffered)
    flash_mma<<<dim3(SDIM / 64, NHEAD, BDIM), 128, FLASH_SMEM>>>(p_qkv, p_atto);

    // residual + reinterpretation-projection
    resid_attn<<<dim3(DDIM / 32, SDIM / 32, BDIM), dim3(32, 8)>>>(
        x, p_atto, p_wsum, p_x1);

    // ln2
    ln_kernel<<<ROWS, 256>>>(p_x1, ln2w, ln2b, p_ln);

    // MLP (fp16 HMMA)
    mma_gemm<1><<<dim3(MDIM / 128, ROWS / 128), 256, GEMM_SMEM>>>(
        p_ln, p_w1t, p_h, ROWS, MDIM, DDIM, b1, nullptr);
    mma_gemm<2><<<dim3(DDIM / 128, ROWS / 128), 256, GEMM_SMEM>>>(
        p_h, p_w2t, out, ROWS, DDIM, MDIM, b2, p_x1);
}

// round 14
// speedup vs baseline: 5.9183x; 1.2023x over previous
#include <cuda_runtime.h>
#include <cuda_fp16.h>
#include <math.h>
#include <stdint.h>

// Problem constants
#define BDIM 2
#define SDIM 2048
#define DDIM 1024
#define NHEAD 16
#define HDIM 64
#define MDIM 4096
#define ROWS (BDIM*SDIM)          // 4096 token rows
#define QKVC (NHEAD*3*HDIM)       // 3072 packed qkv columns

// ---------------- scratch (device globals; no allocation allowed) ----------
__device__ __half g_ln  [ROWS*DDIM];
__device__ __half g_wqt [QKVC*DDIM];
__device__ __half g_w1t [MDIM*DDIM];
__device__ __half g_w2t [DDIM*MDIM];
__device__ __half g_qkv [ROWS*QKVC];
__device__ float  g_atto[BDIM*NHEAD*SDIM*HDIM];
__device__ float  g_wsum[DDIM];
__device__ float  g_x1  [ROWS*DDIM];
__device__ __half g_h   [ROWS*MDIM];

// ============================ helpers =======================================
__device__ __forceinline__ uint32_t smem_u32(const void* p) {
    uint32_t a;
    asm("{ .reg .u64 t; cvta.to.shared.u64 t, %1; cvt.u32.u64 %0, t; }"
        : "=r"(a) : "l"(p));
    return a;
}
__device__ __forceinline__ void cp16(uint32_t dst, const void* src) {
    asm volatile("cp.async.cg.shared.global [%0], [%1], 16;" :: "r"(dst), "l"(src));
}
__device__ __forceinline__ float gelu_exact(float v) {
    return 0.5f * v * (1.0f + erff(v * 0.70710678118654752440f));
}
__device__ __forceinline__ uint32_t pack_h2(float x, float y) {
    __half2 h = __floats2half2_rn(x, y);
    return *(uint32_t*)&h;
}

#define MMA_F16(c, a, b) \
    asm volatile("mma.sync.aligned.m16n8k16.row.col.f32.f16.f16.f32 " \
        "{%0,%1,%2,%3}, {%4,%5,%6,%7}, {%8,%9}, {%0,%1,%2,%3};" \
        : "+f"((c)[0]), "+f"((c)[1]), "+f"((c)[2]), "+f"((c)[3]) \
        : "r"((a)[0]), "r"((a)[1]), "r"((a)[2]), "r"((a)[3]), \
          "r"((b)[0]), "r"((b)[1]))

#define LDSM_X4(r0, r1, r2, r3, addr) \
    asm volatile("ldmatrix.sync.aligned.m8n8.x4.shared.b16 {%0,%1,%2,%3}, [%4];" \
        : "=r"(r0), "=r"(r1), "=r"(r2), "=r"(r3) : "r"(addr))
#define LDSM_X2(r0, r1, addr) \
    asm volatile("ldmatrix.sync.aligned.m8n8.x2.shared.b16 {%0,%1}, [%2];" \
        : "=r"(r0), "=r"(r1) : "r"(addr))
#define LDSM_X2T(r0, r1, addr) \
    asm volatile("ldmatrix.sync.aligned.m8n8.x2.trans.shared.b16 {%0,%1}, [%2];" \
        : "=r"(r0), "=r"(r1) : "r"(addr))

// ========== fp16 HMMA GEMM: C[M,N] = A[M,K] * Bt[N,K]^T =====================
// CTA 128x128, 256 thr (8 warps 2x4 -> warp tile 64x32). K staged at 32,
// 4-slot cp.async pipeline (3 in flight), ldmatrix fragments, 1 sync/stage.
// Pitch 40 halves: ldmatrix row banks (20r)%32 all distinct.
#define GP 40
#define STAGE_H (128*GP)
#define NSTG 4
#define GEMM_SMEM (2*NSTG*STAGE_H*2)          // 81920 bytes

// EPI: 1 = +bias, gelu -> half; 2 = +bias +res -> float; 3 = plain -> half
template<int EPI>
__global__ __launch_bounds__(256, 2)
void mma_gemm(const __half* __restrict__ A, const __half* __restrict__ Bt,
              void* __restrict__ Cv, int M, int N, int K,
              const float* __restrict__ bias, const float* __restrict__ res)
{
    extern __shared__ __half smh[];
    __half* As = smh;                  // [NSTG][STAGE_H]
    __half* Bs = smh + NSTG * STAGE_H;

    const int tid = threadIdx.x;
    const int wid = tid >> 5, lane = tid & 31;
    const int bm = blockIdx.y * 128, bn = blockIdx.x * 128;
    const int mbase = (wid >> 2) * 64;
    const int nbase = (wid & 3) * 32;
    const int q = lane >> 2, r4 = lane & 3;
    const int lr16 = lane & 15;              // A ldmatrix row-in-16
    const int lc8  = (lane >> 4) << 3;       // A ldmatrix col half-offset
    const int br   = lane & 7;               // B ldmatrix row
    const int bc   = lane & 8;               // B ldmatrix col half-offset

    const uint32_t sA = smem_u32(As);
    const uint32_t sB = smem_u32(Bs);
    const int nst = K >> 5;

    auto load_stage = [&](int s) {
        int slot = s & (NSTG - 1);
        int k0 = s << 5;
        const __half* Ag = A + (size_t)bm * K + k0;
        const __half* Bg = Bt + (size_t)bn * K + k0;
        uint32_t ab = sA + slot * (STAGE_H * 2);
        uint32_t bb = sB + slot * (STAGE_H * 2);
        #pragma unroll
        for (int i = 0; i < 2; ++i) {
            int linear = i * 256 + tid;
            int row = linear >> 2, c = linear & 3;
            uint32_t off = (uint32_t)(row * GP + c * 8) * 2;
            cp16(ab + off, Ag + (size_t)row * K + c * 8);
            cp16(bb + off, Bg + (size_t)row * K + c * 8);
        }
        asm volatile("cp.async.commit_group;" ::: "memory");
    };

    float c[4][4][4];
    #pragma unroll
    for (int mt = 0; mt < 4; ++mt)
        #pragma unroll
        for (int nt = 0; nt < 4; ++nt)
            #pragma unroll
            for (int j = 0; j < 4; ++j) c[mt][nt][j] = 0.f;

    load_stage(0); load_stage(1); load_stage(2);

    for (int s = 0; s < nst; ++s) {
        int slot = s & (NSTG - 1);
        asm volatile("cp.async.wait_group 2;" ::: "memory");
        __syncthreads();
        if (s + 3 < nst) load_stage(s + 3);
        else asm volatile("cp.async.commit_group;" ::: "memory");

        uint32_t aA = sA + slot * (STAGE_H * 2);
        uint32_t aB = sB + slot * (STAGE_H * 2);
        #pragma unroll
        for (int kk = 0; kk < 2; ++kk) {
            int kb = kk * 16;
            uint32_t a[4][4];
            #pragma unroll
            for (int mt = 0; mt < 4; ++mt) {
                uint32_t ad = aA +
                    (uint32_t)((mbase + mt * 16 + lr16) * GP + kb + lc8) * 2;
                LDSM_X4(a[mt][0], a[mt][1], a[mt][2], a[mt][3], ad);
            }
            uint32_t b[4][2];
            #pragma unroll
            for (int nt = 0; nt < 4; ++nt) {
                uint32_t bd = aB +
                    (uint32_t)((nbase + nt * 8 + br) * GP + kb + bc) * 2;
                LDSM_X2(b[nt][0], b[nt][1], bd);
            }
            #pragma unroll
            for (int mt = 0; mt < 4; ++mt)
                #pragma unroll
                for (int nt = 0; nt < 4; ++nt)
                    MMA_F16(c[mt][nt], a[mt], b[nt]);
        }
    }

    #pragma unroll
    for (int mt = 0; mt < 4; ++mt) {
        #pragma unroll
        for (int nt = 0; nt < 4; ++nt) {
            int row0 = bm + mbase + mt * 16 + q;
            int col  = bn + nbase + nt * 8 + r4 * 2;
            #pragma unroll
            for (int h = 0; h < 2; ++h) {
                int row = row0 + h * 8;
                float vx = c[mt][nt][2 * h], vy = c[mt][nt][2 * h + 1];
                if (EPI == 1) {
                    vx = gelu_exact(vx + bias[col]);
                    vy = gelu_exact(vy + bias[col + 1]);
                    __half* C = (__half*)Cv;
                    *(uint32_t*)(C + (size_t)row * N + col) = pack_h2(vx, vy);
                } else if (EPI == 2) {
                    const float* rp = res + (size_t)row * N + col;
                    vx += bias[col] + rp[0];
                    vy += bias[col + 1] + rp[1];
                    float* C = (float*)Cv;
                    *(float2*)(C + (size_t)row * N + col) = make_float2(vx, vy);
                } else {
                    __half* C = (__half*)Cv;
                    *(uint32_t*)(C + (size_t)row * N + col) = pack_h2(vx, vy);
                }
            }
        }
    }
}

// ---------------- layernorm (ddof=1, eps=1e-4) -> half ----------------------
__global__ __launch_bounds__(256) void ln_kernel(
    const float* __restrict__ x, const float* __restrict__ w,
    const float* __restrict__ bb, __half* __restrict__ y)
{
    int row = blockIdx.x;
    int t = threadIdx.x;
    const float4* xr = (const float4*)(x + (size_t)row * DDIM);
    float4 v = xr[t];

    __shared__ float red[8];
    __shared__ float s_mu, s_inv;

    float s = v.x + v.y + v.z + v.w;
    #pragma unroll
    for (int o = 16; o > 0; o >>= 1) s += __shfl_xor_sync(0xffffffffu, s, o);
    if ((t & 31) == 0) red[t >> 5] = s;
    __syncthreads();
    if (t == 0) {
        float tot = 0.f;
        #pragma unroll
        for (int i = 0; i < 8; ++i) tot += red[i];
        s_mu = tot * (1.0f / DDIM);
    }
    __syncthreads();
    float mu = s_mu;
    float dx = v.x - mu, dy = v.y - mu, dz = v.z - mu, dw = v.w - mu;
    float ss = dx*dx + dy*dy + dz*dz + dw*dw;
    #pragma unroll
    for (int o = 16; o > 0; o >>= 1) ss += __shfl_xor_sync(0xffffffffu, ss, o);
    __syncthreads();
    if ((t & 31) == 0) red[t >> 5] = ss;
    __syncthreads();
    if (t == 0) {
        float tot = 0.f;
        #pragma unroll
        for (int i = 0; i < 8; ++i) tot += red[i];
        s_inv = rsqrtf(tot * (1.0f / (DDIM - 1)) + 1e-4f);
    }
    __syncthreads();
    float inv = s_inv;
    float4 wv = ((const float4*)w)[t];
    float4 bv = ((const float4*)bb)[t];
    uint2 o;
    o.x = pack_h2(dx * inv * wv.x + bv.x, dy * inv * wv.y + bv.y);
    o.y = pack_h2(dz * inv * wv.z + bv.z, dw * inv * wv.w + bv.w);
    *(uint2*)(y + (size_t)row * DDIM + t * 4) = o;
}

// ------------- transpose [K,N] float -> [N,K] half --------------------------
__global__ __launch_bounds__(256) void transpose_h(
    const float* __restrict__ in, __half* __restrict__ out, int K, int N)
{
    __shared__ float t[32][33];
    int k0 = blockIdx.y * 32, n0 = blockIdx.x * 32;
    int tx = threadIdx.x, ty = threadIdx.y;
    #pragma unroll
    for (int r = 0; r < 32; r += 8)
        t[ty + r][tx] = in[(size_t)(k0 + ty + r) * N + n0 + tx];
    __syncthreads();
    #pragma unroll
    for (int r = 0; r < 32; r += 8)
        out[(size_t)(n0 + ty + r) * K + k0 + tx] = __float2half_rn(t[tx][ty + r]);
}

// ------- pack+transpose W_qkv[N,D,192] -> [(n*192+j), d] half ----------------
__global__ __launch_bounds__(256) void pack_wqkv_t(
    const float* __restrict__ W, __half* __restrict__ out)
{
    __shared__ float t[32][33];
    int j0 = blockIdx.x * 32, d0 = blockIdx.y * 32, n = blockIdx.z;
    int tx = threadIdx.x, ty = threadIdx.y;
    #pragma unroll
    for (int r = 0; r < 32; r += 8)
        t[ty + r][tx] = W[((size_t)n * DDIM + d0 + ty + r) * 192 + j0 + tx];
    __syncthreads();
    #pragma unroll
    for (int r = 0; r < 32; r += 8)
        out[((size_t)n * 192 + j0 + ty + r) * DDIM + d0 + tx] =
            __float2half_rn(t[tx][ty + r]);
}

// ---------------- w_sum[d] = sum_{n,h} W_out[n,h,d] -------------------------
__global__ __launch_bounds__(256) void wsum_kernel(
    const float* __restrict__ Wout, float* __restrict__ ws)
{
    int d = blockIdx.x * 256 + threadIdx.x;
    float s = 0.f;
    for (int i = 0; i < NHEAD * HDIM; ++i) s += Wout[(size_t)i * DDIM + d];
    ws[d] = s;
}

// ============ flash attention, fp16 HMMA + ldmatrix =========================
// 128 thr / 4 warps; warp w owns q rows [w*16, w*16+16).
// Q A-fragments hoisted (loop-invariant). K,V both row-major in smem,
// double-buffered; V B-fragments via ldmatrix.x2.trans. P register-direct.
#define FPH 72
#define FLASH_SMEM (5*64*FPH*2)   // Qs + 2*K + 2*V = 46080 bytes

__global__ __launch_bounds__(128) void flash_mma(
    const __half* __restrict__ qkv, float* __restrict__ atto)
{
    extern __shared__ __half smf[];
    __half* Qs = smf;                    // [64][FPH] Q, scaled
    __half* Kb = smf + 64 * FPH;         // [2][64][FPH] K row-major (j x h)
    __half* Vb = smf + 3 * 64 * FPH;     // [2][64][FPH] V row-major (j x h)

    const int qt = (int)gridDim.x - 1 - (int)blockIdx.x;   // longest first
    const int n = blockIdx.y, b = blockIdx.z;
    const int tid = threadIdx.x, wid = tid >> 5, lane = tid & 31;
    const int q = lane >> 2, r4 = lane & 3;
    const int lr16 = lane & 15, lc8 = (lane >> 4) << 3;
    const int br = lane & 7, bc = lane & 8;
    const int mrow = wid * 16;
    const __half* base = qkv + (size_t)b * SDIM * QKVC + n * 192;
    const __half2 qscale = __float2half2_rn(0.125f);   // exact

    // load Q tile, scaled
    #pragma unroll
    for (int i = 0; i < 4; ++i) {
        int linear = i * 128 + tid;
        int row = linear >> 3, c8 = (linear & 7) * 8;
        uint4 v = *(const uint4*)(base + (size_t)(qt * 64 + row) * QKVC + c8);
        __half2* h = (__half2*)&v;
        h[0] = __hmul2(h[0], qscale); h[1] = __hmul2(h[1], qscale);
        h[2] = __hmul2(h[2], qscale); h[3] = __hmul2(h[3], qscale);
        *(uint4*)(Qs + row * FPH + c8) = v;
    }

    uint4 kr[4], vr[4];
    auto ldg_tile = [&](int kt) {
        #pragma unroll
        for (int i = 0; i < 4; ++i) {
            int linear = i * 128 + tid;
            int row = linear >> 3, c8 = (linear & 7) * 8;
            const __half* rb = base + (size_t)(kt * 64 + row) * QKVC;
            kr[i] = *(const uint4*)(rb + 64 + c8);
            vr[i] = *(const uint4*)(rb + 128 + c8);
        }
    };
    auto sts_tile = [&](int buf) {
        __half* Ksb = Kb + buf * 64 * FPH;
        __half* Vsb = Vb + buf * 64 * FPH;
        #pragma unroll
        for (int i = 0; i < 4; ++i) {
            int linear = i * 128 + tid;
            int row = linear >> 3, c8 = (linear & 7) * 8;
            *(uint4*)(Ksb + row * FPH + c8) = kr[i];
            *(uint4*)(Vsb + row * FPH + c8) = vr[i];
        }
    };

    float m0 = -INFINITY, m1 = -INFINITY, l0 = 0.f, l1 = 0.f;
    float o[8][4];
    #pragma unroll
    for (int nt = 0; nt < 8; ++nt)
        o[nt][0] = o[nt][1] = o[nt][2] = o[nt][3] = 0.f;

    ldg_tile(0);
    sts_tile(0);
    __syncthreads();

    // Q A-fragments: loop-invariant, load once
    uint32_t aq[4][4];
    {
        uint32_t qb = smem_u32(Qs);
        #pragma unroll
        for (int kk = 0; kk < 4; ++kk) {
            uint32_t ad = qb + (uint32_t)((mrow + lr16) * FPH + kk * 16 + lc8) * 2;
            LDSM_X4(aq[kk][0], aq[kk][1], aq[kk][2], aq[kk][3], ad);
        }
    }

    const uint32_t kb0 = smem_u32(Kb);
    const uint32_t vb0 = smem_u32(Vb);

    for (int kt = 0; kt <= qt; ++kt) {
        int cur = kt & 1;
        if (kt < qt) ldg_tile(kt + 1);            // prefetch into registers

        uint32_t ks = kb0 + cur * (64 * FPH * 2);
        uint32_t vs = vb0 + cur * (64 * FPH * 2);

        // S = Q @ K^T  (16x64 per warp, 4 k16 steps)
        float c[8][4];
        #pragma unroll
        for (int nt = 0; nt < 8; ++nt)
            c[nt][0] = c[nt][1] = c[nt][2] = c[nt][3] = 0.f;
        #pragma unroll
        for (int kk = 0; kk < 4; ++kk) {
            int kb = kk * 16;
            #pragma unroll
            for (int nt = 0; nt < 8; ++nt) {
                uint32_t bd = ks + (uint32_t)((nt * 8 + br) * FPH + kb + bc) * 2;
                uint32_t bf[2];
                LDSM_X2(bf[0], bf[1], bd);
                MMA_F16(c[nt], aq[kk], bf);
            }
        }

        // causal mask on diagonal tile
        if (kt == qt) {
            int i0 = mrow + q;
            #pragma unroll
            for (int nt = 0; nt < 8; ++nt) {
                int j0 = nt * 8 + 2 * r4;
                if (j0     > i0)     c[nt][0] = -INFINITY;
                if (j0 + 1 > i0)     c[nt][1] = -INFINITY;
                if (j0     > i0 + 8) c[nt][2] = -INFINITY;
                if (j0 + 1 > i0 + 8) c[nt][3] = -INFINITY;
            }
        }

        // online softmax; rows live in 4 lanes (xor 1,2)
        float rm0 = -INFINITY, rm1 = -INFINITY;
        #pragma unroll
        for (int nt = 0; nt < 8; ++nt) {
            rm0 = fmaxf(rm0, fmaxf(c[nt][0], c[nt][1]));
            rm1 = fmaxf(rm1, fmaxf(c[nt][2], c[nt][3]));
        }
        rm0 = fmaxf(rm0, __shfl_xor_sync(0xffffffffu, rm0, 1));
        rm0 = fmaxf(rm0, __shfl_xor_sync(0xffffffffu, rm0, 2));
        rm1 = fmaxf(rm1, __shfl_xor_sync(0xffffffffu, rm1, 1));
        rm1 = fmaxf(rm1, __shfl_xor_sync(0xffffffffu, rm1, 2));
        float mn0 = fmaxf(m0, rm0), mn1 = fmaxf(m1, rm1);
        float al0 = __expf(m0 - mn0), al1 = __expf(m1 - mn1);
        m0 = mn0; m1 = mn1;
        float rs0 = 0.f, rs1 = 0.f;
        #pragma unroll
        for (int nt = 0; nt < 8; ++nt) {
            c[nt][0] = __expf(c[nt][0] - mn0); rs0 += c[nt][0];
            c[nt][1] = __expf(c[nt][1] - mn0); rs0 += c[nt][1];
            c[nt][2] = __expf(c[nt][2] - mn1); rs1 += c[nt][2];
            c[nt][3] = __expf(c[nt][3] - mn1); rs1 += c[nt][3];
        }
        rs0 += __shfl_xor_sync(0xffffffffu, rs0, 1);
        rs0 += __shfl_xor_sync(0xffffffffu, rs0, 2);
        rs1 += __shfl_xor_sync(0xffffffffu, rs1, 1);
        rs1 += __shfl_xor_sync(0xffffffffu, rs1, 2);
        l0 = l0 * al0 + rs0;
        l1 = l1 * al1 + rs1;
        #pragma unroll
        for (int nt = 0; nt < 8; ++nt) {
            o[nt][0] *= al0; o[nt][1] *= al0;
            o[nt][2] *= al1; o[nt][3] *= al1;
        }

        // O += P @ V — P register-direct A-fragments; V via ldmatrix.trans
        #pragma unroll
        for (int kk = 0; kk < 4; ++kk) {
            int kb = kk * 16;
            uint32_t a[4] = {pack_h2(c[2*kk][0],   c[2*kk][1]),
                             pack_h2(c[2*kk][2],   c[2*kk][3]),
                             pack_h2(c[2*kk+1][0], c[2*kk+1][1]),
                             pack_h2(c[2*kk+1][2], c[2*kk+1][3])};
            #pragma unroll
            for (int nt = 0; nt < 8; ++nt) {
                uint32_t vd = vs + (uint32_t)((kb + lr16) * FPH + nt * 8) * 2;
                uint32_t bf[2];
                LDSM_X2T(bf[0], bf[1], vd);
                MMA_F16(o[nt], a, bf);
            }
        }

        if (kt < qt) {
            sts_tile(cur ^ 1);
            __syncthreads();
        }
    }

    // normalize + store (b,n,s,h) fp32
    float inv0 = 1.0f / l0, inv1 = 1.0f / l1;
    float* ob = atto + ((size_t)(b * NHEAD + n) * SDIM + qt * 64) * HDIM;
    int row0 = mrow + q;
    #pragma unroll
    for (int nt = 0; nt < 8; ++nt) {
        int col = nt * 8 + 2 * r4;
        *(float2*)(ob + (size_t)row0 * HDIM + col) =
            make_float2(o[nt][0] * inv0, o[nt][1] * inv0);
        *(float2*)(ob + (size_t)(row0 + 8) * HDIM + col) =
            make_float2(o[nt][2] * inv1, o[nt][3] * inv1);
    }
}

// ------- residual + torch-reinterpretation "projection" ---------------------
__global__ void resid_attn(const float* __restrict__ x,
                           const float* __restrict__ atto,
                           const float* __restrict__ wsum,
                           float* __restrict__ x1)
{
    __shared__ float tile[32][33];
    int b = blockIdx.z;
    int d0 = blockIdx.x * 32, s0 = blockIdx.y * 32;
    int tx = threadIdx.x, ty = threadIdx.y;
    const float* ab = atto + (size_t)b * (DDIM * SDIM);
    #pragma unroll
    for (int r = 0; r < 32; r += 8) {
        int d = d0 + ty + r, s = s0 + tx;
        tile[ty + r][tx] = ab[(size_t)d * SDIM + s];
    }
    __syncthreads();
    #pragma unroll
    for (int r = 0; r < 32; r += 8) {
        int s = s0 + ty + r, d = d0 + tx;
        size_t idx = ((size_t)b * SDIM + s) * DDIM + d;
        x1[idx] = x[idx] + tile[tx][ty + r] * wsum[d];
    }
}

// ---------------------------------------------------------------------------
extern "C" void kernel_launch(void* const* d_in, const int* in_sizes, int n_in,
                              void* d_out, int out_size)
{
    const float* x    = (const float*)d_in[0];
    const float* Wqkv = (const float*)d_in[1];
    const float* Wout = (const float*)d_in[2];
    const float* ln1w = (const float*)d_in[3];
    const float* ln1b = (const float*)d_in[4];
    const float* ln2w = (const float*)d_in[5];
    const float* ln2b = (const float*)d_in[6];
    const float* W1   = (const float*)d_in[7];
    const float* b1   = (const float*)d_in[8];
    const float* W2   = (const float*)d_in[9];
    const float* b2   = (const float*)d_in[10];
    float* out = (float*)d_out;

    __half *p_ln, *p_wqt, *p_w1t, *p_w2t, *p_qkv, *p_h;
    float *p_atto, *p_wsum, *p_x1;
    cudaGetSymbolAddress((void**)&p_ln,   g_ln);
    cudaGetSymbolAddress((void**)&p_wqt,  g_wqt);
    cudaGetSymbolAddress((void**)&p_w1t,  g_w1t);
    cudaGetSymbolAddress((void**)&p_w2t,  g_w2t);
    cudaGetSymbolAddress((void**)&p_qkv,  g_qkv);
    cudaGetSymbolAddress((void**)&p_atto, g_atto);
    cudaGetSymbolAddress((void**)&p_wsum, g_wsum);
    cudaGetSymbolAddress((void**)&p_x1,   g_x1);
    cudaGetSymbolAddress((void**)&p_h,    g_h);

    cudaFuncSetAttribute(mma_gemm<1>, cudaFuncAttributeMaxDynamicSharedMemorySize, GEMM_SMEM);
    cudaFuncSetAttribute(mma_gemm<2>, cudaFuncAttributeMaxDynamicSharedMemorySize, GEMM_SMEM);
    cudaFuncSetAttribute(mma_gemm<3>, cudaFuncAttributeMaxDynamicSharedMemorySize, GEMM_SMEM);
    cudaFuncSetAttribute(flash_mma, cudaFuncAttributeMaxDynamicSharedMemorySize, FLASH_SMEM);

    // ln1 + weight prep (all emit fp16)
    ln_kernel<<<ROWS, 256>>>(x, ln1w, ln1b, p_ln);
    pack_wqkv_t<<<dim3(6, 32, 16), dim3(32, 8)>>>(Wqkv, p_wqt);
    transpose_h<<<dim3(MDIM / 32, DDIM / 32), dim3(32, 8)>>>(W1, p_w1t, DDIM, MDIM);
    transpose_h<<<dim3(DDIM / 32, MDIM / 32), dim3(32, 8)>>>(W2, p_w2t, MDIM, DDIM);
    wsum_kernel<<<DDIM / 256, 256>>>(Wout, p_wsum);

    // QKV projection (fp16 HMMA, half out for flash)
    mma_gemm<3><<<dim3(QKVC / 128, ROWS / 128), 256, GEMM_SMEM>>>(
        p_ln, p_wqt, p_qkv, ROWS, QKVC, DDIM, nullptr, nullptr);

    // attention (fp16 HMMA flash, ldmatrix + double buffer)
    flash_mma<<<dim3(SDIM / 64, NHEAD, BDIM), 128, FLASH_SMEM>>>(p_qkv, p_atto);

    // residual + reinterpretation-projection
    resid_attn<<<dim3(DDIM / 32, SDIM / 32, BDIM), dim3(32, 8)>>>(
        x, p_atto, p_wsum, p_x1);

    // ln2
    ln_kernel<<<ROWS, 256>>>(p_x1, ln2w, ln2b, p_ln);

    // MLP (fp16 HMMA)
    mma_gemm<1><<<dim3(MDIM / 128, ROWS / 128), 256, GEMM_SMEM>>>(
        p_ln, p_w1t, p_h, ROWS, MDIM, DDIM, b1, nullptr);
    mma_gemm<2><<<dim3(DDIM / 128, ROWS / 128), 256, GEMM_SMEM>>>(
        p_h, p_w2t, out, ROWS, DDIM, MDIM, b2, p_x1);
}

// round 15
// speedup vs baseline: 6.0267x; 1.0183x over previous
#include <cuda_runtime.h>
#include <cuda_fp16.h>
#include <math.h>
#include <stdint.h>

// Problem constants
#define BDIM 2
#define SDIM 2048
#define DDIM 1024
#define NHEAD 16
#define HDIM 64
#define MDIM 4096
#define ROWS (BDIM*SDIM)          // 4096 token rows
#define QKVC (NHEAD*3*HDIM)       // 3072 packed qkv columns

// ---------------- scratch (device globals; no allocation allowed) ----------
__device__ __half g_ln  [ROWS*DDIM];
__device__ __half g_wqt [QKVC*DDIM];
__device__ __half g_w1t [MDIM*DDIM];
__device__ __half g_w2t [DDIM*MDIM];
__device__ __half g_qkv [ROWS*QKVC];
__device__ float  g_atto[BDIM*NHEAD*SDIM*HDIM];
__device__ float  g_wsum[DDIM];
__device__ float  g_x1  [ROWS*DDIM];
__device__ __half g_h   [ROWS*MDIM];

// ============================ helpers =======================================
__device__ __forceinline__ uint32_t smem_u32(const void* p) {
    uint32_t a;
    asm("{ .reg .u64 t; cvta.to.shared.u64 t, %1; cvt.u32.u64 %0, t; }"
        : "=r"(a) : "l"(p));
    return a;
}
__device__ __forceinline__ void cp16(uint32_t dst, const void* src) {
    asm volatile("cp.async.cg.shared.global [%0], [%1], 16;" :: "r"(dst), "l"(src));
}
__device__ __forceinline__ float gelu_exact(float v) {
    return 0.5f * v * (1.0f + erff(v * 0.70710678118654752440f));
}
__device__ __forceinline__ uint32_t pack_h2(float x, float y) {
    __half2 h = __floats2half2_rn(x, y);
    return *(uint32_t*)&h;
}

#define MMA_F16(c, a, b) \
    asm volatile("mma.sync.aligned.m16n8k16.row.col.f32.f16.f16.f32 " \
        "{%0,%1,%2,%3}, {%4,%5,%6,%7}, {%8,%9}, {%0,%1,%2,%3};" \
        : "+f"((c)[0]), "+f"((c)[1]), "+f"((c)[2]), "+f"((c)[3]) \
        : "r"((a)[0]), "r"((a)[1]), "r"((a)[2]), "r"((a)[3]), \
          "r"((b)[0]), "r"((b)[1]))

#define LDSM_X4(r0, r1, r2, r3, addr) \
    asm volatile("ldmatrix.sync.aligned.m8n8.x4.shared.b16 {%0,%1,%2,%3}, [%4];" \
        : "=r"(r0), "=r"(r1), "=r"(r2), "=r"(r3) : "r"(addr))
#define LDSM_X4T(r0, r1, r2, r3, addr) \
    asm volatile("ldmatrix.sync.aligned.m8n8.x4.trans.shared.b16 {%0,%1,%2,%3}, [%4];" \
        : "=r"(r0), "=r"(r1), "=r"(r2), "=r"(r3) : "r"(addr))

// ========== fp16 HMMA GEMM: C[M,N] = A[M,K] * Bt[N,K]^T =====================
// CTA 128x128, 256 thr (8 warps 2x4 -> warp tile 64x32). K staged at 32,
// 4-slot cp.async pipeline (3 in flight), x4 ldmatrix everywhere, 1 sync/stage.
#define GP 40
#define STAGE_H (128*GP)
#define NSTG 4
#define GEMM_SMEM (2*NSTG*STAGE_H*2)          // 81920 bytes

// EPI: 1 = +bias, gelu -> half; 2 = +bias +res -> float; 3 = plain -> half
template<int EPI>
__global__ __launch_bounds__(256, 2)
void mma_gemm(const __half* __restrict__ A, const __half* __restrict__ Bt,
              void* __restrict__ Cv, int M, int N, int K,
              const float* __restrict__ bias, const float* __restrict__ res)
{
    extern __shared__ __half smh[];
    __half* As = smh;                  // [NSTG][STAGE_H]
    __half* Bs = smh + NSTG * STAGE_H;

    const int tid = threadIdx.x;
    const int wid = tid >> 5, lane = tid & 31;
    const int bm = blockIdx.y * 128, bn = blockIdx.x * 128;
    const int mbase = (wid >> 2) * 64;
    const int nbase = (wid & 3) * 32;
    const int q = lane >> 2, r4 = lane & 3;
    const int lr16 = lane & 15;              // A ldmatrix row-in-16
    const int lc8  = (lane >> 4) << 3;       // A ldmatrix col half-offset
    const int bRow = ((lane >> 4) << 3) + (lane & 7);   // B x4 row
    const int bCol = ((lane >> 3) & 1) << 3;            // B x4 col half-offset

    const uint32_t sA = smem_u32(As);
    const uint32_t sB = smem_u32(Bs);
    const int nst = K >> 5;

    auto load_stage = [&](int s) {
        int slot = s & (NSTG - 1);
        int k0 = s << 5;
        const __half* Ag = A + (size_t)bm * K + k0;
        const __half* Bg = Bt + (size_t)bn * K + k0;
        uint32_t ab = sA + slot * (STAGE_H * 2);
        uint32_t bb = sB + slot * (STAGE_H * 2);
        #pragma unroll
        for (int i = 0; i < 2; ++i) {
            int linear = i * 256 + tid;
            int row = linear >> 2, c = linear & 3;
            uint32_t off = (uint32_t)(row * GP + c * 8) * 2;
            cp16(ab + off, Ag + (size_t)row * K + c * 8);
            cp16(bb + off, Bg + (size_t)row * K + c * 8);
        }
        asm volatile("cp.async.commit_group;" ::: "memory");
    };

    float c[4][4][4];
    #pragma unroll
    for (int mt = 0; mt < 4; ++mt)
        #pragma unroll
        for (int nt = 0; nt < 4; ++nt)
            #pragma unroll
            for (int j = 0; j < 4; ++j) c[mt][nt][j] = 0.f;

    load_stage(0); load_stage(1); load_stage(2);

    for (int s = 0; s < nst; ++s) {
        int slot = s & (NSTG - 1);
        asm volatile("cp.async.wait_group 2;" ::: "memory");
        __syncthreads();
        if (s + 3 < nst) load_stage(s + 3);
        else asm volatile("cp.async.commit_group;" ::: "memory");

        uint32_t aA = sA + slot * (STAGE_H * 2);
        uint32_t aB = sB + slot * (STAGE_H * 2);
        #pragma unroll
        for (int kk = 0; kk < 2; ++kk) {
            int kb = kk * 16;
            uint32_t a[4][4];
            #pragma unroll
            for (int mt = 0; mt < 4; ++mt) {
                uint32_t ad = aA +
                    (uint32_t)((mbase + mt * 16 + lr16) * GP + kb + lc8) * 2;
                LDSM_X4(a[mt][0], a[mt][1], a[mt][2], a[mt][3], ad);
            }
            uint32_t b[4][2];
            #pragma unroll
            for (int ntp = 0; ntp < 2; ++ntp) {
                uint32_t bd = aB +
                    (uint32_t)((nbase + ntp * 16 + bRow) * GP + kb + bCol) * 2;
                LDSM_X4(b[2*ntp][0], b[2*ntp][1], b[2*ntp+1][0], b[2*ntp+1][1], bd);
            }
            #pragma unroll
            for (int mt = 0; mt < 4; ++mt)
                #pragma unroll
                for (int nt = 0; nt < 4; ++nt)
                    MMA_F16(c[mt][nt], a[mt], b[nt]);
        }
    }

    #pragma unroll
    for (int mt = 0; mt < 4; ++mt) {
        #pragma unroll
        for (int nt = 0; nt < 4; ++nt) {
            int row0 = bm + mbase + mt * 16 + q;
            int col  = bn + nbase + nt * 8 + r4 * 2;
            #pragma unroll
            for (int h = 0; h < 2; ++h) {
                int row = row0 + h * 8;
                float vx = c[mt][nt][2 * h], vy = c[mt][nt][2 * h + 1];
                if (EPI == 1) {
                    vx = gelu_exact(vx + bias[col]);
                    vy = gelu_exact(vy + bias[col + 1]);
                    __half* C = (__half*)Cv;
                    *(uint32_t*)(C + (size_t)row * N + col) = pack_h2(vx, vy);
                } else if (EPI == 2) {
                    const float* rp = res + (size_t)row * N + col;
                    vx += bias[col] + rp[0];
                    vy += bias[col + 1] + rp[1];
                    float* C = (float*)Cv;
                    *(float2*)(C + (size_t)row * N + col) = make_float2(vx, vy);
                } else {
                    __half* C = (__half*)Cv;
                    *(uint32_t*)(C + (size_t)row * N + col) = pack_h2(vx, vy);
                }
            }
        }
    }
}

// ---------------- layernorm (ddof=1, eps=1e-4) -> half ----------------------
__global__ __launch_bounds__(256) void ln_kernel(
    const float* __restrict__ x, const float* __restrict__ w,
    const float* __restrict__ bb, __half* __restrict__ y)
{
    int row = blockIdx.x;
    int t = threadIdx.x;
    const float4* xr = (const float4*)(x + (size_t)row * DDIM);
    float4 v = xr[t];

    __shared__ float red[8];
    __shared__ float s_mu, s_inv;

    float s = v.x + v.y + v.z + v.w;
    #pragma unroll
    for (int o = 16; o > 0; o >>= 1) s += __shfl_xor_sync(0xffffffffu, s, o);
    if ((t & 31) == 0) red[t >> 5] = s;
    __syncthreads();
    if (t == 0) {
        float tot = 0.f;
        #pragma unroll
        for (int i = 0; i < 8; ++i) tot += red[i];
        s_mu = tot * (1.0f / DDIM);
    }
    __syncthreads();
    float mu = s_mu;
    float dx = v.x - mu, dy = v.y - mu, dz = v.z - mu, dw = v.w - mu;
    float ss = dx*dx + dy*dy + dz*dz + dw*dw;
    #pragma unroll
    for (int o = 16; o > 0; o >>= 1) ss += __shfl_xor_sync(0xffffffffu, ss, o);
    __syncthreads();
    if ((t & 31) == 0) red[t >> 5] = ss;
    __syncthreads();
    if (t == 0) {
        float tot = 0.f;
        #pragma unroll
        for (int i = 0; i < 8; ++i) tot += red[i];
        s_inv = rsqrtf(tot * (1.0f / (DDIM - 1)) + 1e-4f);
    }
    __syncthreads();
    float inv = s_inv;
    float4 wv = ((const float4*)w)[t];
    float4 bv = ((const float4*)bb)[t];
    uint2 o;
    o.x = pack_h2(dx * inv * wv.x + bv.x, dy * inv * wv.y + bv.y);
    o.y = pack_h2(dz * inv * wv.z + bv.z, dw * inv * wv.w + bv.w);
    *(uint2*)(y + (size_t)row * DDIM + t * 4) = o;
}

// ------------- transpose [K,N] float -> [N,K] half --------------------------
__global__ __launch_bounds__(256) void transpose_h(
    const float* __restrict__ in, __half* __restrict__ out, int K, int N)
{
    __shared__ float t[32][33];
    int k0 = blockIdx.y * 32, n0 = blockIdx.x * 32;
    int tx = threadIdx.x, ty = threadIdx.y;
    #pragma unroll
    for (int r = 0; r < 32; r += 8)
        t[ty + r][tx] = in[(size_t)(k0 + ty + r) * N + n0 + tx];
    __syncthreads();
    #pragma unroll
    for (int r = 0; r < 32; r += 8)
        out[(size_t)(n0 + ty + r) * K + k0 + tx] = __float2half_rn(t[tx][ty + r]);
}

// ------- pack+transpose W_qkv[N,D,192] -> [(n*192+j), d] half ----------------
__global__ __launch_bounds__(256) void pack_wqkv_t(
    const float* __restrict__ W, __half* __restrict__ out)
{
    __shared__ float t[32][33];
    int j0 = blockIdx.x * 32, d0 = blockIdx.y * 32, n = blockIdx.z;
    int tx = threadIdx.x, ty = threadIdx.y;
    #pragma unroll
    for (int r = 0; r < 32; r += 8)
        t[ty + r][tx] = W[((size_t)n * DDIM + d0 + ty + r) * 192 + j0 + tx];
    __syncthreads();
    #pragma unroll
    for (int r = 0; r < 32; r += 8)
        out[((size_t)n * 192 + j0 + ty + r) * DDIM + d0 + tx] =
            __float2half_rn(t[tx][ty + r]);
}

// ---------------- w_sum[d] = sum_{n,h} W_out[n,h,d] -------------------------
__global__ __launch_bounds__(256) void wsum_kernel(
    const float* __restrict__ Wout, float* __restrict__ ws)
{
    int d = blockIdx.x * 256 + threadIdx.x;
    float s = 0.f;
    for (int i = 0; i < NHEAD * HDIM; ++i) s += Wout[(size_t)i * DDIM + d];
    ws[d] = s;
}

// ============ flash attention, fp16 HMMA + x4 ldmatrix ======================
// 128 q rows per CTA (256 thr / 8 warps, warp w owns rows [w*16, w*16+16)),
// k-tiles of 64, double-buffered with register prefetch. Q fragments hoisted,
// P register-direct, K via ldmatrix.x4, V via ldmatrix.x4.trans.
#define FPH 72
#define FLASH_SMEM ((128 + 256) * FPH * 2)   // Qs + 2*K + 2*V = 55296 bytes

__global__ __launch_bounds__(256) void flash_mma(
    const __half* __restrict__ qkv, float* __restrict__ atto)
{
    extern __shared__ __half smf[];
    __half* Qs = smf;                      // [128][FPH] Q, scaled
    __half* Kb = smf + 128 * FPH;          // [2][64][FPH] K row-major (j x h)
    __half* Vb = smf + 256 * FPH;          // [2][64][FPH] V row-major (j x h)

    const int qt = (int)gridDim.x - 1 - (int)blockIdx.x;   // longest first
    const int n = blockIdx.y, b = blockIdx.z;
    const int tid = threadIdx.x, wid = tid >> 5, lane = tid & 31;
    const int q = lane >> 2, r4 = lane & 3;
    const int lr16 = lane & 15, lc8 = (lane >> 4) << 3;
    const int bRow = ((lane >> 4) << 3) + (lane & 7);
    const int bCol = ((lane >> 3) & 1) << 3;
    const int mrow = wid * 16;
    const __half* base = qkv + (size_t)b * SDIM * QKVC + n * 192;
    const __half2 qscale = __float2half2_rn(0.125f);   // exact

    // load Q tile (128 rows), scaled
    #pragma unroll
    for (int i = 0; i < 4; ++i) {
        int linear = i * 256 + tid;
        int row = linear >> 3, c8 = (linear & 7) * 8;
        uint4 v = *(const uint4*)(base + (size_t)(qt * 128 + row) * QKVC + c8);
        __half2* h = (__half2*)&v;
        h[0] = __hmul2(h[0], qscale); h[1] = __hmul2(h[1], qscale);
        h[2] = __hmul2(h[2], qscale); h[3] = __hmul2(h[3], qscale);
        *(uint4*)(Qs + row * FPH + c8) = v;
    }

    uint4 kr[2], vr[2];
    auto ldg_tile = [&](int kt) {
        #pragma unroll
        for (int i = 0; i < 2; ++i) {
            int linear = i * 256 + tid;
            int row = linear >> 3, c8 = (linear & 7) * 8;
            const __half* rb = base + (size_t)(kt * 64 + row) * QKVC;
            kr[i] = *(const uint4*)(rb + 64 + c8);
            vr[i] = *(const uint4*)(rb + 128 + c8);
        }
    };
    auto sts_tile = [&](int buf) {
        __half* Ksb = Kb + buf * 64 * FPH;
        __half* Vsb = Vb + buf * 64 * FPH;
        #pragma unroll
        for (int i = 0; i < 2; ++i) {
            int linear = i * 256 + tid;
            int row = linear >> 3, c8 = (linear & 7) * 8;
            *(uint4*)(Ksb + row * FPH + c8) = kr[i];
            *(uint4*)(Vsb + row * FPH + c8) = vr[i];
        }
    };

    float m0 = -INFINITY, m1 = -INFINITY, l0 = 0.f, l1 = 0.f;
    float o[8][4];
    #pragma unroll
    for (int nt = 0; nt < 8; ++nt)
        o[nt][0] = o[nt][1] = o[nt][2] = o[nt][3] = 0.f;

    ldg_tile(0);
    sts_tile(0);
    __syncthreads();

    // Q A-fragments: loop-invariant, load once
    uint32_t aq[4][4];
    {
        uint32_t qb = smem_u32(Qs);
        #pragma unroll
        for (int kk = 0; kk < 4; ++kk) {
            uint32_t ad = qb + (uint32_t)((mrow + lr16) * FPH + kk * 16 + lc8) * 2;
            LDSM_X4(aq[kk][0], aq[kk][1], aq[kk][2], aq[kk][3], ad);
        }
    }

    const uint32_t kb0 = smem_u32(Kb);
    const uint32_t vb0 = smem_u32(Vb);
    const int kend = 2 * qt + 1;

    for (int kt = 0; kt <= kend; ++kt) {
        int cur = kt & 1;
        if (kt < kend) ldg_tile(kt + 1);          // prefetch into registers

        // warp fully masked on this tile? (all j > all i) — skip compute
        bool active = (kt * 64) <= (qt * 128 + mrow + 15);

        if (active) {
            uint32_t ks = kb0 + cur * (64 * FPH * 2);
            uint32_t vs = vb0 + cur * (64 * FPH * 2);

            // S = Q @ K^T  (16x64 per warp, 4 k16 steps)
            float c[8][4];
            #pragma unroll
            for (int nt = 0; nt < 8; ++nt)
                c[nt][0] = c[nt][1] = c[nt][2] = c[nt][3] = 0.f;
            #pragma unroll
            for (int kk = 0; kk < 4; ++kk) {
                int kb = kk * 16;
                #pragma unroll
                for (int ntp = 0; ntp < 4; ++ntp) {
                    uint32_t bd = ks +
                        (uint32_t)((ntp * 16 + bRow) * FPH + kb + bCol) * 2;
                    uint32_t bf[4];
                    LDSM_X4(bf[0], bf[1], bf[2], bf[3], bd);
                    MMA_F16(c[2*ntp],   aq[kk], bf);
                    MMA_F16(c[2*ntp+1], aq[kk], bf + 2);
                }
            }

            // causal mask (global indices) — only near the diagonal
            if (kt * 64 + 63 > qt * 128 + mrow) {
                int i0 = qt * 128 + mrow + q;
                #pragma unroll
                for (int nt = 0; nt < 8; ++nt) {
                    int j0 = kt * 64 + nt * 8 + 2 * r4;
                    if (j0     > i0)     c[nt][0] = -INFINITY;
                    if (j0 + 1 > i0)     c[nt][1] = -INFINITY;
                    if (j0     > i0 + 8) c[nt][2] = -INFINITY;
                    if (j0 + 1 > i0 + 8) c[nt][3] = -INFINITY;
                }
            }

            // online softmax; rows live in 4 lanes (xor 1,2)
            float rm0 = -INFINITY, rm1 = -INFINITY;
            #pragma unroll
            for (int nt = 0; nt < 8; ++nt) {
                rm0 = fmaxf(rm0, fmaxf(c[nt][0], c[nt][1]));
                rm1 = fmaxf(rm1, fmaxf(c[nt][2], c[nt][3]));
            }
            rm0 = fmaxf(rm0, __shfl_xor_sync(0xffffffffu, rm0, 1));
            rm0 = fmaxf(rm0, __shfl_xor_sync(0xffffffffu, rm0, 2));
            rm1 = fmaxf(rm1, __shfl_xor_sync(0xffffffffu, rm1, 1));
            rm1 = fmaxf(rm1, __shfl_xor_sync(0xffffffffu, rm1, 2));
            float mn0 = fmaxf(m0, rm0), mn1 = fmaxf(m1, rm1);
            float al0 = __expf(m0 - mn0), al1 = __expf(m1 - mn1);
            m0 = mn0; m1 = mn1;
            float rs0 = 0.f, rs1 = 0.f;
            #pragma unroll
            for (int nt = 0; nt < 8; ++nt) {
                c[nt][0] = __expf(c[nt][0] - mn0); rs0 += c[nt][0];
                c[nt][1] = __expf(c[nt][1] - mn0); rs0 += c[nt][1];
                c[nt][2] = __expf(c[nt][2] - mn1); rs1 += c[nt][2];
                c[nt][3] = __expf(c[nt][3] - mn1); rs1 += c[nt][3];
            }
            rs0 += __shfl_xor_sync(0xffffffffu, rs0, 1);
            rs0 += __shfl_xor_sync(0xffffffffu, rs0, 2);
            rs1 += __shfl_xor_sync(0xffffffffu, rs1, 1);
            rs1 += __shfl_xor_sync(0xffffffffu, rs1, 2);
            l0 = l0 * al0 + rs0;
            l1 = l1 * al1 + rs1;
            #pragma unroll
            for (int nt = 0; nt < 8; ++nt) {
                o[nt][0] *= al0; o[nt][1] *= al0;
                o[nt][2] *= al1; o[nt][3] *= al1;
            }

            // O += P @ V — P register-direct A-fragments; V via ldmatrix.x4.trans
            #pragma unroll
            for (int kk = 0; kk < 4; ++kk) {
                int kb = kk * 16;
                uint32_t a[4] = {pack_h2(c[2*kk][0],   c[2*kk][1]),
                                 pack_h2(c[2*kk][2],   c[2*kk][3]),
                                 pack_h2(c[2*kk+1][0], c[2*kk+1][1]),
                                 pack_h2(c[2*kk+1][2], c[2*kk+1][3])};
                #pragma unroll
                for (int ntp = 0; ntp < 4; ++ntp) {
                    uint32_t vd = vs +
                        (uint32_t)((kb + lr16) * FPH + ntp * 16 + lc8) * 2;
                    uint32_t bf[4];
                    LDSM_X4T(bf[0], bf[1], bf[2], bf[3], vd);
                    MMA_F16(o[2*ntp],   a, bf);
                    MMA_F16(o[2*ntp+1], a, bf + 2);
                }
            }
        }

        if (kt < kend) {
            sts_tile(cur ^ 1);
            __syncthreads();
        }
    }

    // normalize + store (b,n,s,h) fp32
    float inv0 = 1.0f / l0, inv1 = 1.0f / l1;
    float* ob = atto + ((size_t)(b * NHEAD + n) * SDIM + qt * 128) * HDIM;
    int row0 = mrow + q;
    #pragma unroll
    for (int nt = 0; nt < 8; ++nt) {
        int col = nt * 8 + 2 * r4;
        *(float2*)(ob + (size_t)row0 * HDIM + col) =
            make_float2(o[nt][0] * inv0, o[nt][1] * inv0);
        *(float2*)(ob + (size_t)(row0 + 8) * HDIM + col) =
            make_float2(o[nt][2] * inv1, o[nt][3] * inv1);
    }
}

// ------- residual + torch-reinterpretation "projection" ---------------------
__global__ void resid_attn(const float* __restrict__ x,
                           const float* __restrict__ atto,
                           const float* __restrict__ wsum,
                           float* __restrict__ x1)
{
    __shared__ float tile[32][33];
    int b = blockIdx.z;
    int d0 = blockIdx.x * 32, s0 = blockIdx.y * 32;
    int tx = threadIdx.x, ty = threadIdx.y;
    const float* ab = atto + (size_t)b * (DDIM * SDIM);
    #pragma unroll
    for (int r = 0; r < 32; r += 8) {
        int d = d0 + ty + r, s = s0 + tx;
        tile[ty + r][tx] = ab[(size_t)d * SDIM + s];
    }
    __syncthreads();
    #pragma unroll
    for (int r = 0; r < 32; r += 8) {
        int s = s0 + ty + r, d = d0 + tx;
        size_t idx = ((size_t)b * SDIM + s) * DDIM + d;
        x1[idx] = x[idx] + tile[tx][ty + r] * wsum[d];
    }
}

// ---------------------------------------------------------------------------
extern "C" void kernel_launch(void* const* d_in, const int* in_sizes, int n_in,
                              void* d_out, int out_size)
{
    const float* x    = (const float*)d_in[0];
    const float* Wqkv = (const float*)d_in[1];
    const float* Wout = (const float*)d_in[2];
    const float* ln1w = (const float*)d_in[3];
    const float* ln1b = (const float*)d_in[4];
    const float* ln2w = (const float*)d_in[5];
    const float* ln2b = (const float*)d_in[6];
    const float* W1   = (const float*)d_in[7];
    const float* b1   = (const float*)d_in[8];
    const float* W2   = (const float*)d_in[9];
    const float* b2   = (const float*)d_in[10];
    float* out = (float*)d_out;

    __half *p_ln, *p_wqt, *p_w1t, *p_w2t, *p_qkv, *p_h;
    float *p_atto, *p_wsum, *p_x1;
    cudaGetSymbolAddress((void**)&p_ln,   g_ln);
    cudaGetSymbolAddress((void**)&p_wqt,  g_wqt);
    cudaGetSymbolAddress((void**)&p_w1t,  g_w1t);
    cudaGetSymbolAddress((void**)&p_w2t,  g_w2t);
    cudaGetSymbolAddress((void**)&p_qkv,  g_qkv);
    cudaGetSymbolAddress((void**)&p_atto, g_atto);
    cudaGetSymbolAddress((void**)&p_wsum, g_wsum);
    cudaGetSymbolAddress((void**)&p_x1,   g_x1);
    cudaGetSymbolAddress((void**)&p_h,    g_h);

    cudaFuncSetAttribute(mma_gemm<1>, cudaFuncAttributeMaxDynamicSharedMemorySize, GEMM_SMEM);
    cudaFuncSetAttribute(mma_gemm<2>, cudaFuncAttributeMaxDynamicSharedMemorySize, GEMM_SMEM);
    cudaFuncSetAttribute(mma_gemm<3>, cudaFuncAttributeMaxDynamicSharedMemorySize, GEMM_SMEM);
    cudaFuncSetAttribute(flash_mma, cudaFuncAttributeMaxDynamicSharedMemorySize, FLASH_SMEM);

    // ln1 + weight prep (all emit fp16)
    ln_kernel<<<ROWS, 256>>>(x, ln1w, ln1b, p_ln);
    pack_wqkv_t<<<dim3(6, 32, 16), dim3(32, 8)>>>(Wqkv, p_wqt);
    transpose_h<<<dim3(MDIM / 32, DDIM / 32), dim3(32, 8)>>>(W1, p_w1t, DDIM, MDIM);
    transpose_h<<<dim3(DDIM / 32, MDIM / 32), dim3(32, 8)>>>(W2, p_w2t, MDIM, DDIM);
    wsum_kernel<<<DDIM / 256, 256>>>(Wout, p_wsum);

    // QKV projection (fp16 HMMA, half out for flash)
    mma_gemm<3><<<dim3(QKVC / 128, ROWS / 128), 256, GEMM_SMEM>>>(
        p_ln, p_wqt, p_qkv, ROWS, QKVC, DDIM, nullptr, nullptr);

    // attention (fp16 HMMA flash, 128-row q tiles)
    flash_mma<<<dim3(SDIM / 128, NHEAD, BDIM), 256, FLASH_SMEM>>>(p_qkv, p_atto);

    // residual + reinterpretation-projection
    resid_attn<<<dim3(DDIM / 32, SDIM / 32, BDIM), dim3(32, 8)>>>(
        x, p_atto, p_wsum, p_x1);

    // ln2
    ln_kernel<<<ROWS, 256>>>(p_x1, ln2w, ln2b, p_ln);

    // MLP (fp16 HMMA)
    mma_gemm<1><<<dim3(MDIM / 128, ROWS / 128), 256, GEMM_SMEM>>>(
        p_ln, p_w1t, p_h, ROWS, MDIM, DDIM, b1, nullptr);
    mma_gemm<2><<<dim3(DDIM / 128, ROWS / 128), 256, GEMM_SMEM>>>(
        p_h, p_w2t, out, ROWS, DDIM, MDIM, b2, p_x1);
}

// round 16
// speedup vs baseline: 6.3849x; 1.0594x over previous
#include <cuda_runtime.h>
#include <cuda_fp16.h>
#include <math.h>
#include <stdint.h>

// Problem constants
#define BDIM 2
#define SDIM 2048
#define DDIM 1024
#define NHEAD 16
#define HDIM 64
#define MDIM 4096
#define ROWS (BDIM*SDIM)          // 4096 token rows
#define QKVC (NHEAD*3*HDIM)       // 3072 packed qkv columns

// ---------------- scratch (device globals; no allocation allowed) ----------
__device__ __half g_ln  [ROWS*DDIM];
__device__ __half g_wqt [QKVC*DDIM];
__device__ __half g_w1t [MDIM*DDIM];
__device__ __half g_w2t [DDIM*MDIM];
__device__ __half g_qkv [ROWS*QKVC];
__device__ float  g_atto[BDIM*NHEAD*SDIM*HDIM];
__device__ float  g_wsum[DDIM];
__device__ float  g_x1  [ROWS*DDIM];
__device__ __half g_h   [ROWS*MDIM];

// ============================ helpers =======================================
__device__ __forceinline__ uint32_t smem_u32(const void* p) {
    uint32_t a;
    asm("{ .reg .u64 t; cvta.to.shared.u64 t, %1; cvt.u32.u64 %0, t; }"
        : "=r"(a) : "l"(p));
    return a;
}
__device__ __forceinline__ void cp16(uint32_t dst, const void* src) {
    asm volatile("cp.async.cg.shared.global [%0], [%1], 16;" :: "r"(dst), "l"(src));
}
__device__ __forceinline__ float gelu_exact(float v) {
    return 0.5f * v * (1.0f + erff(v * 0.70710678118654752440f));
}
__device__ __forceinline__ uint32_t pack_h2(float x, float y) {
    __half2 h = __floats2half2_rn(x, y);
    return *(uint32_t*)&h;
}

#define MMA_F16(c, a, b) \
    asm volatile("mma.sync.aligned.m16n8k16.row.col.f32.f16.f16.f32 " \
        "{%0,%1,%2,%3}, {%4,%5,%6,%7}, {%8,%9}, {%0,%1,%2,%3};" \
        : "+f"((c)[0]), "+f"((c)[1]), "+f"((c)[2]), "+f"((c)[3]) \
        : "r"((a)[0]), "r"((a)[1]), "r"((a)[2]), "r"((a)[3]), \
          "r"((b)[0]), "r"((b)[1]))

#define LDSM_X4(r0, r1, r2, r3, addr) \
    asm volatile("ldmatrix.sync.aligned.m8n8.x4.shared.b16 {%0,%1,%2,%3}, [%4];" \
        : "=r"(r0), "=r"(r1), "=r"(r2), "=r"(r3) : "r"(addr))
#define LDSM_X4T(r0, r1, r2, r3, addr) \
    asm volatile("ldmatrix.sync.aligned.m8n8.x4.trans.shared.b16 {%0,%1,%2,%3}, [%4];" \
        : "=r"(r0), "=r"(r1), "=r"(r2), "=r"(r3) : "r"(addr))

// ========== fp16 HMMA GEMM: C[M,N] = A[M,K] * Bt[N,K]^T =====================
// CTA 128x128, 128 thr (4 warps 2x2 -> warp tile 64x64, 1:4 LDSM:MMA ratio).
// K staged at 32, 4-slot cp.async pipeline (3 in flight), 1 sync/stage.
// 2 CTAs/SM. Pitch 40 halves: conflict-free ldmatrix.
#define GP 40
#define STAGE_H (128*GP)
#define NSTG 4
#define GEMM_SMEM (2*NSTG*STAGE_H*2)          // 81920 bytes

// EPI: 1 = +bias, gelu -> half; 2 = +bias +res -> float; 3 = plain -> half
template<int EPI>
__global__ __launch_bounds__(128, 2)
void mma_gemm(const __half* __restrict__ A, const __half* __restrict__ Bt,
              void* __restrict__ Cv, int M, int N, int K,
              const float* __restrict__ bias, const float* __restrict__ res)
{
    extern __shared__ __half smh[];
    __half* As = smh;                  // [NSTG][STAGE_H]
    __half* Bs = smh + NSTG * STAGE_H;

    const int tid = threadIdx.x;
    const int wid = tid >> 5, lane = tid & 31;
    const int bm = blockIdx.y * 128, bn = blockIdx.x * 128;
    const int mbase = (wid >> 1) * 64;
    const int nbase = (wid & 1) * 64;
    const int q = lane >> 2, r4 = lane & 3;
    const int lr16 = lane & 15;              // A ldmatrix row-in-16
    const int lc8  = (lane >> 4) << 3;       // A ldmatrix col half-offset
    const int bRow = ((lane >> 4) << 3) + (lane & 7);   // B x4 row
    const int bCol = ((lane >> 3) & 1) << 3;            // B x4 col half-offset

    const uint32_t sA = smem_u32(As);
    const uint32_t sB = smem_u32(Bs);
    const int nst = K >> 5;

    auto load_stage = [&](int s) {
        int slot = s & (NSTG - 1);
        int k0 = s << 5;
        const __half* Ag = A + (size_t)bm * K + k0;
        const __half* Bg = Bt + (size_t)bn * K + k0;
        uint32_t ab = sA + slot * (STAGE_H * 2);
        uint32_t bb = sB + slot * (STAGE_H * 2);
        #pragma unroll
        for (int i = 0; i < 4; ++i) {
            int linear = i * 128 + tid;          // 0..511
            int row = linear >> 2, c = linear & 3;
            uint32_t off = (uint32_t)(row * GP + c * 8) * 2;
            cp16(ab + off, Ag + (size_t)row * K + c * 8);
            cp16(bb + off, Bg + (size_t)row * K + c * 8);
        }
        asm volatile("cp.async.commit_group;" ::: "memory");
    };

    float c[4][8][4];
    #pragma unroll
    for (int mt = 0; mt < 4; ++mt)
        #pragma unroll
        for (int nt = 0; nt < 8; ++nt)
            #pragma unroll
            for (int j = 0; j < 4; ++j) c[mt][nt][j] = 0.f;

    load_stage(0); load_stage(1); load_stage(2);

    for (int s = 0; s < nst; ++s) {
        int slot = s & (NSTG - 1);
        asm volatile("cp.async.wait_group 2;" ::: "memory");
        __syncthreads();
        if (s + 3 < nst) load_stage(s + 3);
        else asm volatile("cp.async.commit_group;" ::: "memory");

        uint32_t aA = sA + slot * (STAGE_H * 2);
        uint32_t aB = sB + slot * (STAGE_H * 2);
        #pragma unroll
        for (int kk = 0; kk < 2; ++kk) {
            int kb = kk * 16;
            uint32_t a[4][4];
            #pragma unroll
            for (int mt = 0; mt < 4; ++mt) {
                uint32_t ad = aA +
                    (uint32_t)((mbase + mt * 16 + lr16) * GP + kb + lc8) * 2;
                LDSM_X4(a[mt][0], a[mt][1], a[mt][2], a[mt][3], ad);
            }
            uint32_t b[8][2];
            #pragma unroll
            for (int ntp = 0; ntp < 4; ++ntp) {
                uint32_t bd = aB +
                    (uint32_t)((nbase + ntp * 16 + bRow) * GP + kb + bCol) * 2;
                LDSM_X4(b[2*ntp][0], b[2*ntp][1], b[2*ntp+1][0], b[2*ntp+1][1], bd);
            }
            #pragma unroll
            for (int mt = 0; mt < 4; ++mt)
                #pragma unroll
                for (int nt = 0; nt < 8; ++nt)
                    MMA_F16(c[mt][nt], a[mt], b[nt]);
        }
    }

    #pragma unroll
    for (int mt = 0; mt < 4; ++mt) {
        #pragma unroll
        for (int nt = 0; nt < 8; ++nt) {
            int row0 = bm + mbase + mt * 16 + q;
            int col  = bn + nbase + nt * 8 + r4 * 2;
            #pragma unroll
            for (int h = 0; h < 2; ++h) {
                int row = row0 + h * 8;
                float vx = c[mt][nt][2 * h], vy = c[mt][nt][2 * h + 1];
                if (EPI == 1) {
                    vx = gelu_exact(vx + bias[col]);
                    vy = gelu_exact(vy + bias[col + 1]);
                    __half* C = (__half*)Cv;
                    *(uint32_t*)(C + (size_t)row * N + col) = pack_h2(vx, vy);
                } else if (EPI == 2) {
                    const float* rp = res + (size_t)row * N + col;
                    vx += bias[col] + rp[0];
                    vy += bias[col + 1] + rp[1];
                    float* C = (float*)Cv;
                    *(float2*)(C + (size_t)row * N + col) = make_float2(vx, vy);
                } else {
                    __half* C = (__half*)Cv;
                    *(uint32_t*)(C + (size_t)row * N + col) = pack_h2(vx, vy);
                }
            }
        }
    }
}

// ---------------- layernorm (ddof=1, eps=1e-4) -> half ----------------------
__global__ __launch_bounds__(256) void ln_kernel(
    const float* __restrict__ x, const float* __restrict__ w,
    const float* __restrict__ bb, __half* __restrict__ y)
{
    int row = blockIdx.x;
    int t = threadIdx.x;
    const float4* xr = (const float4*)(x + (size_t)row * DDIM);
    float4 v = xr[t];

    __shared__ float red[8];
    __shared__ float s_mu, s_inv;

    float s = v.x + v.y + v.z + v.w;
    #pragma unroll
    for (int o = 16; o > 0; o >>= 1) s += __shfl_xor_sync(0xffffffffu, s, o);
    if ((t & 31) == 0) red[t >> 5] = s;
    __syncthreads();
    if (t == 0) {
        float tot = 0.f;
        #pragma unroll
        for (int i = 0; i < 8; ++i) tot += red[i];
        s_mu = tot * (1.0f / DDIM);
    }
    __syncthreads();
    float mu = s_mu;
    float dx = v.x - mu, dy = v.y - mu, dz = v.z - mu, dw = v.w - mu;
    float ss = dx*dx + dy*dy + dz*dz + dw*dw;
    #pragma unroll
    for (int o = 16; o > 0; o >>= 1) ss += __shfl_xor_sync(0xffffffffu, ss, o);
    __syncthreads();
    if ((t & 31) == 0) red[t >> 5] = ss;
    __syncthreads();
    if (t == 0) {
        float tot = 0.f;
        #pragma unroll
        for (int i = 0; i < 8; ++i) tot += red[i];
        s_inv = rsqrtf(tot * (1.0f / (DDIM - 1)) + 1e-4f);
    }
    __syncthreads();
    float inv = s_inv;
    float4 wv = ((const float4*)w)[t];
    float4 bv = ((const float4*)bb)[t];
    uint2 o;
    o.x = pack_h2(dx * inv * wv.x + bv.x, dy * inv * wv.y + bv.y);
    o.y = pack_h2(dz * inv * wv.z + bv.z, dw * inv * wv.w + bv.w);
    *(uint2*)(y + (size_t)row * DDIM + t * 4) = o;
}

// ------------- transpose [K,N] float -> [N,K] half --------------------------
__global__ __launch_bounds__(256) void transpose_h(
    const float* __restrict__ in, __half* __restrict__ out, int K, int N)
{
    __shared__ float t[32][33];
    int k0 = blockIdx.y * 32, n0 = blockIdx.x * 32;
    int tx = threadIdx.x, ty = threadIdx.y;
    #pragma unroll
    for (int r = 0; r < 32; r += 8)
        t[ty + r][tx] = in[(size_t)(k0 + ty + r) * N + n0 + tx];
    __syncthreads();
    #pragma unroll
    for (int r = 0; r < 32; r += 8)
        out[(size_t)(n0 + ty + r) * K + k0 + tx] = __float2half_rn(t[tx][ty + r]);
}

// ------- pack+transpose W_qkv[N,D,192] -> [(n*192+j), d] half ----------------
__global__ __launch_bounds__(256) void pack_wqkv_t(
    const float* __restrict__ W, __half* __restrict__ out)
{
    __shared__ float t[32][33];
    int j0 = blockIdx.x * 32, d0 = blockIdx.y * 32, n = blockIdx.z;
    int tx = threadIdx.x, ty = threadIdx.y;
    #pragma unroll
    for (int r = 0; r < 32; r += 8)
        t[ty + r][tx] = W[((size_t)n * DDIM + d0 + ty + r) * 192 + j0 + tx];
    __syncthreads();
    #pragma unroll
    for (int r = 0; r < 32; r += 8)
        out[((size_t)n * 192 + j0 + ty + r) * DDIM + d0 + tx] =
            __float2half_rn(t[tx][ty + r]);
}

// ---------------- w_sum[d] = sum_{n,h} W_out[n,h,d] -------------------------
__global__ __launch_bounds__(256) void wsum_kernel(
    const float* __restrict__ Wout, float* __restrict__ ws)
{
    int d = blockIdx.x * 256 + threadIdx.x;
    float s = 0.f;
    for (int i = 0; i < NHEAD * HDIM; ++i) s += Wout[(size_t)i * DDIM + d];
    ws[d] = s;
}

// ============ flash attention, fp16 HMMA + x4 ldmatrix ======================
// 128 q rows per CTA (256 thr / 8 warps), k-tiles of 64, double-buffered with
// register prefetch. Q fragments hoisted, P register-direct.
#define FPH 72
#define FLASH_SMEM ((128 + 256) * FPH * 2)   // Qs + 2*K + 2*V = 55296 bytes

__global__ __launch_bounds__(256) void flash_mma(
    const __half* __restrict__ qkv, float* __restrict__ atto)
{
    extern __shared__ __half smf[];
    __half* Qs = smf;                      // [128][FPH] Q, scaled
    __half* Kb = smf + 128 * FPH;          // [2][64][FPH] K row-major (j x h)
    __half* Vb = smf + 256 * FPH;          // [2][64][FPH] V row-major (j x h)

    const int qt = (int)gridDim.x - 1 - (int)blockIdx.x;   // longest first
    const int n = blockIdx.y, b = blockIdx.z;
    const int tid = threadIdx.x, wid = tid >> 5, lane = tid & 31;
    const int q = lane >> 2, r4 = lane & 3;
    const int lr16 = lane & 15, lc8 = (lane >> 4) << 3;
    const int bRow = ((lane >> 4) << 3) + (lane & 7);
    const int bCol = ((lane >> 3) & 1) << 3;
    const int mrow = wid * 16;
    const __half* base = qkv + (size_t)b * SDIM * QKVC + n * 192;
    const __half2 qscale = __float2half2_rn(0.125f);   // exact

    // load Q tile (128 rows), scaled
    #pragma unroll
    for (int i = 0; i < 4; ++i) {
        int linear = i * 256 + tid;
        int row = linear >> 3, c8 = (linear & 7) * 8;
        uint4 v = *(const uint4*)(base + (size_t)(qt * 128 + row) * QKVC + c8);
        __half2* h = (__half2*)&v;
        h[0] = __hmul2(h[0], qscale); h[1] = __hmul2(h[1], qscale);
        h[2] = __hmul2(h[2], qscale); h[3] = __hmul2(h[3], qscale);
        *(uint4*)(Qs + row * FPH + c8) = v;
    }

    uint4 kr[2], vr[2];
    auto ldg_tile = [&](int kt) {
        #pragma unroll
        for (int i = 0; i < 2; ++i) {
            int linear = i * 256 + tid;
            int row = linear >> 3, c8 = (linear & 7) * 8;
            const __half* rb = base + (size_t)(kt * 64 + row) * QKVC;
            kr[i] = *(const uint4*)(rb + 64 + c8);
            vr[i] = *(const uint4*)(rb + 128 + c8);
        }
    };
    auto sts_tile = [&](int buf) {
        __half* Ksb = Kb + buf * 64 * FPH;
        __half* Vsb = Vb + buf * 64 * FPH;
        #pragma unroll
        for (int i = 0; i < 2; ++i) {
            int linear = i * 256 + tid;
            int row = linear >> 3, c8 = (linear & 7) * 8;
            *(uint4*)(Ksb + row * FPH + c8) = kr[i];
            *(uint4*)(Vsb + row * FPH + c8) = vr[i];
        }
    };

    float m0 = -INFINITY, m1 = -INFINITY, l0 = 0.f, l1 = 0.f;
    float o[8][4];
    #pragma unroll
    for (int nt = 0; nt < 8; ++nt)
        o[nt][0] = o[nt][1] = o[nt][2] = o[nt][3] = 0.f;

    ldg_tile(0);
    sts_tile(0);
    __syncthreads();

    // Q A-fragments: loop-invariant, load once
    uint32_t aq[4][4];
    {
        uint32_t qb = smem_u32(Qs);
        #pragma unroll
        for (int kk = 0; kk < 4; ++kk) {
            uint32_t ad = qb + (uint32_t)((mrow + lr16) * FPH + kk * 16 + lc8) * 2;
            LDSM_X4(aq[kk][0], aq[kk][1], aq[kk][2], aq[kk][3], ad);
        }
    }

    const uint32_t kb0 = smem_u32(Kb);
    const uint32_t vb0 = smem_u32(Vb);
    const int kend = 2 * qt + 1;

    for (int kt = 0; kt <= kend; ++kt) {
        int cur = kt & 1;
        if (kt < kend) ldg_tile(kt + 1);          // prefetch into registers

        // warp fully masked on this tile? (all j > all i) — skip compute
        bool active = (kt * 64) <= (qt * 128 + mrow + 15);

        if (active) {
            uint32_t ks = kb0 + cur * (64 * FPH * 2);
            uint32_t vs = vb0 + cur * (64 * FPH * 2);

            // S = Q @ K^T  (16x64 per warp, 4 k16 steps)
            float c[8][4];
            #pragma unroll
            for (int nt = 0; nt < 8; ++nt)
                c[nt][0] = c[nt][1] = c[nt][2] = c[nt][3] = 0.f;
            #pragma unroll
            for (int kk = 0; kk < 4; ++kk) {
                int kb = kk * 16;
                #pragma unroll
                for (int ntp = 0; ntp < 4; ++ntp) {
                    uint32_t bd = ks +
                        (uint32_t)((ntp * 16 + bRow) * FPH + kb + bCol) * 2;
                    uint32_t bf[4];
                    LDSM_X4(bf[0], bf[1], bf[2], bf[3], bd);
                    MMA_F16(c[2*ntp],   aq[kk], bf);
                    MMA_F16(c[2*ntp+1], aq[kk], bf + 2);
                }
            }

            // causal mask (global indices) — only near the diagonal
            if (kt * 64 + 63 > qt * 128 + mrow) {
                int i0 = qt * 128 + mrow + q;
                #pragma unroll
                for (int nt = 0; nt < 8; ++nt) {
                    int j0 = kt * 64 + nt * 8 + 2 * r4;
                    if (j0     > i0)     c[nt][0] = -INFINITY;
                    if (j0 + 1 > i0)     c[nt][1] = -INFINITY;
                    if (j0     > i0 + 8) c[nt][2] = -INFINITY;
                    if (j0 + 1 > i0 + 8) c[nt][3] = -INFINITY;
                }
            }

            // online softmax; rows live in 4 lanes (xor 1,2)
            float rm0 = -INFINITY, rm1 = -INFINITY;
            #pragma unroll
            for (int nt = 0; nt < 8; ++nt) {
                rm0 = fmaxf(rm0, fmaxf(c[nt][0], c[nt][1]));
                rm1 = fmaxf(rm1, fmaxf(c[nt][2], c[nt][3]));
            }
            rm0 = fmaxf(rm0, __shfl_xor_sync(0xffffffffu, rm0, 1));
            rm0 = fmaxf(rm0, __shfl_xor_sync(0xffffffffu, rm0, 2));
            rm1 = fmaxf(rm1, __shfl_xor_sync(0xffffffffu, rm1, 1));
            rm1 = fmaxf(rm1, __shfl_xor_sync(0xffffffffu, rm1, 2));
            float mn0 = fmaxf(m0, rm0), mn1 = fmaxf(m1, rm1);
            float al0 = __expf(m0 - mn0), al1 = __expf(m1 - mn1);
            m0 = mn0; m1 = mn1;
            float rs0 = 0.f, rs1 = 0.f;
            #pragma unroll
            for (int nt = 0; nt < 8; ++nt) {
                c[nt][0] = __expf(c[nt][0] - mn0); rs0 += c[nt][0];
                c[nt][1] = __expf(c[nt][1] - mn0); rs0 += c[nt][1];
                c[nt][2] = __expf(c[nt][2] - mn1); rs1 += c[nt][2];
                c[nt][3] = __expf(c[nt][3] - mn1); rs1 += c[nt][3];
            }
            rs0 += __shfl_xor_sync(0xffffffffu, rs0, 1);
            rs0 += __shfl_xor_sync(0xffffffffu, rs0, 2);
            rs1 += __shfl_xor_sync(0xffffffffu, rs1, 1);
            rs1 += __shfl_xor_sync(0xffffffffu, rs1, 2);
            l0 = l0 * al0 + rs0;
            l1 = l1 * al1 + rs1;
            #pragma unroll
            for (int nt = 0; nt < 8; ++nt) {
                o[nt][0] *= al0; o[nt][1] *= al0;
                o[nt][2] *= al1; o[nt][3] *= al1;
            }

            // O += P @ V — P register-direct A-fragments; V via ldmatrix.x4.trans
            #pragma unroll
            for (int kk = 0; kk < 4; ++kk) {
                int kb = kk * 16;
                uint32_t a[4] = {pack_h2(c[2*kk][0],   c[2*kk][1]),
                                 pack_h2(c[2*kk][2],   c[2*kk][3]),
                                 pack_h2(c[2*kk+1][0], c[2*kk+1][1]),
                                 pack_h2(c[2*kk+1][2], c[2*kk+1][3])};
                #pragma unroll
                for (int ntp = 0; ntp < 4; ++ntp) {
                    uint32_t vd = vs +
                        (uint32_t)((kb + lr16) * FPH + ntp * 16 + lc8) * 2;
                    uint32_t bf[4];
                    LDSM_X4T(bf[0], bf[1], bf[2], bf[3], vd);
                    MMA_F16(o[2*ntp],   a, bf);
                    MMA_F16(o[2*ntp+1], a, bf + 2);
                }
            }
        }

        if (kt < kend) {
            sts_tile(cur ^ 1);
            __syncthreads();
        }
    }

    // normalize + store (b,n,s,h) fp32
    float inv0 = 1.0f / l0, inv1 = 1.0f / l1;
    float* ob = atto + ((size_t)(b * NHEAD + n) * SDIM + qt * 128) * HDIM;
    int row0 = mrow + q;
    #pragma unroll
    for (int nt = 0; nt < 8; ++nt) {
        int col = nt * 8 + 2 * r4;
        *(float2*)(ob + (size_t)row0 * HDIM + col) =
            make_float2(o[nt][0] * inv0, o[nt][1] * inv0);
        *(float2*)(ob + (size_t)(row0 + 8) * HDIM + col) =
            make_float2(o[nt][2] * inv1, o[nt][3] * inv1);
    }
}

// ------- residual + torch-reinterpretation "projection" ---------------------
__global__ void resid_attn(const float* __restrict__ x,
                           const float* __restrict__ atto,
                           const float* __restrict__ wsum,
                           float* __restrict__ x1)
{
    __shared__ float tile[32][33];
    int b = blockIdx.z;
    int d0 = blockIdx.x * 32, s0 = blockIdx.y * 32;
    int tx = threadIdx.x, ty = threadIdx.y;
    const float* ab = atto + (size_t)b * (DDIM * SDIM);
    #pragma unroll
    for (int r = 0; r < 32; r += 8) {
        int d = d0 + ty + r, s = s0 + tx;
        tile[ty + r][tx] = ab[(size_t)d * SDIM + s];
    }
    __syncthreads();
    #pragma unroll
    for (int r = 0; r < 32; r += 8) {
        int s = s0 + ty + r, d = d0 + tx;
        size_t idx = ((size_t)b * SDIM + s) * DDIM + d;
        x1[idx] = x[idx] + tile[tx][ty + r] * wsum[d];
    }
}

// ---------------------------------------------------------------------------
extern "C" void kernel_launch(void* const* d_in, const int* in_sizes, int n_in,
                              void* d_out, int out_size)
{
    const float* x    = (const float*)d_in[0];
    const float* Wqkv = (const float*)d_in[1];
    const float* Wout = (const float*)d_in[2];
    const float* ln1w = (const float*)d_in[3];
    const float* ln1b = (const float*)d_in[4];
    const float* ln2w = (const float*)d_in[5];
    const float* ln2b = (const float*)d_in[6];
    const float* W1   = (const float*)d_in[7];
    const float* b1   = (const float*)d_in[8];
    const float* W2   = (const float*)d_in[9];
    const float* b2   = (const float*)d_in[10];
    float* out = (float*)d_out;

    __half *p_ln, *p_wqt, *p_w1t, *p_w2t, *p_qkv, *p_h;
    float *p_atto, *p_wsum, *p_x1;
    cudaGetSymbolAddress((void**)&p_ln,   g_ln);
    cudaGetSymbolAddress((void**)&p_wqt,  g_wqt);
    cudaGetSymbolAddress((void**)&p_w1t,  g_w1t);
    cudaGetSymbolAddress((void**)&p_w2t,  g_w2t);
    cudaGetSymbolAddress((void**)&p_qkv,  g_qkv);
    cudaGetSymbolAddress((void**)&p_atto, g_atto);
    cudaGetSymbolAddress((void**)&p_wsum, g_wsum);
    cudaGetSymbolAddress((void**)&p_x1,   g_x1);
    cudaGetSymbolAddress((void**)&p_h,    g_h);

    cudaFuncSetAttribute(mma_gemm<1>, cudaFuncAttributeMaxDynamicSharedMemorySize, GEMM_SMEM);
    cudaFuncSetAttribute(mma_gemm<2>, cudaFuncAttributeMaxDynamicSharedMemorySize, GEMM_SMEM);
    cudaFuncSetAttribute(mma_gemm<3>, cudaFuncAttributeMaxDynamicSharedMemorySize, GEMM_SMEM);
    cudaFuncSetAttribute(flash_mma, cudaFuncAttributeMaxDynamicSharedMemorySize, FLASH_SMEM);

    // ln1 + weight prep (all emit fp16)
    ln_kernel<<<ROWS, 256>>>(x, ln1w, ln1b, p_ln);
    pack_wqkv_t<<<dim3(6, 32, 16), dim3(32, 8)>>>(Wqkv, p_wqt);
    transpose_h<<<dim3(MDIM / 32, DDIM / 32), dim3(32, 8)>>>(W1, p_w1t, DDIM, MDIM);
    transpose_h<<<dim3(DDIM / 32, MDIM / 32), dim3(32, 8)>>>(W2, p_w2t, MDIM, DDIM);
    wsum_kernel<<<DDIM / 256, 256>>>(Wout, p_wsum);

    // QKV projection (fp16 HMMA, half out for flash)
    mma_gemm<3><<<dim3(QKVC / 128, ROWS / 128), 128, GEMM_SMEM>>>(
        p_ln, p_wqt, p_qkv, ROWS, QKVC, DDIM, nullptr, nullptr);

    // attention (fp16 HMMA flash, 128-row q tiles)
    flash_mma<<<dim3(SDIM / 128, NHEAD, BDIM), 256, FLASH_SMEM>>>(p_qkv, p_atto);

    // residual + reinterpretation-projection
    resid_attn<<<dim3(DDIM / 32, SDIM / 32, BDIM), dim3(32, 8)>>>(
        x, p_atto, p_wsum, p_x1);

    // ln2
    ln_kernel<<<ROWS, 256>>>(p_x1, ln2w, ln2b, p_ln);

    // MLP (fp16 HMMA)
    mma_gemm<1><<<dim3(MDIM / 128, ROWS / 128), 128, GEMM_SMEM>>>(
        p_ln, p_w1t, p_h, ROWS, MDIM, DDIM, b1, nullptr);
    mma_gemm<2><<<dim3(DDIM / 128, ROWS / 128), 128, GEMM_SMEM>>>(
        p_h, p_w2t, out, ROWS, DDIM, MDIM, b2, p_x1);
}